// round 1
// baseline (speedup 1.0000x reference)
#include <cuda_runtime.h>
#include <math.h>

#define BB   8
#define CIN  64
#define COUT 64
#define HH   128
#define WW   128
#define KK   9
#define NP   27
#define NPP  28   // padded to multiple of 4 for float4 smem reads

// Precomputed sampling params: [B][K][H][W]
__device__ float g_sy[BB * KK * HH * WW];
__device__ float g_sx[BB * KK * HH * WW];
__device__ float g_mk[BB * KK * HH * WW];

// ---------------------------------------------------------------------------
// Kernel 1: 3x3 dense conv producing 27 param channels, then transform into
// (sy, sx, mask) per (b,k,h,w).  One block per (b,h) row, one thread per w.
// pg_weight staged in dynamic smem reordered as [c*9+t][p] (stride NPP=28).
// ---------------------------------------------------------------------------
__global__ void __launch_bounds__(WW) param_kernel(
    const float* __restrict__ x,
    const float* __restrict__ pgw,
    const float* __restrict__ pgb)
{
    extern __shared__ __align__(16) float ws[];  // [CIN*KK][NPP]

    const int bh = blockIdx.x;
    const int b  = bh / HH;
    const int h  = bh % HH;
    const int w  = threadIdx.x;

    // Stage pg_weight: ws[ct*NPP + p] = pgw[p*CIN*KK + ct]; pad p==27 with 0.
    for (int idx = threadIdx.x; idx < CIN * KK * NPP; idx += blockDim.x) {
        int p  = idx % NPP;
        int ct = idx / NPP;
        ws[idx] = (p < NP) ? pgw[p * (CIN * KK) + ct] : 0.f;
    }
    __syncthreads();

    float acc[NPP];
#pragma unroll
    for (int p = 0; p < NPP; p++) acc[p] = 0.f;

    const float* xb = x + (size_t)b * CIN * HH * WW;

    for (int c = 0; c < CIN; c++) {
        const float* xc = xb + c * HH * WW;
        float xv[9];
#pragma unroll
        for (int t = 0; t < 9; t++) {
            int iy = h - 1 + t / 3;
            int ix = w - 1 + t % 3;
            bool ok = (iy >= 0) && (iy < HH) && (ix >= 0) && (ix < WW);
            xv[t] = ok ? __ldg(xc + iy * WW + ix) : 0.f;
        }
#pragma unroll
        for (int t = 0; t < 9; t++) {
            const float* wrow = ws + (c * 9 + t) * NPP;
            const float  xvt  = xv[t];
#pragma unroll
            for (int p4 = 0; p4 < 7; p4++) {
                float4 wv = *(const float4*)(wrow + p4 * 4);
                acc[p4 * 4 + 0] += xvt * wv.x;
                acc[p4 * 4 + 1] += xvt * wv.y;
                acc[p4 * 4 + 2] += xvt * wv.z;
                acc[p4 * 4 + 3] += xvt * wv.w;
            }
        }
    }

#pragma unroll
    for (int p = 0; p < NP; p++) acc[p] += __ldg(pgb + p);

    // offset layout: dy_k = params[2k], dx_k = params[2k+1], mask_k = sig(params[18+k])
    const int base = b * KK * HH * WW + h * WW + w;
#pragma unroll
    for (int k = 0; k < KK; k++) {
        int ki = k / 3, kj = k % 3;
        g_sy[base + k * HH * WW] = (float)(h - 1 + ki) + acc[2 * k];
        g_sx[base + k * HH * WW] = (float)(w - 1 + kj) + acc[2 * k + 1];
        g_mk[base + k * HH * WW] = 1.f / (1.f + expf(-acc[18 + k]));
    }
}

// ---------------------------------------------------------------------------
// Kernel 2: DCN main.  One block per (b,h) row, one thread per w.
// Each thread carries all 64 output-channel accumulators in registers.
// Per tap k: stage weight slice [c][o] into smem (16 KB), read with
// broadcast float4 (conflict-free), 4 gathers per input channel.
// ---------------------------------------------------------------------------
__global__ void __launch_bounds__(WW) dcn_kernel(
    const float* __restrict__ x,
    const float* __restrict__ wgt,
    const float* __restrict__ bias,
    float* __restrict__ out)
{
    __shared__ __align__(16) float ws[CIN * COUT];  // [c][o] for current k

    const int bh = blockIdx.x;
    const int b  = bh / HH;
    const int h  = bh % HH;
    const int w  = threadIdx.x;

    float acc[COUT];
#pragma unroll
    for (int o = 0; o < COUT; o++) acc[o] = 0.f;

    const float* xb    = x + (size_t)b * CIN * HH * WW;
    const int    pbase = b * KK * HH * WW + h * WW + w;

    for (int k = 0; k < KK; k++) {
        __syncthreads();
        // Stage weight slice: ws[c*64 + o] = wgt[o*576 + c*9 + k]
        for (int idx = threadIdx.x; idx < CIN * COUT; idx += blockDim.x) {
            int o = idx & 63;
            int c = idx >> 6;
            ws[idx] = wgt[o * (CIN * KK) + c * KK + k];
        }
        __syncthreads();

        float sy = g_sy[pbase + k * HH * WW];
        float sx = g_sx[pbase + k * HH * WW];
        float mk = g_mk[pbase + k * HH * WW];

        float y0f = floorf(sy), x0f = floorf(sx);
        int   iy0 = (int)y0f,   ix0 = (int)x0f;
        float fy = sy - y0f,    fx = sx - x0f;

        float w00 = (1.f - fy) * (1.f - fx);
        float w01 = (1.f - fy) * fx;
        float w10 = fy * (1.f - fx);
        float w11 = fy * fx;

        bool oky0 = (iy0 >= 0) && (iy0 < HH);
        bool oky1 = (iy0 + 1 >= 0) && (iy0 + 1 < HH);
        bool okx0 = (ix0 >= 0) && (ix0 < WW);
        bool okx1 = (ix0 + 1 >= 0) && (ix0 + 1 < WW);

        int cy0 = min(max(iy0, 0), HH - 1);
        int cy1 = min(max(iy0 + 1, 0), HH - 1);
        int cx0 = min(max(ix0, 0), WW - 1);
        int cx1 = min(max(ix0 + 1, 0), WW - 1);

        int o00 = cy0 * WW + cx0, o01 = cy0 * WW + cx1;
        int o10 = cy1 * WW + cx0, o11 = cy1 * WW + cx1;

        // fold mask + validity into corner weights
        w00 = (oky0 && okx0) ? w00 * mk : 0.f;
        w01 = (oky0 && okx1) ? w01 * mk : 0.f;
        w10 = (oky1 && okx0) ? w10 * mk : 0.f;
        w11 = (oky1 && okx1) ? w11 * mk : 0.f;

        const float* xc = xb;
        for (int c = 0; c < CIN; c++, xc += HH * WW) {
            float s = w00 * __ldg(xc + o00) + w01 * __ldg(xc + o01)
                    + w10 * __ldg(xc + o10) + w11 * __ldg(xc + o11);
            const float* wrow = ws + (c << 6);
#pragma unroll
            for (int o4 = 0; o4 < 16; o4++) {
                float4 wv = *(const float4*)(wrow + o4 * 4);
                acc[o4 * 4 + 0] += s * wv.x;
                acc[o4 * 4 + 1] += s * wv.y;
                acc[o4 * 4 + 2] += s * wv.z;
                acc[o4 * 4 + 3] += s * wv.w;
            }
        }
    }

    const int obase = (b * COUT * HH + h) * WW + w;
#pragma unroll
    for (int o = 0; o < COUT; o++)
        out[obase + o * HH * WW] = acc[o] + __ldg(bias + o);
}

// ---------------------------------------------------------------------------
extern "C" void kernel_launch(void* const* d_in, const int* in_sizes, int n_in,
                              void* d_out, int out_size)
{
    const float* x    = (const float*)d_in[0];
    const float* wgt  = (const float*)d_in[1];
    const float* bias = (const float*)d_in[2];
    const float* pgw  = (const float*)d_in[3];
    const float* pgb  = (const float*)d_in[4];
    float* out = (float*)d_out;

    const int smem1 = CIN * KK * NPP * (int)sizeof(float);  // 64512 B
    cudaFuncSetAttribute(param_kernel,
                         cudaFuncAttributeMaxDynamicSharedMemorySize, smem1);

    dim3 grid(BB * HH);
    dim3 block(WW);
    param_kernel<<<grid, block, smem1>>>(x, pgw, pgb);
    dcn_kernel<<<grid, block>>>(x, wgt, bias, out);
}

// round 2
// speedup vs baseline: 1.0408x; 1.0408x over previous
#include <cuda_runtime.h>
#include <math.h>

#define BB   8
#define CIN  64
#define COUT 64
#define HH   128
#define WW   128
#define KK   9
#define NP   27
#define NPP  28   // padded to multiple of 4 for float4 smem reads

// Precomputed sampling params: [B][K][H][W]
__device__ float g_sy[BB * KK * HH * WW];
__device__ float g_sx[BB * KK * HH * WW];
__device__ float g_mk[BB * KK * HH * WW];

// ---------------------------------------------------------------------------
// Kernel 1: 3x3 dense conv producing 27 param channels -> (sy, sx, mask).
// One block per (b, h-pair); each thread handles pixel (h0,w) AND (h1,w),
// amortizing each weight LDS.128 across 2 pixels (7 LDS.128 : 56 FMA) and
// the 3x3 window gathers (12 loads cover both pixels' 18 taps).
// ---------------------------------------------------------------------------
__global__ void __launch_bounds__(WW) param_kernel(
    const float* __restrict__ x,
    const float* __restrict__ pgw,
    const float* __restrict__ pgb)
{
    extern __shared__ __align__(16) float ws[];  // [CIN*KK][NPP]

    const int blk = blockIdx.x;          // 0 .. B*H/2-1
    const int b   = blk >> 6;            // H/2 = 64 pairs per image
    const int h0  = (blk & 63) << 1;
    const int h1  = h0 + 1;
    const int w   = threadIdx.x;

    // Stage pg_weight: ws[ct*NPP + p] = pgw[p*CIN*KK + ct]; pad p==27 with 0.
    for (int idx = threadIdx.x; idx < CIN * KK * NPP; idx += blockDim.x) {
        int p  = idx % NPP;
        int ct = idx / NPP;
        ws[idx] = (p < NP) ? pgw[p * (CIN * KK) + ct] : 0.f;
    }
    __syncthreads();

    float acc0[NPP], acc1[NPP];
#pragma unroll
    for (int p = 0; p < NPP; p++) { acc0[p] = 0.f; acc1[p] = 0.f; }

    const float* xb = x + (size_t)b * CIN * HH * WW;

    for (int c = 0; c < CIN; c++) {
        const float* xc = xb + c * HH * WW;
        // window rows h0-1 .. h0+2, cols w-1 .. w+1
        float xv[12];
#pragma unroll
        for (int r = 0; r < 4; r++) {
            int iy = h0 - 1 + r;
            bool oky = (iy >= 0) && (iy < HH);
#pragma unroll
            for (int j = 0; j < 3; j++) {
                int ix = w - 1 + j;
                bool ok = oky && (ix >= 0) && (ix < WW);
                xv[r * 3 + j] = ok ? __ldg(xc + iy * WW + ix) : 0.f;
            }
        }
#pragma unroll
        for (int t = 0; t < 9; t++) {
            const float* wrow = ws + (c * 9 + t) * NPP;
            const float  xa = xv[t];       // row t/3, col t%3 for pixel h0
            const float  xb2 = xv[t + 3];  // row t/3+1 for pixel h1
#pragma unroll
            for (int p4 = 0; p4 < 7; p4++) {
                float4 wv = *(const float4*)(wrow + p4 * 4);
                acc0[p4 * 4 + 0] += xa * wv.x;  acc1[p4 * 4 + 0] += xb2 * wv.x;
                acc0[p4 * 4 + 1] += xa * wv.y;  acc1[p4 * 4 + 1] += xb2 * wv.y;
                acc0[p4 * 4 + 2] += xa * wv.z;  acc1[p4 * 4 + 2] += xb2 * wv.z;
                acc0[p4 * 4 + 3] += xa * wv.w;  acc1[p4 * 4 + 3] += xb2 * wv.w;
            }
        }
    }

#pragma unroll
    for (int p = 0; p < NP; p++) {
        float bv = __ldg(pgb + p);
        acc0[p] += bv;
        acc1[p] += bv;
    }

    // offset layout: dy_k = params[2k], dx_k = params[2k+1], mask_k = sig(params[18+k])
    const int base0 = b * KK * HH * WW + h0 * WW + w;
    const int base1 = base0 + WW;
#pragma unroll
    for (int k = 0; k < KK; k++) {
        int ki = k / 3, kj = k % 3;
        g_sy[base0 + k * HH * WW] = (float)(h0 - 1 + ki) + acc0[2 * k];
        g_sx[base0 + k * HH * WW] = (float)(w - 1 + kj) + acc0[2 * k + 1];
        g_mk[base0 + k * HH * WW] = 1.f / (1.f + expf(-acc0[18 + k]));
        g_sy[base1 + k * HH * WW] = (float)(h1 - 1 + ki) + acc1[2 * k];
        g_sx[base1 + k * HH * WW] = (float)(w - 1 + kj) + acc1[2 * k + 1];
        g_mk[base1 + k * HH * WW] = 1.f / (1.f + expf(-acc1[18 + k]));
    }
}

// ---------------------------------------------------------------------------
// Kernel 2: DCN main as a register-tiled SGEMM per (b,h) row.
// Output tile 64(o) x 128(w); 256 threads; each thread owns a 4(o) x 8(w)
// micro-tile (32 accumulators). Per k-tap:
//   phase A: precompute bilinear corners per w, sample S[c][w] into smem,
//            stage weight slice W[c][o] into smem
//   phase B: GEMM acc += W[c][o-tile] * S[c][w-tile]
// Per c-step: 3 LDS.128 per 32 FMAs -> FMA-bound.
// ---------------------------------------------------------------------------
__global__ void __launch_bounds__(256) dcn_kernel(
    const float* __restrict__ x,
    const float* __restrict__ wgt,
    const float* __restrict__ bias,
    float* __restrict__ out)
{
    extern __shared__ __align__(16) char smraw[];
    float* sS  = (float*)smraw;               // [64][128]  sampled values
    float* sW  = sS + CIN * WW;               // [64][64]   weight slice [c][o]
    int*   sCO = (int*)(sW + CIN * COUT);     // [4][128]   corner offsets
    float* sCW = (float*)(sCO + 4 * WW);      // [4][128]   corner weights (mask folded)

    const int tid   = threadIdx.x;
    const int b     = blockIdx.x >> 7;
    const int h     = blockIdx.x & 127;
    const int ob    = (tid >> 4) << 2;        // output-channel base (0..60)
    const int wb    = (tid & 15) << 3;        // pixel base          (0..120)
    const int wsamp = tid & 127;
    const int cb    = tid >> 7;               // 0 or 1

    const float* xb = x + (size_t)b * CIN * HH * WW;
    const int pb = b * KK * HH * WW + h * WW;

    float acc[32];
#pragma unroll
    for (int i = 0; i < 32; i++) acc[i] = 0.f;

    for (int k = 0; k < KK; k++) {
        __syncthreads();   // previous GEMM must be done reading sS/sW

        // Stage weight slice: sW[c*64 + o] = wgt[o*576 + c*9 + k]
        for (int idx = tid; idx < CIN * COUT; idx += 256) {
            int o = idx & 63;
            int c = idx >> 6;
            sW[idx] = wgt[o * (CIN * KK) + c * KK + k];
        }

        // Corner precompute (one thread per pixel)
        if (tid < WW) {
            int w = tid;
            float sy = g_sy[pb + k * HH * WW + w];
            float sx = g_sx[pb + k * HH * WW + w];
            float mk = g_mk[pb + k * HH * WW + w];

            float y0f = floorf(sy), x0f = floorf(sx);
            int   iy0 = (int)y0f,   ix0 = (int)x0f;
            float fy = sy - y0f,    fx = sx - x0f;

            float w00 = (1.f - fy) * (1.f - fx);
            float w01 = (1.f - fy) * fx;
            float w10 = fy * (1.f - fx);
            float w11 = fy * fx;

            bool oky0 = (iy0 >= 0) && (iy0 < HH);
            bool oky1 = (iy0 + 1 >= 0) && (iy0 + 1 < HH);
            bool okx0 = (ix0 >= 0) && (ix0 < WW);
            bool okx1 = (ix0 + 1 >= 0) && (ix0 + 1 < WW);

            int cy0 = min(max(iy0, 0), HH - 1);
            int cy1 = min(max(iy0 + 1, 0), HH - 1);
            int cx0 = min(max(ix0, 0), WW - 1);
            int cx1 = min(max(ix0 + 1, 0), WW - 1);

            sCO[0 * WW + w] = cy0 * WW + cx0;
            sCO[1 * WW + w] = cy0 * WW + cx1;
            sCO[2 * WW + w] = cy1 * WW + cx0;
            sCO[3 * WW + w] = cy1 * WW + cx1;
            sCW[0 * WW + w] = (oky0 && okx0) ? w00 * mk : 0.f;
            sCW[1 * WW + w] = (oky0 && okx1) ? w01 * mk : 0.f;
            sCW[2 * WW + w] = (oky1 && okx0) ? w10 * mk : 0.f;
            sCW[3 * WW + w] = (oky1 && okx1) ? w11 * mk : 0.f;
        }
        __syncthreads();

        // Sampling: thread covers (w = wsamp, c = 2*cc + cb), 32 channels
        {
            int   o00 = sCO[wsamp],          o01 = sCO[WW + wsamp];
            int   o10 = sCO[2 * WW + wsamp], o11 = sCO[3 * WW + wsamp];
            float q00 = sCW[wsamp],          q01 = sCW[WW + wsamp];
            float q10 = sCW[2 * WW + wsamp], q11 = sCW[3 * WW + wsamp];
#pragma unroll 4
            for (int cc = 0; cc < 32; cc++) {
                int c = (cc << 1) | cb;
                const float* xc = xb + (c << 14);
                float s = q00 * __ldg(xc + o00) + q01 * __ldg(xc + o01)
                        + q10 * __ldg(xc + o10) + q11 * __ldg(xc + o11);
                sS[(c << 7) + wsamp] = s;
            }
        }
        __syncthreads();

        // GEMM: acc[4][8] += W[c][ob..ob+4] * S[c][wb..wb+8]
#pragma unroll 8
        for (int c = 0; c < CIN; c++) {
            float4 wv = *(const float4*)(sW + (c << 6) + ob);
            float4 s0 = *(const float4*)(sS + (c << 7) + wb);
            float4 s1 = *(const float4*)(sS + (c << 7) + wb + 4);
            float wr[4] = {wv.x, wv.y, wv.z, wv.w};
            float sr[8] = {s0.x, s0.y, s0.z, s0.w, s1.x, s1.y, s1.z, s1.w};
#pragma unroll
            for (int i = 0; i < 4; i++)
#pragma unroll
                for (int j = 0; j < 8; j++)
                    acc[i * 8 + j] += wr[i] * sr[j];
        }
    }

    // Epilogue: vectorized stores, bias added
#pragma unroll
    for (int i = 0; i < 4; i++) {
        float bo = __ldg(bias + ob + i);
        float4 v0, v1;
        v0.x = acc[i * 8 + 0] + bo; v0.y = acc[i * 8 + 1] + bo;
        v0.z = acc[i * 8 + 2] + bo; v0.w = acc[i * 8 + 3] + bo;
        v1.x = acc[i * 8 + 4] + bo; v1.y = acc[i * 8 + 5] + bo;
        v1.z = acc[i * 8 + 6] + bo; v1.w = acc[i * 8 + 7] + bo;
        float* op = out + (((size_t)b * COUT + ob + i) * HH + h) * WW + wb;
        *(float4*)(op)     = v0;
        *(float4*)(op + 4) = v1;
    }
}

// ---------------------------------------------------------------------------
extern "C" void kernel_launch(void* const* d_in, const int* in_sizes, int n_in,
                              void* d_out, int out_size)
{
    const float* x    = (const float*)d_in[0];
    const float* wgt  = (const float*)d_in[1];
    const float* bias = (const float*)d_in[2];
    const float* pgw  = (const float*)d_in[3];
    const float* pgb  = (const float*)d_in[4];
    float* out = (float*)d_out;

    const int smem1 = CIN * KK * NPP * (int)sizeof(float);  // 64512 B
    cudaFuncSetAttribute(param_kernel,
                         cudaFuncAttributeMaxDynamicSharedMemorySize, smem1);

    const int smem2 = (CIN * WW + CIN * COUT) * (int)sizeof(float)
                    + 4 * WW * (int)(sizeof(int) + sizeof(float));  // 53248 B
    cudaFuncSetAttribute(dcn_kernel,
                         cudaFuncAttributeMaxDynamicSharedMemorySize, smem2);

    param_kernel<<<BB * HH / 2, WW, smem1>>>(x, pgw, pgb);
    dcn_kernel<<<BB * HH, 256, smem2>>>(x, wgt, bias, out);
}

// round 4
// speedup vs baseline: 1.7421x; 1.6738x over previous
#include <cuda_runtime.h>
#include <math.h>
#include <stdint.h>

#define BB   8
#define CIN  64
#define COUT 64
#define HH   128
#define WW   128
#define KK   9
#define NP   27
#define NPP  28
#define HW   (HH * WW)

#define S_STRIDE 68   // [w][c] tile row stride (words); 68 % 32 == 4 -> A frags conflict-free
#define W_STRIDE 72   // [c][o] tile row stride (words); 72 % 32 == 8 -> B frags conflict-free

// ---------------------------------------------------------------------------
// Scratch (device globals: no allocation allowed)
// ---------------------------------------------------------------------------
__device__ int4     g_co[BB * KK * HW];     // bilinear corner offsets
__device__ float4   g_cq[BB * KK * HW];     // corner weights (mask+validity folded)
__device__ uint32_t g_wt[KK * COUT * CIN];  // weights as [k][c][o], tf32-rounded bits

// ---------------------------------------------------------------------------
__device__ __forceinline__ uint32_t cvt_tf32(float f) {
    uint32_t u;
    asm("cvt.rna.tf32.f32 %0, %1;" : "=r"(u) : "f"(f));
    return u;
}

__device__ __forceinline__ void make_corner(float sy, float sx, float mk,
                                            int4& co, float4& cq) {
    float y0f = floorf(sy), x0f = floorf(sx);
    int   iy0 = (int)y0f,   ix0 = (int)x0f;
    float fy = sy - y0f,    fx = sx - x0f;
    float w00 = (1.f - fy) * (1.f - fx);
    float w01 = (1.f - fy) * fx;
    float w10 = fy * (1.f - fx);
    float w11 = fy * fx;
    bool oky0 = (iy0 >= 0) && (iy0 < HH);
    bool oky1 = (iy0 + 1 >= 0) && (iy0 + 1 < HH);
    bool okx0 = (ix0 >= 0) && (ix0 < WW);
    bool okx1 = (ix0 + 1 >= 0) && (ix0 + 1 < WW);
    int cy0 = min(max(iy0, 0), HH - 1);
    int cy1 = min(max(iy0 + 1, 0), HH - 1);
    int cx0 = min(max(ix0, 0), WW - 1);
    int cx1 = min(max(ix0 + 1, 0), WW - 1);
    co = make_int4(cy0 * WW + cx0, cy0 * WW + cx1, cy1 * WW + cx0, cy1 * WW + cx1);
    cq = make_float4((oky0 && okx0) ? w00 * mk : 0.f,
                     (oky0 && okx1) ? w01 * mk : 0.f,
                     (oky1 && okx0) ? w10 * mk : 0.f,
                     (oky1 && okx1) ? w11 * mk : 0.f);
}

// ---------------------------------------------------------------------------
// Kernel 0: pre-convert main weights to tf32 bits, layout [k][c][o]
// ---------------------------------------------------------------------------
__global__ void wprep_kernel(const float* __restrict__ wgt) {
    int idx = blockIdx.x * blockDim.x + threadIdx.x;
    if (idx >= KK * COUT * CIN) return;
    int k = idx >> 12;
    int r = idx & 4095;
    int c = r >> 6;
    int o = r & 63;
    g_wt[idx] = cvt_tf32(wgt[o * (CIN * KK) + c * KK + k]);
}

// ---------------------------------------------------------------------------
// Kernel 1: param conv (fp32) -> corner offsets/weights
// ---------------------------------------------------------------------------
__global__ void __launch_bounds__(WW) param_kernel(
    const float* __restrict__ x,
    const float* __restrict__ pgw,
    const float* __restrict__ pgb)
{
    extern __shared__ __align__(16) float ws[];  // [CIN*KK][NPP]

    const int blk = blockIdx.x;
    const int b   = blk >> 6;
    const int h0  = (blk & 63) << 1;
    const int w   = threadIdx.x;

    for (int idx = threadIdx.x; idx < CIN * KK * NPP; idx += blockDim.x) {
        int p  = idx % NPP;
        int ct = idx / NPP;
        ws[idx] = (p < NP) ? pgw[p * (CIN * KK) + ct] : 0.f;
    }
    __syncthreads();

    float acc0[NPP], acc1[NPP];
#pragma unroll
    for (int p = 0; p < NPP; p++) { acc0[p] = 0.f; acc1[p] = 0.f; }

    const float* xb = x + (size_t)b * CIN * HW;

    for (int c = 0; c < CIN; c++) {
        const float* xc = xb + c * HW;
        float xv[12];
#pragma unroll
        for (int r = 0; r < 4; r++) {
            int iy = h0 - 1 + r;
            bool oky = (iy >= 0) && (iy < HH);
#pragma unroll
            for (int j = 0; j < 3; j++) {
                int ix = w - 1 + j;
                bool ok = oky && (ix >= 0) && (ix < WW);
                xv[r * 3 + j] = ok ? __ldg(xc + iy * WW + ix) : 0.f;
            }
        }
#pragma unroll
        for (int t = 0; t < 9; t++) {
            const float* wrow = ws + (c * 9 + t) * NPP;
            const float  xa  = xv[t];
            const float  xb2 = xv[t + 3];
#pragma unroll
            for (int p4 = 0; p4 < 7; p4++) {
                float4 wv = *(const float4*)(wrow + p4 * 4);
                acc0[p4 * 4 + 0] += xa * wv.x;  acc1[p4 * 4 + 0] += xb2 * wv.x;
                acc0[p4 * 4 + 1] += xa * wv.y;  acc1[p4 * 4 + 1] += xb2 * wv.y;
                acc0[p4 * 4 + 2] += xa * wv.z;  acc1[p4 * 4 + 2] += xb2 * wv.z;
                acc0[p4 * 4 + 3] += xa * wv.w;  acc1[p4 * 4 + 3] += xb2 * wv.w;
            }
        }
    }

#pragma unroll
    for (int p = 0; p < NP; p++) {
        float bv = __ldg(pgb + p);
        acc0[p] += bv;
        acc1[p] += bv;
    }

    const int base0 = b * KK * HW + h0 * WW + w;
    const int base1 = base0 + WW;
#pragma unroll
    for (int k = 0; k < KK; k++) {
        int ki = k / 3, kj = k % 3;
        int4 co; float4 cq;
        make_corner((float)(h0 - 1 + ki) + acc0[2 * k],
                    (float)(w  - 1 + kj) + acc0[2 * k + 1],
                    1.f / (1.f + expf(-acc0[18 + k])), co, cq);
        g_co[base0 + k * HW] = co;
        g_cq[base0 + k * HW] = cq;
        make_corner((float)(h0 + ki) + acc1[2 * k],
                    (float)(w - 1 + kj) + acc1[2 * k + 1],
                    1.f / (1.f + expf(-acc1[18 + k])), co, cq);
        g_co[base1 + k * HW] = co;
        g_cq[base1 + k * HW] = cq;
    }
}

// ---------------------------------------------------------------------------
// Kernel 2: DCN main via mma.sync m16n8k8 tf32.
// One block per (b,h): D[w=128][o=64] = sum over 9 taps of S_k * W_k^T.
// 8 warps; warp m owns w rows [16m, 16m+16), all 64 o (8 n-tiles),
// 32 fp32 accumulators per thread held across taps.
// ---------------------------------------------------------------------------
__global__ void __launch_bounds__(256) dcn_kernel(
    const float* __restrict__ x,
    const float* __restrict__ bias,
    float* __restrict__ out)
{
    extern __shared__ __align__(16) float sm[];
    uint32_t* sS = (uint32_t*)sm;                 // [128][S_STRIDE]
    uint32_t* sW = (uint32_t*)sm + WW * S_STRIDE; // [64][W_STRIDE]

    const int tid  = threadIdx.x;
    const int lane = tid & 31;
    const int wid  = tid >> 5;
    const int b    = blockIdx.x >> 7;
    const int h    = blockIdx.x & 127;

    const float* xb = x + (size_t)b * CIN * HW;
    const int w  = tid & 127;   // sampling pixel
    const int ch = tid >> 7;    // sampling c-half
    const int pb = b * KK * HW + h * WW + w;

    const int w0 = wid << 4;    // warp's M base
    const int gy = lane >> 2;   // fragment group row
    const int tg = lane & 3;    // thread-in-group

    float acc[32];
#pragma unroll
    for (int i = 0; i < 32; i++) acc[i] = 0.f;

    for (int k = 0; k < KK; k++) {
        // ---- stage W_k: sW[c][o] from g_wt[k][c][o] ----
#pragma unroll
        for (int i = 0; i < 16; i++) {
            int idx = tid + (i << 8);
            int c = idx >> 6, o = idx & 63;
            sW[c * W_STRIDE + o] = g_wt[(k << 12) + idx];
        }
        // ---- stage S_k: bilinear gather -> tf32 -> sS[w][c] (STS.128) ----
        {
            int4   co = g_co[pb + k * HW];
            float4 cq = g_cq[pb + k * HW];
#pragma unroll
            for (int cc4 = 0; cc4 < 8; cc4++) {
                int c0 = ch * 32 + cc4 * 4;
                uint32_t r[4];
#pragma unroll
                for (int j = 0; j < 4; j++) {
                    const float* xc = xb + ((size_t)(c0 + j) << 14);
                    float s = cq.x * __ldg(xc + co.x) + cq.y * __ldg(xc + co.y)
                            + cq.z * __ldg(xc + co.z) + cq.w * __ldg(xc + co.w);
                    r[j] = cvt_tf32(s);
                }
                *(uint4*)(sS + w * S_STRIDE + c0) = make_uint4(r[0], r[1], r[2], r[3]);
            }
        }
        __syncthreads();

        // ---- MMA: 8 K-chunks of 8; A frag shared across 8 n-tiles ----
#pragma unroll
        for (int kc = 0; kc < 8; kc++) {
            int c0 = kc << 3;
            uint32_t a0 = sS[(w0 + gy)     * S_STRIDE + c0 + tg];
            uint32_t a1 = sS[(w0 + gy + 8) * S_STRIDE + c0 + tg];
            uint32_t a2 = sS[(w0 + gy)     * S_STRIDE + c0 + tg + 4];
            uint32_t a3 = sS[(w0 + gy + 8) * S_STRIDE + c0 + tg + 4];
#pragma unroll
            for (int n = 0; n < 8; n++) {
                uint32_t b0 = sW[(c0 + tg)     * W_STRIDE + (n << 3) + gy];
                uint32_t b1 = sW[(c0 + tg + 4) * W_STRIDE + (n << 3) + gy];
                float* d = acc + (n << 2);
                asm volatile(
                    "mma.sync.aligned.m16n8k8.row.col.f32.tf32.tf32.f32 "
                    "{%0,%1,%2,%3}, {%4,%5,%6,%7}, {%8,%9}, {%0,%1,%2,%3};"
                    : "+f"(d[0]), "+f"(d[1]), "+f"(d[2]), "+f"(d[3])
                    : "r"(a0), "r"(a1), "r"(a2), "r"(a3), "r"(b0), "r"(b1));
            }
        }
        __syncthreads();   // mma reads done before next tap's staging
    }

    // ---- epilogue: D fragment -> out[b][o][h][w], bias added ----
#pragma unroll
    for (int n = 0; n < 8; n++) {
#pragma unroll
        for (int j = 0; j < 4; j++) {
            int o  = (n << 3) + (tg << 1) + (j & 1);
            int wr = w0 + gy + ((j >> 1) << 3);
            out[(((size_t)b * COUT + o) * HH + h) * WW + wr] =
                acc[(n << 2) + j] + __ldg(bias + o);
        }
    }
}

// ---------------------------------------------------------------------------
extern "C" void kernel_launch(void* const* d_in, const int* in_sizes, int n_in,
                              void* d_out, int out_size)
{
    const float* x    = (const float*)d_in[0];
    const float* wgt  = (const float*)d_in[1];
    const float* bias = (const float*)d_in[2];
    const float* pgw  = (const float*)d_in[3];
    const float* pgb  = (const float*)d_in[4];
    float* out = (float*)d_out;

    const int smem1 = CIN * KK * NPP * (int)sizeof(float);  // 64512 B
    cudaFuncSetAttribute(param_kernel,
                         cudaFuncAttributeMaxDynamicSharedMemorySize, smem1);

    const int smem2 = (WW * S_STRIDE + COUT * W_STRIDE) * (int)sizeof(float); // 53248 B
    cudaFuncSetAttribute(dcn_kernel,
                         cudaFuncAttributeMaxDynamicSharedMemorySize, smem2);

    wprep_kernel<<<(KK * COUT * CIN + 255) / 256, 256>>>(wgt);
    param_kernel<<<BB * HH / 2, WW, smem1>>>(x, pgw, pgb);
    dcn_kernel<<<BB * HH, 256, smem2>>>(x, bias, out);
}

// round 5
// speedup vs baseline: 2.2295x; 1.2798x over previous
#include <cuda_runtime.h>
#include <math.h>
#include <stdint.h>

#define BB   8
#define CIN  64
#define COUT 64
#define HH   128
#define WW   128
#define KK   9
#define NP   27
#define HW   (HH * WW)

#define S_STRIDE 68   // dcn S tile row stride (words)
#define W_STRIDE 72   // dcn W tile row stride (words)

#define X_STRIDE 68   // param X tile: [pos][c], 130 pos rows, stride 68
#define X_TILE   (130 * X_STRIDE)          // words per image row tile
#define PW_STRIDE 36  // param W tile: [c][p32]
#define PD_STRIDE 36  // param D staging: [w][p32]

// ---------------------------------------------------------------------------
// Scratch (device globals: no allocation allowed)
// ---------------------------------------------------------------------------
__device__ int4     g_co[BB * KK * HW];      // bilinear corner offsets
__device__ float4   g_cq[BB * KK * HW];      // corner weights (mask+validity folded)
__device__ uint32_t g_wt[KK * COUT * CIN];   // main weights [k][c][o], tf32 bits
__device__ uint32_t g_pw[KK * CIN * 32];     // param weights [t][c][p32], tf32 bits

// ---------------------------------------------------------------------------
__device__ __forceinline__ uint32_t cvt_tf32(float f) {
    uint32_t u;
    asm("cvt.rna.tf32.f32 %0, %1;" : "=r"(u) : "f"(f));
    return u;
}

__device__ __forceinline__ void make_corner(float sy, float sx, float mk,
                                            int4& co, float4& cq) {
    float y0f = floorf(sy), x0f = floorf(sx);
    int   iy0 = (int)y0f,   ix0 = (int)x0f;
    float fy = sy - y0f,    fx = sx - x0f;
    float w00 = (1.f - fy) * (1.f - fx);
    float w01 = (1.f - fy) * fx;
    float w10 = fy * (1.f - fx);
    float w11 = fy * fx;
    bool oky0 = (iy0 >= 0) && (iy0 < HH);
    bool oky1 = (iy0 + 1 >= 0) && (iy0 + 1 < HH);
    bool okx0 = (ix0 >= 0) && (ix0 < WW);
    bool okx1 = (ix0 + 1 >= 0) && (ix0 + 1 < WW);
    int cy0 = min(max(iy0, 0), HH - 1);
    int cy1 = min(max(iy0 + 1, 0), HH - 1);
    int cx0 = min(max(ix0, 0), WW - 1);
    int cx1 = min(max(ix0 + 1, 0), WW - 1);
    co = make_int4(cy0 * WW + cx0, cy0 * WW + cx1, cy1 * WW + cx0, cy1 * WW + cx1);
    cq = make_float4((oky0 && okx0) ? w00 * mk : 0.f,
                     (oky0 && okx1) ? w01 * mk : 0.f,
                     (oky1 && okx0) ? w10 * mk : 0.f,
                     (oky1 && okx1) ? w11 * mk : 0.f);
}

#define MMA_TF32(d, a0, a1, a2, a3, b0, b1)                                   \
    asm volatile(                                                             \
        "mma.sync.aligned.m16n8k8.row.col.f32.tf32.tf32.f32 "                 \
        "{%0,%1,%2,%3}, {%4,%5,%6,%7}, {%8,%9}, {%0,%1,%2,%3};"               \
        : "+f"((d)[0]), "+f"((d)[1]), "+f"((d)[2]), "+f"((d)[3])              \
        : "r"(a0), "r"(a1), "r"(a2), "r"(a3), "r"(b0), "r"(b1))

// ---------------------------------------------------------------------------
// Kernel 0: pre-convert both weight tensors to tf32 bits
//   g_wt[k][c][o]  from wgt[o][c][k]    (36864 entries)
//   g_pw[t][c][p]  from pgw[p][c][t]    (18432 entries, p>=27 zero)
// ---------------------------------------------------------------------------
__global__ void wprep_kernel(const float* __restrict__ wgt,
                             const float* __restrict__ pgw) {
    int idx = blockIdx.x * blockDim.x + threadIdx.x;
    if (idx < KK * COUT * CIN) {
        int k = idx >> 12;
        int r = idx & 4095;
        int c = r >> 6;
        int o = r & 63;
        g_wt[idx] = cvt_tf32(wgt[o * (CIN * KK) + c * KK + k]);
    } else if (idx < KK * COUT * CIN + KK * CIN * 32) {
        int j = idx - KK * COUT * CIN;
        int t = j >> 11;
        int r = j & 2047;
        int c = r >> 5;
        int p = r & 31;
        g_pw[j] = (p < NP) ? cvt_tf32(pgw[p * (CIN * KK) + c * KK + t]) : 0u;
    }
}

// ---------------------------------------------------------------------------
// Kernel 1: param conv via mma.sync m16n8k8 tf32 -> corner offsets/weights.
// One block per (b,h).  D[w=128][p=32] = sum_t X_t[w][c] * Wp_t[p][c].
// X rows h-1,h,h+1 staged once as [pos 0..129][c] (pos 0/129 zero => pad);
// tap (ti,tj) reads pos = w + tj from row tile ti.
// ---------------------------------------------------------------------------
__global__ void __launch_bounds__(256) param_mma_kernel(
    const float* __restrict__ x,
    const float* __restrict__ pgb)
{
    extern __shared__ __align__(16) uint32_t psm[];
    uint32_t* sX = psm;                         // [3][130][X_STRIDE]
    uint32_t* sW = psm + 3 * X_TILE;            // [64][PW_STRIDE]
    float*    sD = (float*)(sW + CIN * PW_STRIDE);  // [128][PD_STRIDE]

    const int tid  = threadIdx.x;
    const int lane = tid & 31;
    const int wid  = tid >> 5;
    const int b    = blockIdx.x >> 7;
    const int h    = blockIdx.x & 127;

    const float* xb = x + (size_t)b * CIN * HW;
    const int w  = tid & 127;
    const int ch = tid >> 7;

    const int w0 = wid << 4;
    const int gy = lane >> 2;
    const int tg = lane & 3;

    // ---- stage X rows h-1..h+1 (tf32), zero pad pos 0 and 129 ----
#pragma unroll
    for (int ti = 0; ti < 3; ti++) {
        int row = h - 1 + ti;
        bool okr = (row >= 0) && (row < HH);
        uint32_t* dst = sX + ti * X_TILE + (w + 1) * X_STRIDE;
#pragma unroll
        for (int cc4 = 0; cc4 < 8; cc4++) {
            int c0 = ch * 32 + cc4 * 4;
            uint32_t r[4];
#pragma unroll
            for (int j = 0; j < 4; j++)
                r[j] = okr ? cvt_tf32(__ldg(xb + ((size_t)(c0 + j) << 14) + row * WW + w)) : 0u;
            *(uint4*)(dst + c0) = make_uint4(r[0], r[1], r[2], r[3]);
        }
    }
    if (tid < 96) {
        int ti  = tid >> 5;
        int q   = tid & 31;
        int pos = (q >> 4) ? 129 : 0;
        int c4  = (q & 15) << 2;
        *(uint4*)(sX + ti * X_TILE + pos * X_STRIDE + c4) = make_uint4(0, 0, 0, 0);
    }

    float acc[16];
#pragma unroll
    for (int i = 0; i < 16; i++) acc[i] = 0.f;

    for (int t = 0; t < KK; t++) {
        __syncthreads();   // prev tap's sW reads done (also covers sX staging at t=0)
        // ---- stage Wp_t: [c][p32], 2048 words, linear copy ----
        {
            const uint4* src = (const uint4*)(g_pw + (t << 11));
#pragma unroll
            for (int i = 0; i < 2; i++) {
                int idx = tid + (i << 8);          // uint4 index, 512 total
                uint4 v = __ldg(src + idx);
                int c  = idx >> 3;
                int p4 = (idx & 7) << 2;
                *(uint4*)(sW + c * PW_STRIDE + p4) = v;
            }
        }
        __syncthreads();

        const int ti = t / 3, tj = t % 3;
        const uint32_t* sXt = sX + ti * X_TILE + tj * X_STRIDE;  // fold tap shift
#pragma unroll
        for (int kc = 0; kc < 8; kc++) {
            int c0 = kc << 3;
            uint32_t a0 = sXt[(w0 + gy)     * X_STRIDE + c0 + tg];
            uint32_t a1 = sXt[(w0 + gy + 8) * X_STRIDE + c0 + tg];
            uint32_t a2 = sXt[(w0 + gy)     * X_STRIDE + c0 + tg + 4];
            uint32_t a3 = sXt[(w0 + gy + 8) * X_STRIDE + c0 + tg + 4];
#pragma unroll
            for (int n = 0; n < 4; n++) {
                uint32_t b0 = sW[(c0 + tg)     * PW_STRIDE + (n << 3) + gy];
                uint32_t b1 = sW[(c0 + tg + 4) * PW_STRIDE + (n << 3) + gy];
                MMA_TF32(acc + (n << 2), a0, a1, a2, a3, b0, b1);
            }
        }
    }
    __syncthreads();

    // ---- D fragments -> sD[w][p] ----
#pragma unroll
    for (int n = 0; n < 4; n++) {
#pragma unroll
        for (int j = 0; j < 4; j++) {
            int p  = (n << 3) + (tg << 1) + (j & 1);
            int wr = w0 + gy + ((j >> 1) << 3);
            sD[wr * PD_STRIDE + p] = acc[(n << 2) + j];
        }
    }
    __syncthreads();

    // ---- corners: one thread per pixel ----
    if (tid < WW) {
        float prm[NP];
#pragma unroll
        for (int p = 0; p < NP; p++)
            prm[p] = sD[tid * PD_STRIDE + p] + __ldg(pgb + p);
        const int base = b * KK * HW + h * WW + tid;
#pragma unroll
        for (int k = 0; k < KK; k++) {
            int ki = k / 3, kj = k % 3;
            int4 co; float4 cq;
            make_corner((float)(h - 1 + ki) + prm[2 * k],
                        (float)(tid - 1 + kj) + prm[2 * k + 1],
                        1.f / (1.f + expf(-prm[18 + k])), co, cq);
            g_co[base + k * HW] = co;
            g_cq[base + k * HW] = cq;
        }
    }
}

// ---------------------------------------------------------------------------
// Kernel 2: DCN main via mma.sync m16n8k8 tf32 (unchanged from round 4).
// ---------------------------------------------------------------------------
__global__ void __launch_bounds__(256) dcn_kernel(
    const float* __restrict__ x,
    const float* __restrict__ bias,
    float* __restrict__ out)
{
    extern __shared__ __align__(16) float sm[];
    uint32_t* sS = (uint32_t*)sm;                 // [128][S_STRIDE]
    uint32_t* sW = (uint32_t*)sm + WW * S_STRIDE; // [64][W_STRIDE]

    const int tid  = threadIdx.x;
    const int lane = tid & 31;
    const int wid  = tid >> 5;
    const int b    = blockIdx.x >> 7;
    const int h    = blockIdx.x & 127;

    const float* xb = x + (size_t)b * CIN * HW;
    const int w  = tid & 127;
    const int ch = tid >> 7;
    const int pb = b * KK * HW + h * WW + w;

    const int w0 = wid << 4;
    const int gy = lane >> 2;
    const int tg = lane & 3;

    float acc[32];
#pragma unroll
    for (int i = 0; i < 32; i++) acc[i] = 0.f;

    for (int k = 0; k < KK; k++) {
#pragma unroll
        for (int i = 0; i < 16; i++) {
            int idx = tid + (i << 8);
            int c = idx >> 6, o = idx & 63;
            sW[c * W_STRIDE + o] = g_wt[(k << 12) + idx];
        }
        {
            int4   co = g_co[pb + k * HW];
            float4 cq = g_cq[pb + k * HW];
#pragma unroll
            for (int cc4 = 0; cc4 < 8; cc4++) {
                int c0 = ch * 32 + cc4 * 4;
                uint32_t r[4];
#pragma unroll
                for (int j = 0; j < 4; j++) {
                    const float* xc = xb + ((size_t)(c0 + j) << 14);
                    float s = cq.x * __ldg(xc + co.x) + cq.y * __ldg(xc + co.y)
                            + cq.z * __ldg(xc + co.z) + cq.w * __ldg(xc + co.w);
                    r[j] = cvt_tf32(s);
                }
                *(uint4*)(sS + w * S_STRIDE + c0) = make_uint4(r[0], r[1], r[2], r[3]);
            }
        }
        __syncthreads();

#pragma unroll
        for (int kc = 0; kc < 8; kc++) {
            int c0 = kc << 3;
            uint32_t a0 = sS[(w0 + gy)     * S_STRIDE + c0 + tg];
            uint32_t a1 = sS[(w0 + gy + 8) * S_STRIDE + c0 + tg];
            uint32_t a2 = sS[(w0 + gy)     * S_STRIDE + c0 + tg + 4];
            uint32_t a3 = sS[(w0 + gy + 8) * S_STRIDE + c0 + tg + 4];
#pragma unroll
            for (int n = 0; n < 8; n++) {
                uint32_t b0 = sW[(c0 + tg)     * W_STRIDE + (n << 3) + gy];
                uint32_t b1 = sW[(c0 + tg + 4) * W_STRIDE + (n << 3) + gy];
                MMA_TF32(acc + (n << 2), a0, a1, a2, a3, b0, b1);
            }
        }
        __syncthreads();
    }

#pragma unroll
    for (int n = 0; n < 8; n++) {
#pragma unroll
        for (int j = 0; j < 4; j++) {
            int o  = (n << 3) + (tg << 1) + (j & 1);
            int wr = w0 + gy + ((j >> 1) << 3);
            out[(((size_t)b * COUT + o) * HH + h) * WW + wr] =
                acc[(n << 2) + j] + __ldg(bias + o);
        }
    }
}

// ---------------------------------------------------------------------------
extern "C" void kernel_launch(void* const* d_in, const int* in_sizes, int n_in,
                              void* d_out, int out_size)
{
    const float* x    = (const float*)d_in[0];
    const float* wgt  = (const float*)d_in[1];
    const float* bias = (const float*)d_in[2];
    const float* pgw  = (const float*)d_in[3];
    const float* pgb  = (const float*)d_in[4];
    float* out = (float*)d_out;

    const int smem1 = (3 * X_TILE + CIN * PW_STRIDE) * (int)sizeof(uint32_t)
                    + WW * PD_STRIDE * (int)sizeof(float);   // 133728 B
    cudaFuncSetAttribute(param_mma_kernel,
                         cudaFuncAttributeMaxDynamicSharedMemorySize, smem1);

    const int smem2 = (WW * S_STRIDE + COUT * W_STRIDE) * (int)sizeof(float); // 53248 B
    cudaFuncSetAttribute(dcn_kernel,
                         cudaFuncAttributeMaxDynamicSharedMemorySize, smem2);

    const int nprep = KK * COUT * CIN + KK * CIN * 32;
    wprep_kernel<<<(nprep + 255) / 256, 256>>>(wgt, pgw);
    param_mma_kernel<<<BB * HH, 256, smem1>>>(x, pgb);
    dcn_kernel<<<BB * HH, 256, smem2>>>(x, bias, out);
}

// round 6
// speedup vs baseline: 2.7755x; 1.2449x over previous
#include <cuda_runtime.h>
#include <math.h>
#include <stdint.h>

#define BB   8
#define CIN  64
#define COUT 64
#define HH   128
#define WW   128
#define KK   9
#define NP   27
#define HW   (HH * WW)

#define S_STRIDE 68   // dcn S tile row stride (words)
#define W_STRIDE 72   // dcn W tile row stride (words)

#define X_STRIDE 68   // param X tile: [pos][c], 130 pos rows
#define X_TILE   (130 * X_STRIDE)
#define PW_STRIDE 36  // param W tile: [c][p32]
#define PD_STRIDE 36  // param D staging: [w][p32]

// ---------------------------------------------------------------------------
// Scratch (device globals: no allocation allowed)
// ---------------------------------------------------------------------------
__device__ int4     g_co[BB * KK * HW];      // bilinear corner offsets (plane-linear)
__device__ float4   g_cq[BB * KK * HW];      // corner weights (mask+validity folded)
__device__ uint32_t g_wt[KK * COUT * CIN];   // main weights [k][c][o], tf32 bits
__device__ uint32_t g_pw[KK * CIN * 32];     // param weights [t][c][p32], tf32 bits
__device__ float    g_xt[BB * HW * CIN];     // x transposed to NHWC: [b][y][x][c]

// ---------------------------------------------------------------------------
__device__ __forceinline__ uint32_t cvt_tf32(float f) {
    uint32_t u;
    asm("cvt.rna.tf32.f32 %0, %1;" : "=r"(u) : "f"(f));
    return u;
}

__device__ __forceinline__ void make_corner(float sy, float sx, float mk,
                                            int4& co, float4& cq) {
    float y0f = floorf(sy), x0f = floorf(sx);
    int   iy0 = (int)y0f,   ix0 = (int)x0f;
    float fy = sy - y0f,    fx = sx - x0f;
    float w00 = (1.f - fy) * (1.f - fx);
    float w01 = (1.f - fy) * fx;
    float w10 = fy * (1.f - fx);
    float w11 = fy * fx;
    bool oky0 = (iy0 >= 0) && (iy0 < HH);
    bool oky1 = (iy0 + 1 >= 0) && (iy0 + 1 < HH);
    bool okx0 = (ix0 >= 0) && (ix0 < WW);
    bool okx1 = (ix0 + 1 >= 0) && (ix0 + 1 < WW);
    int cy0 = min(max(iy0, 0), HH - 1);
    int cy1 = min(max(iy0 + 1, 0), HH - 1);
    int cx0 = min(max(ix0, 0), WW - 1);
    int cx1 = min(max(ix0 + 1, 0), WW - 1);
    co = make_int4(cy0 * WW + cx0, cy0 * WW + cx1, cy1 * WW + cx0, cy1 * WW + cx1);
    cq = make_float4((oky0 && okx0) ? w00 * mk : 0.f,
                     (oky0 && okx1) ? w01 * mk : 0.f,
                     (oky1 && okx0) ? w10 * mk : 0.f,
                     (oky1 && okx1) ? w11 * mk : 0.f);
}

#define MMA_TF32(d, a0, a1, a2, a3, b0, b1)                                   \
    asm volatile(                                                             \
        "mma.sync.aligned.m16n8k8.row.col.f32.tf32.tf32.f32 "                 \
        "{%0,%1,%2,%3}, {%4,%5,%6,%7}, {%8,%9}, {%0,%1,%2,%3};"               \
        : "+f"((d)[0]), "+f"((d)[1]), "+f"((d)[2]), "+f"((d)[3])              \
        : "r"(a0), "r"(a1), "r"(a2), "r"(a3), "r"(b0), "r"(b1))

// ---------------------------------------------------------------------------
// Kernel 0a: weight prep (tf32 bit conversion + relayout)
// ---------------------------------------------------------------------------
__global__ void wprep_kernel(const float* __restrict__ wgt,
                             const float* __restrict__ pgw) {
    int idx = blockIdx.x * blockDim.x + threadIdx.x;
    if (idx < KK * COUT * CIN) {
        int k = idx >> 12;
        int r = idx & 4095;
        int c = r >> 6;
        int o = r & 63;
        g_wt[idx] = cvt_tf32(wgt[o * (CIN * KK) + c * KK + k]);
    } else if (idx < KK * COUT * CIN + KK * CIN * 32) {
        int j = idx - KK * COUT * CIN;
        int t = j >> 11;
        int r = j & 2047;
        int c = r >> 5;
        int p = r & 31;
        g_pw[j] = (p < NP) ? cvt_tf32(pgw[p * (CIN * KK) + c * KK + t]) : 0u;
    }
}

// ---------------------------------------------------------------------------
// Kernel 0b: transpose x NCHW -> NHWC (g_xt[b][y][x][c])
// One block per (b,y). Reads coalesced along w; writes float4 along c.
// ---------------------------------------------------------------------------
__global__ void __launch_bounds__(256) transpose_kernel(const float* __restrict__ x) {
    const int b = blockIdx.x >> 7;
    const int y = blockIdx.x & 127;
    const int tid = threadIdx.x;
    const float* src = x + (size_t)b * CIN * HW + y * WW;     // + c*HW + w
    float*       dst = g_xt + ((size_t)b * HH + y) * WW * CIN; // + w*64 + c
#pragma unroll
    for (int i = 0; i < 8; i++) {
        int idx = tid + (i << 8);        // 2048 (c4, w) pairs
        int c0  = (idx >> 7) << 2;
        int w   = idx & 127;
        float4 v;
        v.x = __ldg(src + (size_t)(c0 + 0) * HW + w);
        v.y = __ldg(src + (size_t)(c0 + 1) * HW + w);
        v.z = __ldg(src + (size_t)(c0 + 2) * HW + w);
        v.w = __ldg(src + (size_t)(c0 + 3) * HW + w);
        *(float4*)(dst + w * CIN + c0) = v;
    }
}

// ---------------------------------------------------------------------------
// Kernel 1: param conv via mma.sync -> corner offsets/weights (unchanged R5)
// ---------------------------------------------------------------------------
__global__ void __launch_bounds__(256) param_mma_kernel(
    const float* __restrict__ x,
    const float* __restrict__ pgb)
{
    extern __shared__ __align__(16) uint32_t psm[];
    uint32_t* sX = psm;                              // [3][130][X_STRIDE]
    uint32_t* sW = psm + 3 * X_TILE;                 // [64][PW_STRIDE]
    float*    sD = (float*)(sW + CIN * PW_STRIDE);   // [128][PD_STRIDE]

    const int tid  = threadIdx.x;
    const int lane = tid & 31;
    const int wid  = tid >> 5;
    const int b    = blockIdx.x >> 7;
    const int h    = blockIdx.x & 127;

    const float* xb = x + (size_t)b * CIN * HW;
    const int w  = tid & 127;
    const int ch = tid >> 7;

    const int w0 = wid << 4;
    const int gy = lane >> 2;
    const int tg = lane & 3;

#pragma unroll
    for (int ti = 0; ti < 3; ti++) {
        int row = h - 1 + ti;
        bool okr = (row >= 0) && (row < HH);
        uint32_t* dst = sX + ti * X_TILE + (w + 1) * X_STRIDE;
#pragma unroll
        for (int cc4 = 0; cc4 < 8; cc4++) {
            int c0 = ch * 32 + cc4 * 4;
            uint32_t r[4];
#pragma unroll
            for (int j = 0; j < 4; j++)
                r[j] = okr ? cvt_tf32(__ldg(xb + ((size_t)(c0 + j) << 14) + row * WW + w)) : 0u;
            *(uint4*)(dst + c0) = make_uint4(r[0], r[1], r[2], r[3]);
        }
    }
    if (tid < 96) {
        int ti  = tid >> 5;
        int q   = tid & 31;
        int pos = (q >> 4) ? 129 : 0;
        int c4  = (q & 15) << 2;
        *(uint4*)(sX + ti * X_TILE + pos * X_STRIDE + c4) = make_uint4(0, 0, 0, 0);
    }

    float acc[16];
#pragma unroll
    for (int i = 0; i < 16; i++) acc[i] = 0.f;

    for (int t = 0; t < KK; t++) {
        __syncthreads();
        {
            const uint4* src = (const uint4*)(g_pw + (t << 11));
#pragma unroll
            for (int i = 0; i < 2; i++) {
                int idx = tid + (i << 8);
                uint4 v = __ldg(src + idx);
                int c  = idx >> 3;
                int p4 = (idx & 7) << 2;
                *(uint4*)(sW + c * PW_STRIDE + p4) = v;
            }
        }
        __syncthreads();

        const int ti = t / 3, tj = t % 3;
        const uint32_t* sXt = sX + ti * X_TILE + tj * X_STRIDE;
#pragma unroll
        for (int kc = 0; kc < 8; kc++) {
            int c0 = kc << 3;
            uint32_t a0 = sXt[(w0 + gy)     * X_STRIDE + c0 + tg];
            uint32_t a1 = sXt[(w0 + gy + 8) * X_STRIDE + c0 + tg];
            uint32_t a2 = sXt[(w0 + gy)     * X_STRIDE + c0 + tg + 4];
            uint32_t a3 = sXt[(w0 + gy + 8) * X_STRIDE + c0 + tg + 4];
#pragma unroll
            for (int n = 0; n < 4; n++) {
                uint32_t b0 = sW[(c0 + tg)     * PW_STRIDE + (n << 3) + gy];
                uint32_t b1 = sW[(c0 + tg + 4) * PW_STRIDE + (n << 3) + gy];
                MMA_TF32(acc + (n << 2), a0, a1, a2, a3, b0, b1);
            }
        }
    }
    __syncthreads();

#pragma unroll
    for (int n = 0; n < 4; n++) {
#pragma unroll
        for (int j = 0; j < 4; j++) {
            int p  = (n << 3) + (tg << 1) + (j & 1);
            int wr = w0 + gy + ((j >> 1) << 3);
            sD[wr * PD_STRIDE + p] = acc[(n << 2) + j];
        }
    }
    __syncthreads();

    if (tid < WW) {
        float prm[NP];
#pragma unroll
        for (int p = 0; p < NP; p++)
            prm[p] = sD[tid * PD_STRIDE + p] + __ldg(pgb + p);
        const int base = b * KK * HW + h * WW + tid;
#pragma unroll
        for (int k = 0; k < KK; k++) {
            int ki = k / 3, kj = k % 3;
            int4 co; float4 cq;
            make_corner((float)(h - 1 + ki) + prm[2 * k],
                        (float)(tid - 1 + kj) + prm[2 * k + 1],
                        1.f / (1.f + expf(-prm[18 + k])), co, cq);
            g_co[base + k * HW] = co;
            g_cq[base + k * HW] = cq;
        }
    }
}

// ---------------------------------------------------------------------------
// Kernel 2: DCN main. Sampling now reads NHWC (g_xt) with float4 gathers:
// lane = (c-group 0..15, pixel 0..1); per round each lane does 4 LDG.128
// (one per bilinear corner, 256B-aligned contiguous blocks) -> 4x fewer
// load instructions than the scalar NCHW gather. MMA unchanged.
// ---------------------------------------------------------------------------
__global__ void __launch_bounds__(256) dcn_kernel(
    const float* __restrict__ bias,
    float* __restrict__ out)
{
    extern __shared__ __align__(16) float sm[];
    uint32_t* sS = (uint32_t*)sm;                 // [128][S_STRIDE]
    uint32_t* sW = (uint32_t*)sm + WW * S_STRIDE; // [64][W_STRIDE]

    const int tid  = threadIdx.x;
    const int lane = tid & 31;
    const int wid  = tid >> 5;
    const int b    = blockIdx.x >> 7;
    const int h    = blockIdx.x & 127;

    const int cl = lane & 15;        // c-group: channels cl*4 .. cl*4+3
    const int wp = lane >> 4;        // pixel parity within round
    const float* xb4 = g_xt + ((size_t)b << 20);   // b * HW * 64
    const int prow = b * KK * HW + h * WW;

    const int w0 = wid << 4;
    const int gy = lane >> 2;
    const int tg = lane & 3;

    float acc[32];
#pragma unroll
    for (int i = 0; i < 32; i++) acc[i] = 0.f;

    for (int k = 0; k < KK; k++) {
        // ---- stage W_k: vectorized 16KB copy into [c][W_STRIDE] ----
        {
            const uint4* src = (const uint4*)(g_wt + (k << 12));
#pragma unroll
            for (int i = 0; i < 4; i++) {
                int idx = tid + (i << 8);          // 1024 uint4
                uint4 v = __ldg(src + idx);
                int c  = idx >> 4;
                int o4 = (idx & 15) << 2;
                *(uint4*)(sW + c * W_STRIDE + o4) = v;
            }
        }
        // ---- stage S_k: NHWC float4 bilinear gather ----
        {
            const int pk = prow + k * HW;
#pragma unroll
            for (int r = 0; r < 8; r++) {
                int w = w0 + (r << 1) + wp;
                int4   co = __ldg(&g_co[pk + w]);
                float4 cq = __ldg(&g_cq[pk + w]);
                float4 f0 = __ldg((const float4*)(xb4 + ((size_t)co.x << 6)) + cl);
                float4 f1 = __ldg((const float4*)(xb4 + ((size_t)co.y << 6)) + cl);
                float4 f2 = __ldg((const float4*)(xb4 + ((size_t)co.z << 6)) + cl);
                float4 f3 = __ldg((const float4*)(xb4 + ((size_t)co.w << 6)) + cl);
                float4 s;
                s.x = cq.x * f0.x + cq.y * f1.x + cq.z * f2.x + cq.w * f3.x;
                s.y = cq.x * f0.y + cq.y * f1.y + cq.z * f2.y + cq.w * f3.y;
                s.z = cq.x * f0.z + cq.y * f1.z + cq.z * f2.z + cq.w * f3.z;
                s.w = cq.x * f0.w + cq.y * f1.w + cq.z * f2.w + cq.w * f3.w;
                *(uint4*)(sS + w * S_STRIDE + (cl << 2)) =
                    make_uint4(cvt_tf32(s.x), cvt_tf32(s.y), cvt_tf32(s.z), cvt_tf32(s.w));
            }
        }
        __syncthreads();

        // ---- MMA: 8 K-chunks of 8; A frag shared across 8 n-tiles ----
#pragma unroll
        for (int kc = 0; kc < 8; kc++) {
            int c0 = kc << 3;
            uint32_t a0 = sS[(w0 + gy)     * S_STRIDE + c0 + tg];
            uint32_t a1 = sS[(w0 + gy + 8) * S_STRIDE + c0 + tg];
            uint32_t a2 = sS[(w0 + gy)     * S_STRIDE + c0 + tg + 4];
            uint32_t a3 = sS[(w0 + gy + 8) * S_STRIDE + c0 + tg + 4];
#pragma unroll
            for (int n = 0; n < 8; n++) {
                uint32_t b0 = sW[(c0 + tg)     * W_STRIDE + (n << 3) + gy];
                uint32_t b1 = sW[(c0 + tg + 4) * W_STRIDE + (n << 3) + gy];
                MMA_TF32(acc + (n << 2), a0, a1, a2, a3, b0, b1);
            }
        }
        __syncthreads();
    }

    // ---- epilogue ----
#pragma unroll
    for (int n = 0; n < 8; n++) {
#pragma unroll
        for (int j = 0; j < 4; j++) {
            int o  = (n << 3) + (tg << 1) + (j & 1);
            int wr = w0 + gy + ((j >> 1) << 3);
            out[(((size_t)b * COUT + o) * HH + h) * WW + wr] =
                acc[(n << 2) + j] + __ldg(bias + o);
        }
    }
}

// ---------------------------------------------------------------------------
extern "C" void kernel_launch(void* const* d_in, const int* in_sizes, int n_in,
                              void* d_out, int out_size)
{
    const float* x    = (const float*)d_in[0];
    const float* wgt  = (const float*)d_in[1];
    const float* bias = (const float*)d_in[2];
    const float* pgw  = (const float*)d_in[3];
    const float* pgb  = (const float*)d_in[4];
    float* out = (float*)d_out;

    const int smem1 = (3 * X_TILE + CIN * PW_STRIDE) * (int)sizeof(uint32_t)
                    + WW * PD_STRIDE * (int)sizeof(float);
    cudaFuncSetAttribute(param_mma_kernel,
                         cudaFuncAttributeMaxDynamicSharedMemorySize, smem1);

    const int smem2 = (WW * S_STRIDE + COUT * W_STRIDE) * (int)sizeof(float);
    cudaFuncSetAttribute(dcn_kernel,
                         cudaFuncAttributeMaxDynamicSharedMemorySize, smem2);

    const int nprep = KK * COUT * CIN + KK * CIN * 32;
    wprep_kernel<<<(nprep + 255) / 256, 256>>>(wgt, pgw);
    transpose_kernel<<<BB * HH, 256>>>(x);
    param_mma_kernel<<<BB * HH, 256, smem1>>>(x, pgb);
    dcn_kernel<<<BB * HH, 256, smem2>>>(bias, out);
}

// round 7
// speedup vs baseline: 3.1078x; 1.1197x over previous
#include <cuda_runtime.h>
#include <cuda_fp16.h>
#include <math.h>
#include <stdint.h>

#define BB   8
#define CIN  64
#define COUT 64
#define HH   128
#define WW   128
#define KK   9
#define NP   27
#define HW   (HH * WW)

#define S_STRIDE 68   // dcn S tile row stride (words)
#define W_STRIDE 72   // dcn W tile row stride (words)
#define BUF_SZ   (WW * S_STRIDE + COUT * W_STRIDE)   // words per double-buffer slot

#define X_STRIDE 68   // param X tile: [pos][c], 130 pos rows
#define X_TILE   (130 * X_STRIDE)
#define PW_STRIDE 36
#define PD_STRIDE 36

// ---------------------------------------------------------------------------
// Scratch (device globals: no allocation allowed)
// ---------------------------------------------------------------------------
__device__ int4     g_co[BB * KK * HW];      // bilinear corner offsets (plane-linear)
__device__ float4   g_cq[BB * KK * HW];      // corner weights (mask+validity folded)
__device__ uint32_t g_wt[KK * COUT * CIN];   // main weights [k][c][o], tf32 bits
__device__ uint32_t g_pw[KK * CIN * 32];     // param weights [t][c][p32], tf32 bits
__device__ __half   g_xh[BB * HW * CIN];     // x as fp16 NHWC: [b][y][x][c]

// ---------------------------------------------------------------------------
__device__ __forceinline__ uint32_t cvt_tf32(float f) {
    uint32_t u;
    asm("cvt.rna.tf32.f32 %0, %1;" : "=r"(u) : "f"(f));
    return u;
}

__device__ __forceinline__ void make_corner(float sy, float sx, float mk,
                                            int4& co, float4& cq) {
    float y0f = floorf(sy), x0f = floorf(sx);
    int   iy0 = (int)y0f,   ix0 = (int)x0f;
    float fy = sy - y0f,    fx = sx - x0f;
    float w00 = (1.f - fy) * (1.f - fx);
    float w01 = (1.f - fy) * fx;
    float w10 = fy * (1.f - fx);
    float w11 = fy * fx;
    bool oky0 = (iy0 >= 0) && (iy0 < HH);
    bool oky1 = (iy0 + 1 >= 0) && (iy0 + 1 < HH);
    bool okx0 = (ix0 >= 0) && (ix0 < WW);
    bool okx1 = (ix0 + 1 >= 0) && (ix0 + 1 < WW);
    int cy0 = min(max(iy0, 0), HH - 1);
    int cy1 = min(max(iy0 + 1, 0), HH - 1);
    int cx0 = min(max(ix0, 0), WW - 1);
    int cx1 = min(max(ix0 + 1, 0), WW - 1);
    co = make_int4(cy0 * WW + cx0, cy0 * WW + cx1, cy1 * WW + cx0, cy1 * WW + cx1);
    cq = make_float4((oky0 && okx0) ? w00 * mk : 0.f,
                     (oky0 && okx1) ? w01 * mk : 0.f,
                     (oky1 && okx0) ? w10 * mk : 0.f,
                     (oky1 && okx1) ? w11 * mk : 0.f);
}

#define MMA_TF32(d, a0, a1, a2, a3, b0, b1)                                   \
    asm volatile(                                                             \
        "mma.sync.aligned.m16n8k8.row.col.f32.tf32.tf32.f32 "                 \
        "{%0,%1,%2,%3}, {%4,%5,%6,%7}, {%8,%9}, {%0,%1,%2,%3};"               \
        : "+f"((d)[0]), "+f"((d)[1]), "+f"((d)[2]), "+f"((d)[3])              \
        : "r"(a0), "r"(a1), "r"(a2), "r"(a3), "r"(b0), "r"(b1))

// ---------------------------------------------------------------------------
// Kernel 0a: weight prep (tf32 bit conversion + relayout)
// ---------------------------------------------------------------------------
__global__ void wprep_kernel(const float* __restrict__ wgt,
                             const float* __restrict__ pgw) {
    int idx = blockIdx.x * blockDim.x + threadIdx.x;
    if (idx < KK * COUT * CIN) {
        int k = idx >> 12;
        int r = idx & 4095;
        int c = r >> 6;
        int o = r & 63;
        g_wt[idx] = cvt_tf32(wgt[o * (CIN * KK) + c * KK + k]);
    } else if (idx < KK * COUT * CIN + KK * CIN * 32) {
        int j = idx - KK * COUT * CIN;
        int t = j >> 11;
        int r = j & 2047;
        int c = r >> 5;
        int p = r & 31;
        g_pw[j] = (p < NP) ? cvt_tf32(pgw[p * (CIN * KK) + c * KK + t]) : 0u;
    }
}

// ---------------------------------------------------------------------------
// Kernel 0b: transpose x NCHW -> fp16 NHWC (g_xh[b][y][x][c])
// ---------------------------------------------------------------------------
__global__ void __launch_bounds__(256) transpose_kernel(const float* __restrict__ x) {
    const int b = blockIdx.x >> 7;
    const int y = blockIdx.x & 127;
    const int tid = threadIdx.x;
    const float* src = x + (size_t)b * CIN * HW + y * WW;       // + c*HW + w
    __half*      dst = g_xh + ((size_t)b * HH + y) * WW * CIN;  // + w*64 + c
#pragma unroll
    for (int i = 0; i < 8; i++) {
        int idx = tid + (i << 8);        // 2048 (c4, w) pairs
        int c0  = (idx >> 7) << 2;
        int w   = idx & 127;
        float2 v0, v1;
        v0.x = __ldg(src + (size_t)(c0 + 0) * HW + w);
        v0.y = __ldg(src + (size_t)(c0 + 1) * HW + w);
        v1.x = __ldg(src + (size_t)(c0 + 2) * HW + w);
        v1.y = __ldg(src + (size_t)(c0 + 3) * HW + w);
        __half2 h0 = __float22half2_rn(v0);
        __half2 h1 = __float22half2_rn(v1);
        uint2 pk;
        pk.x = *(uint32_t*)&h0;
        pk.y = *(uint32_t*)&h1;
        *(uint2*)(dst + w * CIN + c0) = pk;
    }
}

// ---------------------------------------------------------------------------
// Kernel 1: param conv via mma.sync -> corner offsets/weights (unchanged)
// ---------------------------------------------------------------------------
__global__ void __launch_bounds__(256) param_mma_kernel(
    const float* __restrict__ x,
    const float* __restrict__ pgb)
{
    extern __shared__ __align__(16) uint32_t psm[];
    uint32_t* sX = psm;                              // [3][130][X_STRIDE]
    uint32_t* sW = psm + 3 * X_TILE;                 // [64][PW_STRIDE]
    float*    sD = (float*)(sW + CIN * PW_STRIDE);   // [128][PD_STRIDE]

    const int tid  = threadIdx.x;
    const int lane = tid & 31;
    const int wid  = tid >> 5;
    const int b    = blockIdx.x >> 7;
    const int h    = blockIdx.x & 127;

    const float* xb = x + (size_t)b * CIN * HW;
    const int w  = tid & 127;
    const int ch = tid >> 7;

    const int w0 = wid << 4;
    const int gy = lane >> 2;
    const int tg = lane & 3;

#pragma unroll
    for (int ti = 0; ti < 3; ti++) {
        int row = h - 1 + ti;
        bool okr = (row >= 0) && (row < HH);
        uint32_t* dst = sX + ti * X_TILE + (w + 1) * X_STRIDE;
#pragma unroll
        for (int cc4 = 0; cc4 < 8; cc4++) {
            int c0 = ch * 32 + cc4 * 4;
            uint32_t r[4];
#pragma unroll
            for (int j = 0; j < 4; j++)
                r[j] = okr ? cvt_tf32(__ldg(xb + ((size_t)(c0 + j) << 14) + row * WW + w)) : 0u;
            *(uint4*)(dst + c0) = make_uint4(r[0], r[1], r[2], r[3]);
        }
    }
    if (tid < 96) {
        int ti  = tid >> 5;
        int q   = tid & 31;
        int pos = (q >> 4) ? 129 : 0;
        int c4  = (q & 15) << 2;
        *(uint4*)(sX + ti * X_TILE + pos * X_STRIDE + c4) = make_uint4(0, 0, 0, 0);
    }

    float acc[16];
#pragma unroll
    for (int i = 0; i < 16; i++) acc[i] = 0.f;

    for (int t = 0; t < KK; t++) {
        __syncthreads();
        {
            const uint4* src = (const uint4*)(g_pw + (t << 11));
#pragma unroll
            for (int i = 0; i < 2; i++) {
                int idx = tid + (i << 8);
                uint4 v = __ldg(src + idx);
                int c  = idx >> 3;
                int p4 = (idx & 7) << 2;
                *(uint4*)(sW + c * PW_STRIDE + p4) = v;
            }
        }
        __syncthreads();

        const int ti = t / 3, tj = t % 3;
        const uint32_t* sXt = sX + ti * X_TILE + tj * X_STRIDE;
#pragma unroll
        for (int kc = 0; kc < 8; kc++) {
            int c0 = kc << 3;
            uint32_t a0 = sXt[(w0 + gy)     * X_STRIDE + c0 + tg];
            uint32_t a1 = sXt[(w0 + gy + 8) * X_STRIDE + c0 + tg];
            uint32_t a2 = sXt[(w0 + gy)     * X_STRIDE + c0 + tg + 4];
            uint32_t a3 = sXt[(w0 + gy + 8) * X_STRIDE + c0 + tg + 4];
#pragma unroll
            for (int n = 0; n < 4; n++) {
                uint32_t b0 = sW[(c0 + tg)     * PW_STRIDE + (n << 3) + gy];
                uint32_t b1 = sW[(c0 + tg + 4) * PW_STRIDE + (n << 3) + gy];
                MMA_TF32(acc + (n << 2), a0, a1, a2, a3, b0, b1);
            }
        }
    }
    __syncthreads();

#pragma unroll
    for (int n = 0; n < 4; n++) {
#pragma unroll
        for (int j = 0; j < 4; j++) {
            int p  = (n << 3) + (tg << 1) + (j & 1);
            int wr = w0 + gy + ((j >> 1) << 3);
            sD[wr * PD_STRIDE + p] = acc[(n << 2) + j];
        }
    }
    __syncthreads();

    if (tid < WW) {
        float prm[NP];
#pragma unroll
        for (int p = 0; p < NP; p++)
            prm[p] = sD[tid * PD_STRIDE + p] + __ldg(pgb + p);
        const int base = b * KK * HW + h * WW + tid;
#pragma unroll
        for (int k = 0; k < KK; k++) {
            int ki = k / 3, kj = k % 3;
            int4 co; float4 cq;
            make_corner((float)(h - 1 + ki) + prm[2 * k],
                        (float)(tid - 1 + kj) + prm[2 * k + 1],
                        1.f / (1.f + expf(-prm[18 + k])), co, cq);
            g_co[base + k * HW] = co;
            g_cq[base + k * HW] = cq;
        }
    }
}

// ---------------------------------------------------------------------------
// Kernel 2: DCN main. fp16 NHWC gathers (LDG.128 = 8 channels/corner) +
// double-buffered S/W tiles with a single __syncthreads per tap:
//   for k: stage(buf[k&1]); sync; mma(buf[k&1]);
// The sync at tap k-1 already orders every warp's mma(k-2) before any
// warp's stage(k) on the same buffer, so no trailing barrier is needed.
// ---------------------------------------------------------------------------
__global__ void __launch_bounds__(256) dcn_kernel(
    const float* __restrict__ bias,
    float* __restrict__ out)
{
    extern __shared__ __align__(16) uint32_t sm[];   // 2 * BUF_SZ words

    const int tid  = threadIdx.x;
    const int lane = tid & 31;
    const int wid  = tid >> 5;
    const int b    = blockIdx.x >> 7;
    const int h    = blockIdx.x & 127;

    const int cg = lane & 7;         // c-group: channels cg*8 .. cg*8+7
    const int px = lane >> 3;        // pixel 0..3 within round
    const __half* xh = g_xh + ((size_t)b << 20);   // b * HW * 64
    const int prow = b * KK * HW + h * WW;

    const int w0 = wid << 4;
    const int gy = lane >> 2;
    const int tg = lane & 3;

    float acc[32];
#pragma unroll
    for (int i = 0; i < 32; i++) acc[i] = 0.f;

    for (int k = 0; k < KK; k++) {
        uint32_t* sS = sm + (k & 1) * BUF_SZ;
        uint32_t* sW = sS + WW * S_STRIDE;

        // ---- stage W_k: vectorized 16KB copy into [c][W_STRIDE] ----
        {
            const uint4* src = (const uint4*)(g_wt + (k << 12));
#pragma unroll
            for (int i = 0; i < 4; i++) {
                int idx = tid + (i << 8);          // 1024 uint4
                uint4 v = __ldg(src + idx);
                int c  = idx >> 4;
                int o4 = (idx & 15) << 2;
                *(uint4*)(sW + c * W_STRIDE + o4) = v;
            }
        }
        // ---- stage S_k: fp16 NHWC gather, 8 channels per LDG.128 ----
        {
            const int pk = prow + k * HW;
#pragma unroll
            for (int r = 0; r < 4; r++) {
                int w = w0 + (r << 2) + px;
                int4   co = __ldg(&g_co[pk + w]);
                float4 cq = __ldg(&g_cq[pk + w]);
                uint4 u0 = __ldg((const uint4*)(xh + ((size_t)co.x << 6)) + cg);
                uint4 u1 = __ldg((const uint4*)(xh + ((size_t)co.y << 6)) + cg);
                uint4 u2 = __ldg((const uint4*)(xh + ((size_t)co.z << 6)) + cg);
                uint4 u3 = __ldg((const uint4*)(xh + ((size_t)co.w << 6)) + cg);
                const __half2* p0 = (const __half2*)&u0;
                const __half2* p1 = (const __half2*)&u1;
                const __half2* p2 = (const __half2*)&u2;
                const __half2* p3 = (const __half2*)&u3;
                uint32_t res[8];
#pragma unroll
                for (int j = 0; j < 4; j++) {
                    float2 f0 = __half22float2(p0[j]);
                    float2 f1 = __half22float2(p1[j]);
                    float2 f2 = __half22float2(p2[j]);
                    float2 f3 = __half22float2(p3[j]);
                    res[2 * j]     = cvt_tf32(cq.x * f0.x + cq.y * f1.x + cq.z * f2.x + cq.w * f3.x);
                    res[2 * j + 1] = cvt_tf32(cq.x * f0.y + cq.y * f1.y + cq.z * f2.y + cq.w * f3.y);
                }
                uint32_t* dst = sS + w * S_STRIDE + (cg << 3);
                *(uint4*)(dst)     = make_uint4(res[0], res[1], res[2], res[3]);
                *(uint4*)(dst + 4) = make_uint4(res[4], res[5], res[6], res[7]);
            }
        }
        __syncthreads();

        // ---- MMA: 8 K-chunks of 8; A frag shared across 8 n-tiles ----
#pragma unroll
        for (int kc = 0; kc < 8; kc++) {
            int c0 = kc << 3;
            uint32_t a0 = sS[(w0 + gy)     * S_STRIDE + c0 + tg];
            uint32_t a1 = sS[(w0 + gy + 8) * S_STRIDE + c0 + tg];
            uint32_t a2 = sS[(w0 + gy)     * S_STRIDE + c0 + tg + 4];
            uint32_t a3 = sS[(w0 + gy + 8) * S_STRIDE + c0 + tg + 4];
#pragma unroll
            for (int n = 0; n < 8; n++) {
                uint32_t b0 = sW[(c0 + tg)     * W_STRIDE + (n << 3) + gy];
                uint32_t b1 = sW[(c0 + tg + 4) * W_STRIDE + (n << 3) + gy];
                MMA_TF32(acc + (n << 2), a0, a1, a2, a3, b0, b1);
            }
        }
    }

    // ---- epilogue ----
#pragma unroll
    for (int n = 0; n < 8; n++) {
#pragma unroll
        for (int j = 0; j < 4; j++) {
            int o  = (n << 3) + (tg << 1) + (j & 1);
            int wr = w0 + gy + ((j >> 1) << 3);
            out[(((size_t)b * COUT + o) * HH + h) * WW + wr] =
                acc[(n << 2) + j] + __ldg(bias + o);
        }
    }
}

// ---------------------------------------------------------------------------
extern "C" void kernel_launch(void* const* d_in, const int* in_sizes, int n_in,
                              void* d_out, int out_size)
{
    const float* x    = (const float*)d_in[0];
    const float* wgt  = (const float*)d_in[1];
    const float* bias = (const float*)d_in[2];
    const float* pgw  = (const float*)d_in[3];
    const float* pgb  = (const float*)d_in[4];
    float* out = (float*)d_out;

    const int smem1 = (3 * X_TILE + CIN * PW_STRIDE) * (int)sizeof(uint32_t)
                    + WW * PD_STRIDE * (int)sizeof(float);
    cudaFuncSetAttribute(param_mma_kernel,
                         cudaFuncAttributeMaxDynamicSharedMemorySize, smem1);

    const int smem2 = 2 * BUF_SZ * (int)sizeof(uint32_t);   // 106496 B
    cudaFuncSetAttribute(dcn_kernel,
                         cudaFuncAttributeMaxDynamicSharedMemorySize, smem2);

    const int nprep = KK * COUT * CIN + KK * CIN * 32;
    wprep_kernel<<<(nprep + 255) / 256, 256>>>(wgt, pgw);
    transpose_kernel<<<BB * HH, 256>>>(x);
    param_mma_kernel<<<BB * HH, 256, smem1>>>(x, pgb);
    dcn_kernel<<<BB * HH, 256, smem2>>>(bias, out);
}

// round 8
// speedup vs baseline: 3.8400x; 1.2356x over previous
#include <cuda_runtime.h>
#include <cuda_fp16.h>
#include <math.h>
#include <stdint.h>

#define BB   8
#define CIN  64
#define COUT 64
#define HH   128
#define WW   128
#define KK   9
#define NP   27
#define HW   (HH * WW)

// fp16 dcn tiles: rows padded to 72 halves (144 B) -> ldmatrix conflict-free
#define SH_STRIDE 72
#define BUF_H     (WW * SH_STRIDE + COUT * SH_STRIDE)   // halves per buffer slot

#define X_STRIDE 68   // param X tile: [pos][c], 130 pos rows (tf32 words)
#define X_TILE   (130 * X_STRIDE)
#define PW_STRIDE 36
#define PD_STRIDE 36

// ---------------------------------------------------------------------------
// Scratch (device globals: no allocation allowed)
// ---------------------------------------------------------------------------
__device__ int4     g_co[BB * KK * HW];      // bilinear corner offsets
__device__ float4   g_cq[BB * KK * HW];      // corner weights (mask folded)
__device__ __half   g_wt[KK * COUT * CIN];   // main weights [k][o][c], fp16
__device__ uint32_t g_pw[KK * CIN * 32];     // param weights [t][c][p32], tf32 bits
__device__ __half   g_xh[BB * HW * CIN];     // x as fp16 NHWC: [b][y][x][c]

// ---------------------------------------------------------------------------
__device__ __forceinline__ uint32_t cvt_tf32(float f) {
    uint32_t u;
    asm("cvt.rna.tf32.f32 %0, %1;" : "=r"(u) : "f"(f));
    return u;
}

__device__ __forceinline__ uint32_t smem_u32(const void* p) {
    uint32_t a;
    asm("{ .reg .u64 t; cvta.to.shared.u64 t, %1; cvt.u32.u64 %0, t; }" : "=r"(a) : "l"(p));
    return a;
}

__device__ __forceinline__ void make_corner(float sy, float sx, float mk,
                                            int4& co, float4& cq) {
    float y0f = floorf(sy), x0f = floorf(sx);
    int   iy0 = (int)y0f,   ix0 = (int)x0f;
    float fy = sy - y0f,    fx = sx - x0f;
    float w00 = (1.f - fy) * (1.f - fx);
    float w01 = (1.f - fy) * fx;
    float w10 = fy * (1.f - fx);
    float w11 = fy * fx;
    bool oky0 = (iy0 >= 0) && (iy0 < HH);
    bool oky1 = (iy0 + 1 >= 0) && (iy0 + 1 < HH);
    bool okx0 = (ix0 >= 0) && (ix0 < WW);
    bool okx1 = (ix0 + 1 >= 0) && (ix0 + 1 < WW);
    int cy0 = min(max(iy0, 0), HH - 1);
    int cy1 = min(max(iy0 + 1, 0), HH - 1);
    int cx0 = min(max(ix0, 0), WW - 1);
    int cx1 = min(max(ix0 + 1, 0), WW - 1);
    co = make_int4(cy0 * WW + cx0, cy0 * WW + cx1, cy1 * WW + cx0, cy1 * WW + cx1);
    cq = make_float4((oky0 && okx0) ? w00 * mk : 0.f,
                     (oky0 && okx1) ? w01 * mk : 0.f,
                     (oky1 && okx0) ? w10 * mk : 0.f,
                     (oky1 && okx1) ? w11 * mk : 0.f);
}

#define MMA_TF32(d, a0, a1, a2, a3, b0, b1)                                   \
    asm volatile(                                                             \
        "mma.sync.aligned.m16n8k8.row.col.f32.tf32.tf32.f32 "                 \
        "{%0,%1,%2,%3}, {%4,%5,%6,%7}, {%8,%9}, {%0,%1,%2,%3};"               \
        : "+f"((d)[0]), "+f"((d)[1]), "+f"((d)[2]), "+f"((d)[3])              \
        : "r"(a0), "r"(a1), "r"(a2), "r"(a3), "r"(b0), "r"(b1))

#define MMA_F16(d, a0, a1, a2, a3, b0, b1)                                    \
    asm volatile(                                                             \
        "mma.sync.aligned.m16n8k16.row.col.f32.f16.f16.f32 "                  \
        "{%0,%1,%2,%3}, {%4,%5,%6,%7}, {%8,%9}, {%0,%1,%2,%3};"               \
        : "+f"((d)[0]), "+f"((d)[1]), "+f"((d)[2]), "+f"((d)[3])              \
        : "r"(a0), "r"(a1), "r"(a2), "r"(a3), "r"(b0), "r"(b1))

#define LDMATRIX_X4(r0, r1, r2, r3, addr)                                     \
    asm volatile("ldmatrix.sync.aligned.m8n8.x4.shared.b16 {%0,%1,%2,%3}, [%4];" \
                 : "=r"(r0), "=r"(r1), "=r"(r2), "=r"(r3) : "r"(addr))

// ---------------------------------------------------------------------------
// Kernel 0a: weight prep
//   g_wt[k][o][c] fp16  from wgt[o][c][k]
//   g_pw[t][c][p] tf32  from pgw[p][c][t]
// ---------------------------------------------------------------------------
__global__ void wprep_kernel(const float* __restrict__ wgt,
                             const float* __restrict__ pgw) {
    int idx = blockIdx.x * blockDim.x + threadIdx.x;
    if (idx < KK * COUT * CIN) {
        int k = idx >> 12;
        int r = idx & 4095;
        int o = r >> 6;
        int c = r & 63;
        g_wt[idx] = __float2half(wgt[o * (CIN * KK) + c * KK + k]);
    } else if (idx < KK * COUT * CIN + KK * CIN * 32) {
        int j = idx - KK * COUT * CIN;
        int t = j >> 11;
        int r = j & 2047;
        int c = r >> 5;
        int p = r & 31;
        g_pw[j] = (p < NP) ? cvt_tf32(pgw[p * (CIN * KK) + c * KK + t]) : 0u;
    }
}

// ---------------------------------------------------------------------------
// Kernel 0b: transpose x NCHW -> fp16 NHWC
// ---------------------------------------------------------------------------
__global__ void __launch_bounds__(256) transpose_kernel(const float* __restrict__ x) {
    const int b = blockIdx.x >> 7;
    const int y = blockIdx.x & 127;
    const int tid = threadIdx.x;
    const float* src = x + (size_t)b * CIN * HW + y * WW;
    __half*      dst = g_xh + ((size_t)b * HH + y) * WW * CIN;
#pragma unroll
    for (int i = 0; i < 8; i++) {
        int idx = tid + (i << 8);
        int c0  = (idx >> 7) << 2;
        int w   = idx & 127;
        float2 v0, v1;
        v0.x = __ldg(src + (size_t)(c0 + 0) * HW + w);
        v0.y = __ldg(src + (size_t)(c0 + 1) * HW + w);
        v1.x = __ldg(src + (size_t)(c0 + 2) * HW + w);
        v1.y = __ldg(src + (size_t)(c0 + 3) * HW + w);
        __half2 h0 = __float22half2_rn(v0);
        __half2 h1 = __float22half2_rn(v1);
        uint2 pk;
        pk.x = *(uint32_t*)&h0;
        pk.y = *(uint32_t*)&h1;
        *(uint2*)(dst + w * CIN + c0) = pk;
    }
}

// ---------------------------------------------------------------------------
// Kernel 1: param conv via tf32 mma.sync (unchanged from R5/R6/R7)
// ---------------------------------------------------------------------------
__global__ void __launch_bounds__(256) param_mma_kernel(
    const float* __restrict__ x,
    const float* __restrict__ pgb)
{
    extern __shared__ __align__(16) uint32_t psm[];
    uint32_t* sX = psm;                              // [3][130][X_STRIDE]
    uint32_t* sW = psm + 3 * X_TILE;                 // [64][PW_STRIDE]
    float*    sD = (float*)(sW + CIN * PW_STRIDE);   // [128][PD_STRIDE]

    const int tid  = threadIdx.x;
    const int lane = tid & 31;
    const int wid  = tid >> 5;
    const int b    = blockIdx.x >> 7;
    const int h    = blockIdx.x & 127;

    const float* xb = x + (size_t)b * CIN * HW;
    const int w  = tid & 127;
    const int ch = tid >> 7;

    const int w0 = wid << 4;
    const int gy = lane >> 2;
    const int tg = lane & 3;

#pragma unroll
    for (int ti = 0; ti < 3; ti++) {
        int row = h - 1 + ti;
        bool okr = (row >= 0) && (row < HH);
        uint32_t* dst = sX + ti * X_TILE + (w + 1) * X_STRIDE;
#pragma unroll
        for (int cc4 = 0; cc4 < 8; cc4++) {
            int c0 = ch * 32 + cc4 * 4;
            uint32_t r[4];
#pragma unroll
            for (int j = 0; j < 4; j++)
                r[j] = okr ? cvt_tf32(__ldg(xb + ((size_t)(c0 + j) << 14) + row * WW + w)) : 0u;
            *(uint4*)(dst + c0) = make_uint4(r[0], r[1], r[2], r[3]);
        }
    }
    if (tid < 96) {
        int ti  = tid >> 5;
        int q   = tid & 31;
        int pos = (q >> 4) ? 129 : 0;
        int c4  = (q & 15) << 2;
        *(uint4*)(sX + ti * X_TILE + pos * X_STRIDE + c4) = make_uint4(0, 0, 0, 0);
    }

    float acc[16];
#pragma unroll
    for (int i = 0; i < 16; i++) acc[i] = 0.f;

    for (int t = 0; t < KK; t++) {
        __syncthreads();
        {
            const uint4* src = (const uint4*)(g_pw + (t << 11));
#pragma unroll
            for (int i = 0; i < 2; i++) {
                int idx = tid + (i << 8);
                uint4 v = __ldg(src + idx);
                int c  = idx >> 3;
                int p4 = (idx & 7) << 2;
                *(uint4*)(sW + c * PW_STRIDE + p4) = v;
            }
        }
        __syncthreads();

        const int ti = t / 3, tj = t % 3;
        const uint32_t* sXt = sX + ti * X_TILE + tj * X_STRIDE;
#pragma unroll
        for (int kc = 0; kc < 8; kc++) {
            int c0 = kc << 3;
            uint32_t a0 = sXt[(w0 + gy)     * X_STRIDE + c0 + tg];
            uint32_t a1 = sXt[(w0 + gy + 8) * X_STRIDE + c0 + tg];
            uint32_t a2 = sXt[(w0 + gy)     * X_STRIDE + c0 + tg + 4];
            uint32_t a3 = sXt[(w0 + gy + 8) * X_STRIDE + c0 + tg + 4];
#pragma unroll
            for (int n = 0; n < 4; n++) {
                uint32_t b0 = sW[(c0 + tg)     * PW_STRIDE + (n << 3) + gy];
                uint32_t b1 = sW[(c0 + tg + 4) * PW_STRIDE + (n << 3) + gy];
                MMA_TF32(acc + (n << 2), a0, a1, a2, a3, b0, b1);
            }
        }
    }
    __syncthreads();

#pragma unroll
    for (int n = 0; n < 4; n++) {
#pragma unroll
        for (int j = 0; j < 4; j++) {
            int p  = (n << 3) + (tg << 1) + (j & 1);
            int wr = w0 + gy + ((j >> 1) << 3);
            sD[wr * PD_STRIDE + p] = acc[(n << 2) + j];
        }
    }
    __syncthreads();

    if (tid < WW) {
        float prm[NP];
#pragma unroll
        for (int p = 0; p < NP; p++)
            prm[p] = sD[tid * PD_STRIDE + p] + __ldg(pgb + p);
        const int base = b * KK * HW + h * WW + tid;
#pragma unroll
        for (int k = 0; k < KK; k++) {
            int ki = k / 3, kj = k % 3;
            int4 co; float4 cq;
            make_corner((float)(h - 1 + ki) + prm[2 * k],
                        (float)(tid - 1 + kj) + prm[2 * k + 1],
                        1.f / (1.f + expf(-prm[18 + k])), co, cq);
            g_co[base + k * HW] = co;
            g_cq[base + k * HW] = cq;
        }
    }
}

// ---------------------------------------------------------------------------
// Kernel 2: DCN main, fp16 mma.sync m16n8k16 + ldmatrix.x4.
// S tile [w=128][c=64] fp16 (stride 72 halves), W tile [o=64][c=64] fp16.
// Double-buffered, one __syncthreads per tap.  Per K=16 chunk per warp:
// 1 ldmatrix.x4 (A) + 4 ldmatrix.x4 (B, 2 n-tiles each) + 8 MMAs.
// ---------------------------------------------------------------------------
__global__ void __launch_bounds__(256) dcn_kernel(
    const float* __restrict__ bias,
    float* __restrict__ out)
{
    extern __shared__ __align__(16) __half smh[];   // 2 * BUF_H halves

    const int tid  = threadIdx.x;
    const int lane = tid & 31;
    const int wid  = tid >> 5;
    const int b    = blockIdx.x >> 7;
    const int h    = blockIdx.x & 127;

    const int cg = lane & 7;         // c-group: channels cg*8 .. cg*8+7
    const int px = lane >> 3;        // pixel 0..3 within round
    const __half* xh = g_xh + ((size_t)b << 20);
    const int prow = b * KK * HW + h * WW;

    const int w0 = wid << 4;
    const int gy = lane >> 2;
    const int tg = lane & 3;

    // ldmatrix source lane mappings (constant per thread)
    const int a_row = w0 + (lane & 15);
    const int a_c8  = (lane >> 4) << 3;              // 0 or 8
    const int b_row = (lane & 7) + ((lane >> 4) << 3);  // 0..15 within o-pair
    const int b_c8  = ((lane >> 3) & 1) << 3;        // 0 or 8

    float acc[32];
#pragma unroll
    for (int i = 0; i < 32; i++) acc[i] = 0.f;

    for (int k = 0; k < KK; k++) {
        __half* sS = smh + (k & 1) * BUF_H;
        __half* sW = sS + WW * SH_STRIDE;

        // ---- stage W_k: [o][c] fp16, 8KB linear copy ----
        {
            const uint4* src = (const uint4*)(g_wt + ((size_t)k << 12));
#pragma unroll
            for (int i = 0; i < 2; i++) {
                int idx = tid + (i << 8);            // 512 uint4 (8 halves each)
                uint4 v = __ldg(src + idx);
                int o  = idx >> 3;
                int c8 = (idx & 7) << 3;
                *(uint4*)(sW + o * SH_STRIDE + c8) = v;
            }
        }
        // ---- stage S_k: fp16 NHWC gather (LDG.128 = 8ch), fp32 blend ----
        {
            const int pk = prow + k * HW;
#pragma unroll
            for (int r = 0; r < 4; r++) {
                int w = w0 + (r << 2) + px;
                int4   co = __ldg(&g_co[pk + w]);
                float4 cq = __ldg(&g_cq[pk + w]);
                uint4 u0 = __ldg((const uint4*)(xh + ((size_t)co.x << 6)) + cg);
                uint4 u1 = __ldg((const uint4*)(xh + ((size_t)co.y << 6)) + cg);
                uint4 u2 = __ldg((const uint4*)(xh + ((size_t)co.z << 6)) + cg);
                uint4 u3 = __ldg((const uint4*)(xh + ((size_t)co.w << 6)) + cg);
                const __half2* p0 = (const __half2*)&u0;
                const __half2* p1 = (const __half2*)&u1;
                const __half2* p2 = (const __half2*)&u2;
                const __half2* p3 = (const __half2*)&u3;
                uint32_t res[4];
#pragma unroll
                for (int j = 0; j < 4; j++) {
                    float2 f0 = __half22float2(p0[j]);
                    float2 f1 = __half22float2(p1[j]);
                    float2 f2 = __half22float2(p2[j]);
                    float2 f3 = __half22float2(p3[j]);
                    float2 s;
                    s.x = cq.x * f0.x + cq.y * f1.x + cq.z * f2.x + cq.w * f3.x;
                    s.y = cq.x * f0.y + cq.y * f1.y + cq.z * f2.y + cq.w * f3.y;
                    __half2 hh = __float22half2_rn(s);
                    res[j] = *(uint32_t*)&hh;
                }
                *(uint4*)(sS + w * SH_STRIDE + (cg << 3)) =
                    make_uint4(res[0], res[1], res[2], res[3]);
            }
        }
        __syncthreads();

        // ---- MMA: 4 K-chunks of 16 ----
        const uint32_t sS_base = smem_u32(sS);
        const uint32_t sW_base = smem_u32(sW);
#pragma unroll
        for (int kc = 0; kc < 4; kc++) {
            int c0 = kc << 4;
            uint32_t a0, a1, a2, a3;
            LDMATRIX_X4(a0, a1, a2, a3,
                        sS_base + (a_row * SH_STRIDE + c0 + a_c8) * 2);
#pragma unroll
            for (int nn = 0; nn < 4; nn++) {
                int o0 = nn << 4;
                uint32_t b0, b1, b2, b3;
                LDMATRIX_X4(b0, b1, b2, b3,
                            sW_base + ((o0 + b_row) * SH_STRIDE + c0 + b_c8) * 2);
                MMA_F16(acc + (nn << 3),      a0, a1, a2, a3, b0, b1);
                MMA_F16(acc + (nn << 3) + 4,  a0, a1, a2, a3, b2, b3);
            }
        }
    }

    // ---- epilogue ----
#pragma unroll
    for (int n = 0; n < 8; n++) {
#pragma unroll
        for (int j = 0; j < 4; j++) {
            int o  = (n << 3) + (tg << 1) + (j & 1);
            int wr = w0 + gy + ((j >> 1) << 3);
            out[(((size_t)b * COUT + o) * HH + h) * WW + wr] =
                acc[(n << 2) + j] + __ldg(bias + o);
        }
    }
}

// ---------------------------------------------------------------------------
extern "C" void kernel_launch(void* const* d_in, const int* in_sizes, int n_in,
                              void* d_out, int out_size)
{
    const float* x    = (const float*)d_in[0];
    const float* wgt  = (const float*)d_in[1];
    const float* bias = (const float*)d_in[2];
    const float* pgw  = (const float*)d_in[3];
    const float* pgb  = (const float*)d_in[4];
    float* out = (float*)d_out;

    const int smem1 = (3 * X_TILE + CIN * PW_STRIDE) * (int)sizeof(uint32_t)
                    + WW * PD_STRIDE * (int)sizeof(float);
    cudaFuncSetAttribute(param_mma_kernel,
                         cudaFuncAttributeMaxDynamicSharedMemorySize, smem1);

    const int smem2 = 2 * BUF_H * (int)sizeof(__half);   // 55296 B
    cudaFuncSetAttribute(dcn_kernel,
                         cudaFuncAttributeMaxDynamicSharedMemorySize, smem2);

    const int nprep = KK * COUT * CIN + KK * CIN * 32;
    wprep_kernel<<<(nprep + 255) / 256, 256>>>(wgt, pgw);
    transpose_kernel<<<BB * HH, 256>>>(x);
    param_mma_kernel<<<BB * HH, 256, smem1>>>(x, pgb);
    dcn_kernel<<<BB * HH, 256, smem2>>>(bias, out);
}

// round 9
// speedup vs baseline: 5.5135x; 1.4358x over previous
#include <cuda_runtime.h>
#include <cuda_fp16.h>
#include <math.h>
#include <stdint.h>

#define BB   8
#define CIN  64
#define COUT 64
#define HH   128
#define WW   128
#define KK   9
#define NP   27
#define HW   (HH * WW)

// fp16 tiles: rows padded to 72 halves (144 B) -> ldmatrix conflict-free
#define SH_STRIDE 72
#define BUF_H     (WW * SH_STRIDE + COUT * SH_STRIDE)   // dcn buffer slot (halves)

#define PX_TILE   (130 * SH_STRIDE)    // param X tile per image row (halves)
#define PW_H      (32 * SH_STRIDE)     // param W tile (halves)
#define PD_STRIDE 36                   // param D staging stride (floats)

// ---------------------------------------------------------------------------
// Scratch (device globals: no allocation allowed)
// ---------------------------------------------------------------------------
__device__ int4     g_co[BB * KK * HW];      // bilinear corner offsets
__device__ float4   g_cq[BB * KK * HW];      // corner weights (mask folded)
__device__ __half   g_wt[KK * COUT * CIN];   // main weights [k][o][c], fp16
__device__ __half   g_pwh[KK * 32 * CIN];    // param weights [t][p32][c], fp16
__device__ __half   g_xh[BB * HW * CIN];     // x as fp16 NHWC: [b][y][x][c]

// ---------------------------------------------------------------------------
__device__ __forceinline__ uint32_t smem_u32(const void* p) {
    uint32_t a;
    asm("{ .reg .u64 t; cvta.to.shared.u64 t, %1; cvt.u32.u64 %0, t; }" : "=r"(a) : "l"(p));
    return a;
}

__device__ __forceinline__ void make_corner(float sy, float sx, float mk,
                                            int4& co, float4& cq) {
    float y0f = floorf(sy), x0f = floorf(sx);
    int   iy0 = (int)y0f,   ix0 = (int)x0f;
    float fy = sy - y0f,    fx = sx - x0f;
    float w00 = (1.f - fy) * (1.f - fx);
    float w01 = (1.f - fy) * fx;
    float w10 = fy * (1.f - fx);
    float w11 = fy * fx;
    bool oky0 = (iy0 >= 0) && (iy0 < HH);
    bool oky1 = (iy0 + 1 >= 0) && (iy0 + 1 < HH);
    bool okx0 = (ix0 >= 0) && (ix0 < WW);
    bool okx1 = (ix0 + 1 >= 0) && (ix0 + 1 < WW);
    int cy0 = min(max(iy0, 0), HH - 1);
    int cy1 = min(max(iy0 + 1, 0), HH - 1);
    int cx0 = min(max(ix0, 0), WW - 1);
    int cx1 = min(max(ix0 + 1, 0), WW - 1);
    co = make_int4(cy0 * WW + cx0, cy0 * WW + cx1, cy1 * WW + cx0, cy1 * WW + cx1);
    cq = make_float4((oky0 && okx0) ? w00 * mk : 0.f,
                     (oky0 && okx1) ? w01 * mk : 0.f,
                     (oky1 && okx0) ? w10 * mk : 0.f,
                     (oky1 && okx1) ? w11 * mk : 0.f);
}

#define MMA_F16(d, a0, a1, a2, a3, b0, b1)                                    \
    asm volatile(                                                             \
        "mma.sync.aligned.m16n8k16.row.col.f32.f16.f16.f32 "                  \
        "{%0,%1,%2,%3}, {%4,%5,%6,%7}, {%8,%9}, {%0,%1,%2,%3};"               \
        : "+f"((d)[0]), "+f"((d)[1]), "+f"((d)[2]), "+f"((d)[3])              \
        : "r"(a0), "r"(a1), "r"(a2), "r"(a3), "r"(b0), "r"(b1))

#define LDMATRIX_X4(r0, r1, r2, r3, addr)                                     \
    asm volatile("ldmatrix.sync.aligned.m8n8.x4.shared.b16 {%0,%1,%2,%3}, [%4];" \
                 : "=r"(r0), "=r"(r1), "=r"(r2), "=r"(r3) : "r"(addr))

// ---------------------------------------------------------------------------
// Kernel 0a: weight prep (fp16)
//   g_wt[k][o][c]   from wgt[o][c][k]
//   g_pwh[t][p][c]  from pgw[p][c][t] (p>=27 zero)
// ---------------------------------------------------------------------------
__global__ void wprep_kernel(const float* __restrict__ wgt,
                             const float* __restrict__ pgw) {
    int idx = blockIdx.x * blockDim.x + threadIdx.x;
    if (idx < KK * COUT * CIN) {
        int k = idx >> 12;
        int r = idx & 4095;
        int o = r >> 6;
        int c = r & 63;
        g_wt[idx] = __float2half(wgt[o * (CIN * KK) + c * KK + k]);
    } else if (idx < KK * COUT * CIN + KK * 32 * CIN) {
        int j = idx - KK * COUT * CIN;
        int t = j >> 11;
        int r = j & 2047;
        int p = r >> 6;
        int c = r & 63;
        g_pwh[j] = (p < NP) ? __float2half(pgw[p * (CIN * KK) + c * KK + t])
                            : __float2half(0.f);
    }
}

// ---------------------------------------------------------------------------
// Kernel 0b: transpose x NCHW -> fp16 NHWC
// ---------------------------------------------------------------------------
__global__ void __launch_bounds__(256) transpose_kernel(const float* __restrict__ x) {
    const int b = blockIdx.x >> 7;
    const int y = blockIdx.x & 127;
    const int tid = threadIdx.x;
    const float* src = x + (size_t)b * CIN * HW + y * WW;
    __half*      dst = g_xh + ((size_t)b * HH + y) * WW * CIN;
#pragma unroll
    for (int i = 0; i < 8; i++) {
        int idx = tid + (i << 8);
        int c0  = (idx >> 7) << 2;
        int w   = idx & 127;
        float2 v0, v1;
        v0.x = __ldg(src + (size_t)(c0 + 0) * HW + w);
        v0.y = __ldg(src + (size_t)(c0 + 1) * HW + w);
        v1.x = __ldg(src + (size_t)(c0 + 2) * HW + w);
        v1.y = __ldg(src + (size_t)(c0 + 3) * HW + w);
        __half2 h0 = __float22half2_rn(v0);
        __half2 h1 = __float22half2_rn(v1);
        uint2 pk;
        pk.x = *(uint32_t*)&h0;
        pk.y = *(uint32_t*)&h1;
        *(uint2*)(dst + w * CIN + c0) = pk;
    }
}

// ---------------------------------------------------------------------------
// Kernel 1: param conv via fp16 mma.sync m16n8k16 + ldmatrix.
// D[w=128][p=32] = sum_t X[rows h-1..h+1, pos w+tj][c] * Wp_t[p][c].
// X staged once (fp16 NHWC, coalesced LDG.128; pos 0/129 zero = conv pad);
// W double-buffered, one sync per tap; tap tj is an A-address shift.
// ---------------------------------------------------------------------------
__global__ void __launch_bounds__(256) param_mma_kernel(
    const float* __restrict__ pgb)
{
    extern __shared__ __align__(16) __half psm[];
    __half* sX = psm;                          // [3][130][SH_STRIDE]
    __half* sW = psm + 3 * PX_TILE;            // [2][32][SH_STRIDE]
    float*  sD = (float*)(sW + 2 * PW_H);      // [128][PD_STRIDE]

    const int tid  = threadIdx.x;
    const int lane = tid & 31;
    const int wid  = tid >> 5;
    const int b    = blockIdx.x >> 7;
    const int h    = blockIdx.x & 127;

    const int w0 = wid << 4;
    const int gy = lane >> 2;
    const int tg = lane & 3;

    // ldmatrix lane maps (same as dcn)
    const int a_row = w0 + (lane & 15);
    const int a_c8  = (lane >> 4) << 3;
    const int b_row = (lane & 7) + ((lane >> 4) << 3);
    const int b_c8  = ((lane >> 3) & 1) << 3;

    // ---- stage X rows h-1..h+1 (coalesced), zero pad pos 0/129 ----
#pragma unroll
    for (int i = 0; i < 12; i++) {
        int idx = tid + (i << 8);           // 3072 uint4
        int ti  = idx >> 10;
        int r   = idx & 1023;
        int w   = r >> 3;
        int cg  = r & 7;
        int row = h - 1 + ti;
        uint4 v = make_uint4(0, 0, 0, 0);
        if (row >= 0 && row < HH)
            v = __ldg((const uint4*)(g_xh + (((size_t)b * HH + row) * WW + w) * CIN) + cg);
        *(uint4*)(sX + (ti * 130 + w + 1) * SH_STRIDE + (cg << 3)) = v;
    }
    if (tid < 48) {
        int ti  = tid >> 4;
        int r   = tid & 15;
        int pos = (r >> 3) ? 129 : 0;
        int cg  = r & 7;
        *(uint4*)(sX + (ti * 130 + pos) * SH_STRIDE + (cg << 3)) = make_uint4(0, 0, 0, 0);
    }

    float acc[16];
#pragma unroll
    for (int i = 0; i < 16; i++) acc[i] = 0.f;

    for (int t = 0; t < KK; t++) {
        __half* sWt = sW + (t & 1) * PW_H;
        // ---- stage Wp_t: [p32][c64] fp16, 256 uint4 ----
        {
            uint4 v = __ldg((const uint4*)(g_pwh + ((size_t)t << 11)) + tid);
            *(uint4*)(sWt + (tid >> 3) * SH_STRIDE + ((tid & 7) << 3)) = v;
        }
        __syncthreads();

        const int ti = t / 3, tj = t % 3;
        const uint32_t sX_base = smem_u32(sX) + (ti * 130 + tj) * SH_STRIDE * 2;
        const uint32_t sW_base = smem_u32(sWt);
#pragma unroll
        for (int kc = 0; kc < 4; kc++) {
            int c0 = kc << 4;
            uint32_t a0, a1, a2, a3;
            LDMATRIX_X4(a0, a1, a2, a3,
                        sX_base + (a_row * SH_STRIDE + c0 + a_c8) * 2);
#pragma unroll
            for (int nn = 0; nn < 2; nn++) {
                uint32_t b0, b1, b2, b3;
                LDMATRIX_X4(b0, b1, b2, b3,
                            sW_base + (((nn << 4) + b_row) * SH_STRIDE + c0 + b_c8) * 2);
                MMA_F16(acc + (nn << 3),     a0, a1, a2, a3, b0, b1);
                MMA_F16(acc + (nn << 3) + 4, a0, a1, a2, a3, b2, b3);
            }
        }
    }
    __syncthreads();

    // ---- D fragments -> sD[w][p]  (acc idx n*4 maps o-base n*8, as before) ----
#pragma unroll
    for (int n = 0; n < 4; n++) {
#pragma unroll
        for (int j = 0; j < 4; j++) {
            int p  = (n << 3) + (tg << 1) + (j & 1);
            int wr = w0 + gy + ((j >> 1) << 3);
            sD[wr * PD_STRIDE + p] = acc[(n << 2) + j];
        }
    }
    __syncthreads();

    // ---- corners: one thread per pixel ----
    if (tid < WW) {
        float prm[NP];
#pragma unroll
        for (int p = 0; p < NP; p++)
            prm[p] = sD[tid * PD_STRIDE + p] + __ldg(pgb + p);
        const int base = b * KK * HW + h * WW + tid;
#pragma unroll
        for (int k = 0; k < KK; k++) {
            int ki = k / 3, kj = k % 3;
            int4 co; float4 cq;
            make_corner((float)(h - 1 + ki) + prm[2 * k],
                        (float)(tid - 1 + kj) + prm[2 * k + 1],
                        1.f / (1.f + expf(-prm[18 + k])), co, cq);
            g_co[base + k * HW] = co;
            g_cq[base + k * HW] = cq;
        }
    }
}

// ---------------------------------------------------------------------------
// Kernel 2: DCN main, fp16 mma + ldmatrix, double-buffered, 1 sync/tap.
// launch_bounds(256,4): cap regs at 64 -> 4 resident blocks (occupancy).
// ---------------------------------------------------------------------------
__global__ void __launch_bounds__(256, 4) dcn_kernel(
    const float* __restrict__ bias,
    float* __restrict__ out)
{
    extern __shared__ __align__(16) __half smh[];   // 2 * BUF_H halves

    const int tid  = threadIdx.x;
    const int lane = tid & 31;
    const int wid  = tid >> 5;
    const int b    = blockIdx.x >> 7;
    const int h    = blockIdx.x & 127;

    const int cg = lane & 7;
    const int px = lane >> 3;
    const __half* xh = g_xh + ((size_t)b << 20);
    const int prow = b * KK * HW + h * WW;

    const int w0 = wid << 4;
    const int gy = lane >> 2;
    const int tg = lane & 3;

    const int a_row = w0 + (lane & 15);
    const int a_c8  = (lane >> 4) << 3;
    const int b_row = (lane & 7) + ((lane >> 4) << 3);
    const int b_c8  = ((lane >> 3) & 1) << 3;

    float acc[32];
#pragma unroll
    for (int i = 0; i < 32; i++) acc[i] = 0.f;

    for (int k = 0; k < KK; k++) {
        __half* sS = smh + (k & 1) * BUF_H;
        __half* sW = sS + WW * SH_STRIDE;

        // ---- stage W_k: [o][c] fp16, 8KB linear copy ----
        {
            const uint4* src = (const uint4*)(g_wt + ((size_t)k << 12));
#pragma unroll
            for (int i = 0; i < 2; i++) {
                int idx = tid + (i << 8);
                uint4 v = __ldg(src + idx);
                int o  = idx >> 3;
                int c8 = (idx & 7) << 3;
                *(uint4*)(sW + o * SH_STRIDE + c8) = v;
            }
        }
        // ---- stage S_k: fp16 NHWC gather (LDG.128 = 8ch), fp32 blend ----
        {
            const int pk = prow + k * HW;
#pragma unroll
            for (int r = 0; r < 4; r++) {
                int w = w0 + (r << 2) + px;
                int4   co = __ldg(&g_co[pk + w]);
                float4 cq = __ldg(&g_cq[pk + w]);
                uint4 u0 = __ldg((const uint4*)(xh + ((size_t)co.x << 6)) + cg);
                uint4 u1 = __ldg((const uint4*)(xh + ((size_t)co.y << 6)) + cg);
                uint4 u2 = __ldg((const uint4*)(xh + ((size_t)co.z << 6)) + cg);
                uint4 u3 = __ldg((const uint4*)(xh + ((size_t)co.w << 6)) + cg);
                const __half2* p0 = (const __half2*)&u0;
                const __half2* p1 = (const __half2*)&u1;
                const __half2* p2 = (const __half2*)&u2;
                const __half2* p3 = (const __half2*)&u3;
                uint32_t res[4];
#pragma unroll
                for (int j = 0; j < 4; j++) {
                    float2 f0 = __half22float2(p0[j]);
                    float2 f1 = __half22float2(p1[j]);
                    float2 f2 = __half22float2(p2[j]);
                    float2 f3 = __half22float2(p3[j]);
                    float2 s;
                    s.x = cq.x * f0.x + cq.y * f1.x + cq.z * f2.x + cq.w * f3.x;
                    s.y = cq.x * f0.y + cq.y * f1.y + cq.z * f2.y + cq.w * f3.y;
                    __half2 hh = __float22half2_rn(s);
                    res[j] = *(uint32_t*)&hh;
                }
                *(uint4*)(sS + w * SH_STRIDE + (cg << 3)) =
                    make_uint4(res[0], res[1], res[2], res[3]);
            }
        }
        __syncthreads();

        // ---- MMA: 4 K-chunks of 16 ----
        const uint32_t sS_base = smem_u32(sS);
        const uint32_t sW_base = smem_u32(sW);
#pragma unroll
        for (int kc = 0; kc < 4; kc++) {
            int c0 = kc << 4;
            uint32_t a0, a1, a2, a3;
            LDMATRIX_X4(a0, a1, a2, a3,
                        sS_base + (a_row * SH_STRIDE + c0 + a_c8) * 2);
#pragma unroll
            for (int nn = 0; nn < 4; nn++) {
                int o0 = nn << 4;
                uint32_t b0, b1, b2, b3;
                LDMATRIX_X4(b0, b1, b2, b3,
                            sW_base + ((o0 + b_row) * SH_STRIDE + c0 + b_c8) * 2);
                MMA_F16(acc + (nn << 3),      a0, a1, a2, a3, b0, b1);
                MMA_F16(acc + (nn << 3) + 4,  a0, a1, a2, a3, b2, b3);
            }
        }
    }

    // ---- epilogue ----
#pragma unroll
    for (int n = 0; n < 8; n++) {
#pragma unroll
        for (int j = 0; j < 4; j++) {
            int o  = (n << 3) + (tg << 1) + (j & 1);
            int wr = w0 + gy + ((j >> 1) << 3);
            out[(((size_t)b * COUT + o) * HH + h) * WW + wr] =
                acc[(n << 2) + j] + __ldg(bias + o);
        }
    }
}

// ---------------------------------------------------------------------------
extern "C" void kernel_launch(void* const* d_in, const int* in_sizes, int n_in,
                              void* d_out, int out_size)
{
    const float* x    = (const float*)d_in[0];
    const float* wgt  = (const float*)d_in[1];
    const float* bias = (const float*)d_in[2];
    const float* pgw  = (const float*)d_in[3];
    const float* pgb  = (const float*)d_in[4];
    float* out = (float*)d_out;

    const int smem1 = (3 * PX_TILE + 2 * PW_H) * (int)sizeof(__half)
                    + WW * PD_STRIDE * (int)sizeof(float);   // 83808 B
    cudaFuncSetAttribute(param_mma_kernel,
                         cudaFuncAttributeMaxDynamicSharedMemorySize, smem1);

    const int smem2 = 2 * BUF_H * (int)sizeof(__half);       // 55296 B
    cudaFuncSetAttribute(dcn_kernel,
                         cudaFuncAttributeMaxDynamicSharedMemorySize, smem2);

    const int nprep = KK * COUT * CIN + KK * 32 * CIN;
    wprep_kernel<<<(nprep + 255) / 256, 256>>>(wgt, pgw);
    transpose_kernel<<<BB * HH, 256>>>(x);
    param_mma_kernel<<<BB * HH, 256, smem1>>>(pgb);
    dcn_kernel<<<BB * HH, 256, smem2>>>(bias, out);
}

// round 11
// speedup vs baseline: 5.9359x; 1.0766x over previous
#include <cuda_runtime.h>
#include <cuda_fp16.h>
#include <math.h>
#include <stdint.h>

#define BB   8
#define CIN  64
#define COUT 64
#define HH   128
#define WW   128
#define KK   9
#define NP   27
#define HW   (HH * WW)

// fp16 tiles: rows padded to 72 halves (144 B) -> ldmatrix conflict-free
#define SH_STRIDE 72
#define BUF_H     (WW * SH_STRIDE + COUT * SH_STRIDE)   // dcn buffer slot (halves)

#define PX_TILE   (130 * SH_STRIDE)    // param X tile per image row (halves)
#define PW_H      (32 * SH_STRIDE)     // param W tile (halves)
#define PD_STRIDE 36                   // param D staging stride (floats)

#define T_STRIDE  66                   // transpose smem tile stride (halves)

// ---------------------------------------------------------------------------
// Scratch (device globals: no allocation allowed)
// ---------------------------------------------------------------------------
__device__ int4     g_co[BB * KK * HW];      // bilinear corner offsets
__device__ float4   g_cq[BB * KK * HW];      // corner weights (mask folded)
__device__ __half   g_wt[KK * COUT * CIN];   // main weights [k][o][c], fp16
__device__ __half   g_pwh[KK * 32 * CIN];    // param weights [t][p32][c], fp16
__device__ __half   g_xh[BB * HW * CIN];     // x as fp16 NHWC: [b][y][x][c]

// ---------------------------------------------------------------------------
__device__ __forceinline__ uint32_t smem_u32(const void* p) {
    uint32_t a;
    asm("{ .reg .u64 t; cvta.to.shared.u64 t, %1; cvt.u32.u64 %0, t; }" : "=r"(a) : "l"(p));
    return a;
}

__device__ __forceinline__ void make_corner(float sy, float sx, float mk,
                                            int4& co, float4& cq) {
    float y0f = floorf(sy), x0f = floorf(sx);
    int   iy0 = (int)y0f,   ix0 = (int)x0f;
    float fy = sy - y0f,    fx = sx - x0f;
    float w00 = (1.f - fy) * (1.f - fx);
    float w01 = (1.f - fy) * fx;
    float w10 = fy * (1.f - fx);
    float w11 = fy * fx;
    bool oky0 = (iy0 >= 0) && (iy0 < HH);
    bool oky1 = (iy0 + 1 >= 0) && (iy0 + 1 < HH);
    bool okx0 = (ix0 >= 0) && (ix0 < WW);
    bool okx1 = (ix0 + 1 >= 0) && (ix0 + 1 < WW);
    int cy0 = min(max(iy0, 0), HH - 1);
    int cy1 = min(max(iy0 + 1, 0), HH - 1);
    int cx0 = min(max(ix0, 0), WW - 1);
    int cx1 = min(max(ix0 + 1, 0), WW - 1);
    co = make_int4(cy0 * WW + cx0, cy0 * WW + cx1, cy1 * WW + cx0, cy1 * WW + cx1);
    cq = make_float4((oky0 && okx0) ? w00 * mk : 0.f,
                     (oky0 && okx1) ? w01 * mk : 0.f,
                     (oky1 && okx0) ? w10 * mk : 0.f,
                     (oky1 && okx1) ? w11 * mk : 0.f);
}

#define MMA_F16(d, a0, a1, a2, a3, b0, b1)                                    \
    asm volatile(                                                             \
        "mma.sync.aligned.m16n8k16.row.col.f32.f16.f16.f32 "                  \
        "{%0,%1,%2,%3}, {%4,%5,%6,%7}, {%8,%9}, {%0,%1,%2,%3};"               \
        : "+f"((d)[0]), "+f"((d)[1]), "+f"((d)[2]), "+f"((d)[3])              \
        : "r"(a0), "r"(a1), "r"(a2), "r"(a3), "r"(b0), "r"(b1))

#define LDMATRIX_X4(r0, r1, r2, r3, addr)                                     \
    asm volatile("ldmatrix.sync.aligned.m8n8.x4.shared.b16 {%0,%1,%2,%3}, [%4];" \
                 : "=r"(r0), "=r"(r1), "=r"(r2), "=r"(r3) : "r"(addr))

// ---------------------------------------------------------------------------
// Kernel 0: fused prep.
//   blocks [0, BB*HH): transpose x NCHW -> fp16 NHWC via smem tile
//   blocks [BB*HH, +216): weight fp16 conversion/relayout
// ---------------------------------------------------------------------------
#define NPREP (KK * COUT * CIN + KK * 32 * CIN)   // 55296

__global__ void __launch_bounds__(256) prep_kernel(
    const float* __restrict__ x,
    const float* __restrict__ wgt,
    const float* __restrict__ pgw)
{
    const int tid = threadIdx.x;
    if (blockIdx.x < BB * HH) {
        extern __shared__ __align__(16) __half sT[];   // [128][T_STRIDE]
        const int b = blockIdx.x >> 7;
        const int y = blockIdx.x & 127;
        const float* src = x + (size_t)b * CIN * HW + y * WW;
        __half*      dst = g_xh + ((size_t)b * HH + y) * WW * CIN;
        // phase 1: coalesced reads, conflict-free STS.32 (half2):
        // bank = (33w + c0/2) mod 32 = (w + c0/2) mod 32, w spans 32 -> distinct
#pragma unroll
        for (int i = 0; i < 16; i++) {
            int idx = tid + (i << 8);       // 4096 (c-pair, w)
            int w   = idx & 127;
            int c0  = (idx >> 7) << 1;
            float2 v;
            v.x = __ldg(src + (size_t)c0 * HW + w);
            v.y = __ldg(src + ((size_t)c0 + 1) * HW + w);
            __half2 hh = __float22half2_rn(v);
            *(__half2*)(sT + w * T_STRIDE + c0) = hh;
        }
        __syncthreads();
        // phase 2: 4x aligned LDS.32 (132w+16cg+4j == 0 mod 4 always; a
        // uint4 LDS would be misaligned for odd w), assemble, STG.128.
        // Banks: word 33w+4cg+j -> (w+4cg+j) mod 32, warp spans w0..w0+3 x cg0..7 -> distinct.
#pragma unroll
        for (int i = 0; i < 4; i++) {
            int idx = tid + (i << 8);       // 1024 (w, cg)
            int w   = idx >> 3;
            int cg  = idx & 7;
            const uint32_t* pr = (const uint32_t*)(sT + w * T_STRIDE + (cg << 3));
            uint4 v;
            v.x = pr[0]; v.y = pr[1]; v.z = pr[2]; v.w = pr[3];
            *(uint4*)(dst + w * CIN + (cg << 3)) = v;
        }
    } else {
        int idx = (blockIdx.x - BB * HH) * 256 + tid;
        if (idx < KK * COUT * CIN) {
            int k = idx >> 12;
            int r = idx & 4095;
            int o = r >> 6;
            int c = r & 63;
            g_wt[idx] = __float2half(wgt[o * (CIN * KK) + c * KK + k]);
        } else if (idx < NPREP) {
            int j = idx - KK * COUT * CIN;
            int t = j >> 11;
            int r = j & 2047;
            int p = r >> 6;
            int c = r & 63;
            g_pwh[j] = (p < NP) ? __float2half(pgw[p * (CIN * KK) + c * KK + t])
                                : __float2half(0.f);
        }
    }
}

// ---------------------------------------------------------------------------
// Kernel 1: param conv via fp16 mma.sync m16n8k16 + ldmatrix (unchanged R9)
// ---------------------------------------------------------------------------
__global__ void __launch_bounds__(256) param_mma_kernel(
    const float* __restrict__ pgb)
{
    extern __shared__ __align__(16) __half psm[];
    __half* sX = psm;                          // [3][130][SH_STRIDE]
    __half* sW = psm + 3 * PX_TILE;            // [2][32][SH_STRIDE]
    float*  sD = (float*)(sW + 2 * PW_H);      // [128][PD_STRIDE]

    const int tid  = threadIdx.x;
    const int lane = tid & 31;
    const int wid  = tid >> 5;
    const int b    = blockIdx.x >> 7;
    const int h    = blockIdx.x & 127;

    const int w0 = wid << 4;
    const int gy = lane >> 2;
    const int tg = lane & 3;

    const int a_row = w0 + (lane & 15);
    const int a_c8  = (lane >> 4) << 3;
    const int b_row = (lane & 7) + ((lane >> 4) << 3);
    const int b_c8  = ((lane >> 3) & 1) << 3;

#pragma unroll
    for (int i = 0; i < 12; i++) {
        int idx = tid + (i << 8);
        int ti  = idx >> 10;
        int r   = idx & 1023;
        int w   = r >> 3;
        int cg  = r & 7;
        int row = h - 1 + ti;
        uint4 v = make_uint4(0, 0, 0, 0);
        if (row >= 0 && row < HH)
            v = __ldg((const uint4*)(g_xh + (((size_t)b * HH + row) * WW + w) * CIN) + cg);
        *(uint4*)(sX + (ti * 130 + w + 1) * SH_STRIDE + (cg << 3)) = v;
    }
    if (tid < 48) {
        int ti  = tid >> 4;
        int r   = tid & 15;
        int pos = (r >> 3) ? 129 : 0;
        int cg  = r & 7;
        *(uint4*)(sX + (ti * 130 + pos) * SH_STRIDE + (cg << 3)) = make_uint4(0, 0, 0, 0);
    }

    float acc[16];
#pragma unroll
    for (int i = 0; i < 16; i++) acc[i] = 0.f;

    for (int t = 0; t < KK; t++) {
        __half* sWt = sW + (t & 1) * PW_H;
        {
            uint4 v = __ldg((const uint4*)(g_pwh + ((size_t)t << 11)) + tid);
            *(uint4*)(sWt + (tid >> 3) * SH_STRIDE + ((tid & 7) << 3)) = v;
        }
        __syncthreads();

        const int ti = t / 3, tj = t % 3;
        const uint32_t sX_base = smem_u32(sX) + (ti * 130 + tj) * SH_STRIDE * 2;
        const uint32_t sW_base = smem_u32(sWt);
#pragma unroll
        for (int kc = 0; kc < 4; kc++) {
            int c0 = kc << 4;
            uint32_t a0, a1, a2, a3;
            LDMATRIX_X4(a0, a1, a2, a3,
                        sX_base + (a_row * SH_STRIDE + c0 + a_c8) * 2);
#pragma unroll
            for (int nn = 0; nn < 2; nn++) {
                uint32_t b0, b1, b2, b3;
                LDMATRIX_X4(b0, b1, b2, b3,
                            sW_base + (((nn << 4) + b_row) * SH_STRIDE + c0 + b_c8) * 2);
                MMA_F16(acc + (nn << 3),     a0, a1, a2, a3, b0, b1);
                MMA_F16(acc + (nn << 3) + 4, a0, a1, a2, a3, b2, b3);
            }
        }
    }
    __syncthreads();

#pragma unroll
    for (int n = 0; n < 4; n++) {
#pragma unroll
        for (int j = 0; j < 4; j++) {
            int p  = (n << 3) + (tg << 1) + (j & 1);
            int wr = w0 + gy + ((j >> 1) << 3);
            sD[wr * PD_STRIDE + p] = acc[(n << 2) + j];
        }
    }
    __syncthreads();

    if (tid < WW) {
        float prm[NP];
#pragma unroll
        for (int p = 0; p < NP; p++)
            prm[p] = sD[tid * PD_STRIDE + p] + __ldg(pgb + p);
        const int base = b * KK * HW + h * WW + tid;
#pragma unroll
        for (int k = 0; k < KK; k++) {
            int ki = k / 3, kj = k % 3;
            int4 co; float4 cq;
            make_corner((float)(h - 1 + ki) + prm[2 * k],
                        (float)(tid - 1 + kj) + prm[2 * k + 1],
                        1.f / (1.f + expf(-prm[18 + k])), co, cq);
            g_co[base + k * HW] = co;
            g_cq[base + k * HW] = cq;
        }
    }
}

// ---------------------------------------------------------------------------
// Kernel 2: DCN main, fp16 mma + ldmatrix, double-buffered, 1 sync/tap.
// MMA warp tile 32w x 32o (mg = wid&3, ng = wid>>2): per kc 2 A-x4 + 2 B-x4
// feed 8 MMAs (vs 1+4 for 16x64) -> 20% fewer fragment loads.
// ---------------------------------------------------------------------------
__global__ void __launch_bounds__(256, 4) dcn_kernel(
    const float* __restrict__ bias,
    float* __restrict__ out)
{
    extern __shared__ __align__(16) __half smh[];   // 2 * BUF_H halves

    const int tid  = threadIdx.x;
    const int lane = tid & 31;
    const int wid  = tid >> 5;
    const int b    = blockIdx.x >> 7;
    const int h    = blockIdx.x & 127;

    // sampling map (unchanged): warp samples pixels ws0..ws0+15
    const int cg = lane & 7;
    const int px = lane >> 3;
    const int ws0 = wid << 4;
    const __half* xh = g_xh + ((size_t)b << 20);
    const int prow = b * KK * HW + h * WW;

    // MMA warp tile: rows [mg*32, mg*32+32), cols o [ng*32, ng*32+32)
    const int mg = wid & 3;
    const int ng = wid >> 2;
    const int gy = lane >> 2;
    const int tg = lane & 3;
    const int a_row0 = (mg << 5) + (lane & 15);
    const int a_c8   = (lane >> 4) << 3;
    const int b_row  = (lane & 7) + ((lane >> 4) << 3);
    const int b_c8   = ((lane >> 3) & 1) << 3;

    float acc[32];
#pragma unroll
    for (int i = 0; i < 32; i++) acc[i] = 0.f;

    for (int k = 0; k < KK; k++) {
        __half* sS = smh + (k & 1) * BUF_H;
        __half* sW = sS + WW * SH_STRIDE;

        // ---- stage W_k: [o][c] fp16, 8KB linear copy ----
        {
            const uint4* src = (const uint4*)(g_wt + ((size_t)k << 12));
#pragma unroll
            for (int i = 0; i < 2; i++) {
                int idx = tid + (i << 8);
                uint4 v = __ldg(src + idx);
                int o  = idx >> 3;
                int c8 = (idx & 7) << 3;
                *(uint4*)(sW + o * SH_STRIDE + c8) = v;
            }
        }
        // ---- stage S_k: fp16 NHWC gather (LDG.128 = 8ch), fp32 blend ----
        {
            const int pk = prow + k * HW;
#pragma unroll
            for (int r = 0; r < 4; r++) {
                int w = ws0 + (r << 2) + px;
                int4   co = __ldg(&g_co[pk + w]);
                float4 cq = __ldg(&g_cq[pk + w]);
                uint4 u0 = __ldg((const uint4*)(xh + ((size_t)co.x << 6)) + cg);
                uint4 u1 = __ldg((const uint4*)(xh + ((size_t)co.y << 6)) + cg);
                uint4 u2 = __ldg((const uint4*)(xh + ((size_t)co.z << 6)) + cg);
                uint4 u3 = __ldg((const uint4*)(xh + ((size_t)co.w << 6)) + cg);
                const __half2* p0 = (const __half2*)&u0;
                const __half2* p1 = (const __half2*)&u1;
                const __half2* p2 = (const __half2*)&u2;
                const __half2* p3 = (const __half2*)&u3;
                uint32_t res[4];
#pragma unroll
                for (int j = 0; j < 4; j++) {
                    float2 f0 = __half22float2(p0[j]);
                    float2 f1 = __half22float2(p1[j]);
                    float2 f2 = __half22float2(p2[j]);
                    float2 f3 = __half22float2(p3[j]);
                    float2 s;
                    s.x = cq.x * f0.x + cq.y * f1.x + cq.z * f2.x + cq.w * f3.x;
                    s.y = cq.x * f0.y + cq.y * f1.y + cq.z * f2.y + cq.w * f3.y;
                    __half2 hh = __float22half2_rn(s);
                    res[j] = *(uint32_t*)&hh;
                }
                *(uint4*)(sS + w * SH_STRIDE + (cg << 3)) =
                    make_uint4(res[0], res[1], res[2], res[3]);
            }
        }
        __syncthreads();

        // ---- MMA: 4 K-chunks of 16, 32w x 32o warp tile ----
        const uint32_t sS_base = smem_u32(sS);
        const uint32_t sW_base = smem_u32(sW);
#pragma unroll
        for (int kc = 0; kc < 4; kc++) {
            int c0 = kc << 4;
            uint32_t a0, a1, a2, a3, a4, a5, a6, a7;
            LDMATRIX_X4(a0, a1, a2, a3,
                        sS_base + (a_row0 * SH_STRIDE + c0 + a_c8) * 2);
            LDMATRIX_X4(a4, a5, a6, a7,
                        sS_base + ((a_row0 + 16) * SH_STRIDE + c0 + a_c8) * 2);
#pragma unroll
            for (int q = 0; q < 2; q++) {
                int o0 = (ng << 5) + (q << 4);
                uint32_t b0, b1, b2, b3;
                LDMATRIX_X4(b0, b1, b2, b3,
                            sW_base + ((o0 + b_row) * SH_STRIDE + c0 + b_c8) * 2);
                int nj = q << 1;
                MMA_F16(acc + (nj << 2),            a0, a1, a2, a3, b0, b1);
                MMA_F16(acc + ((nj + 1) << 2),      a0, a1, a2, a3, b2, b3);
                MMA_F16(acc + ((4 + nj) << 2),      a4, a5, a6, a7, b0, b1);
                MMA_F16(acc + ((4 + nj + 1) << 2),  a4, a5, a6, a7, b2, b3);
            }
        }
    }

    // ---- epilogue: acc[(mi*4+nj)*4+j] -> out[b][o][h][wr] ----
#pragma unroll
    for (int mi = 0; mi < 2; mi++) {
#pragma unroll
        for (int nj = 0; nj < 4; nj++) {
#pragma unroll
            for (int j = 0; j < 4; j++) {
                int o  = (ng << 5) + (nj << 3) + (tg << 1) + (j & 1);
                int wr = (mg << 5) + (mi << 4) + gy + ((j >> 1) << 3);
                out[(((size_t)b * COUT + o) * HH + h) * WW + wr] =
                    acc[((mi << 2) + nj) * 4 + j] + __ldg(bias + o);
            }
        }
    }
}

// ---------------------------------------------------------------------------
extern "C" void kernel_launch(void* const* d_in, const int* in_sizes, int n_in,
                              void* d_out, int out_size)
{
    const float* x    = (const float*)d_in[0];
    const float* wgt  = (const float*)d_in[1];
    const float* bias = (const float*)d_in[2];
    const float* pgw  = (const float*)d_in[3];
    const float* pgb  = (const float*)d_in[4];
    float* out = (float*)d_out;

    const int smem0 = WW * T_STRIDE * (int)sizeof(__half);   // 16896 B
    cudaFuncSetAttribute(prep_kernel,
                         cudaFuncAttributeMaxDynamicSharedMemorySize, smem0);

    const int smem1 = (3 * PX_TILE + 2 * PW_H) * (int)sizeof(__half)
                    + WW * PD_STRIDE * (int)sizeof(float);   // 83808 B
    cudaFuncSetAttribute(param_mma_kernel,
                         cudaFuncAttributeMaxDynamicSharedMemorySize, smem1);

    const int smem2 = 2 * BUF_H * (int)sizeof(__half);       // 55296 B
    cudaFuncSetAttribute(dcn_kernel,
                         cudaFuncAttributeMaxDynamicSharedMemorySize, smem2);

    const int nprep_blocks = (NPREP + 255) / 256;            // 216
    prep_kernel<<<BB * HH + nprep_blocks, 256, smem0>>>(x, wgt, pgw);
    param_mma_kernel<<<BB * HH, 256, smem1>>>(pgb);
    dcn_kernel<<<BB * HH, 256, smem2>>>(bias, out);
}

// round 12
// speedup vs baseline: 6.5592x; 1.1050x over previous
#include <cuda_runtime.h>
#include <cuda_fp16.h>
#include <math.h>
#include <stdint.h>

#define BB   8
#define CIN  64
#define COUT 64
#define HH   128
#define WW   128
#define KK   9
#define NP   27
#define HW   (HH * WW)

// fp16 tiles: rows padded to 72 halves (144 B) -> ldmatrix conflict-free
#define SH_STRIDE 72
#define BUF_H     (WW * SH_STRIDE)    // dcn S buffer slot (halves) — W no longer in smem

#define PX_TILE   (130 * SH_STRIDE)   // param X tile per image row (halves)
#define PD_STRIDE 36                  // param D staging stride (floats)

#define T_STRIDE  66                  // transpose smem tile stride (halves)

#define NBF 4608                      // dcn B-frag entries: 9k x 4(o/16) x 4kc x 32 lanes
#define NPF 2304                      // param B-frag entries: 9t x 2 x 4kc x 32

// ---------------------------------------------------------------------------
// Scratch (device globals: no allocation allowed)
// ---------------------------------------------------------------------------
__device__ int4     g_co[BB * KK * HW];   // bilinear corner offsets
__device__ float4   g_cq[BB * KK * HW];   // corner weights (mask folded)
__device__ uint4    g_bf[NBF];            // dcn  B fragments (mma register layout)
__device__ uint4    g_pf[NPF];            // param B fragments
__device__ __half   g_xh[BB * HW * CIN];  // x as fp16 NHWC: [b][y][x][c]

// ---------------------------------------------------------------------------
__device__ __forceinline__ uint32_t smem_u32(const void* p) {
    uint32_t a;
    asm("{ .reg .u64 t; cvta.to.shared.u64 t, %1; cvt.u32.u64 %0, t; }" : "=r"(a) : "l"(p));
    return a;
}

__device__ __forceinline__ void make_corner(float sy, float sx, float mk,
                                            int4& co, float4& cq) {
    float y0f = floorf(sy), x0f = floorf(sx);
    int   iy0 = (int)y0f,   ix0 = (int)x0f;
    float fy = sy - y0f,    fx = sx - x0f;
    float w00 = (1.f - fy) * (1.f - fx);
    float w01 = (1.f - fy) * fx;
    float w10 = fy * (1.f - fx);
    float w11 = fy * fx;
    bool oky0 = (iy0 >= 0) && (iy0 < HH);
    bool oky1 = (iy0 + 1 >= 0) && (iy0 + 1 < HH);
    bool okx0 = (ix0 >= 0) && (ix0 < WW);
    bool okx1 = (ix0 + 1 >= 0) && (ix0 + 1 < WW);
    int cy0 = min(max(iy0, 0), HH - 1);
    int cy1 = min(max(iy0 + 1, 0), HH - 1);
    int cx0 = min(max(ix0, 0), WW - 1);
    int cx1 = min(max(ix0 + 1, 0), WW - 1);
    co = make_int4(cy0 * WW + cx0, cy0 * WW + cx1, cy1 * WW + cx0, cy1 * WW + cx1);
    cq = make_float4((oky0 && okx0) ? w00 * mk : 0.f,
                     (oky0 && okx1) ? w01 * mk : 0.f,
                     (oky1 && okx0) ? w10 * mk : 0.f,
                     (oky1 && okx1) ? w11 * mk : 0.f);
}

#define MMA_F16(d, a0, a1, a2, a3, b0, b1)                                    \
    asm volatile(                                                             \
        "mma.sync.aligned.m16n8k16.row.col.f32.f16.f16.f32 "                  \
        "{%0,%1,%2,%3}, {%4,%5,%6,%7}, {%8,%9}, {%0,%1,%2,%3};"               \
        : "+f"((d)[0]), "+f"((d)[1]), "+f"((d)[2]), "+f"((d)[3])              \
        : "r"(a0), "r"(a1), "r"(a2), "r"(a3), "r"(b0), "r"(b1))

#define LDMATRIX_X4(r0, r1, r2, r3, addr)                                     \
    asm volatile("ldmatrix.sync.aligned.m8n8.x4.shared.b16 {%0,%1,%2,%3}, [%4];" \
                 : "=r"(r0), "=r"(r1), "=r"(r2), "=r"(r3) : "r"(addr))

__device__ __forceinline__ uint32_t pack2(float lo, float hi) {
    __half2 h = __floats2half2_rn(lo, hi);
    return *(uint32_t*)&h;
}

// ---------------------------------------------------------------------------
// Kernel 0: fused prep.
//   blocks [0, BB*HH): transpose x NCHW -> fp16 NHWC via smem tile
//   blocks [BB*HH, +27): weight B-fragment tables (mma register layout)
// Fragment mapping (derived from ldmatrix.m8n8.x4 + our b_row/b_c8 addressing):
//   reg m of lane l = W[o0 + 8*(m>>1) + (l>>2)][c0 + 8*(m&1) + 2*(l&3) + {0,1}]
// ---------------------------------------------------------------------------
__global__ void __launch_bounds__(256) prep_kernel(
    const float* __restrict__ x,
    const float* __restrict__ wgt,
    const float* __restrict__ pgw)
{
    const int tid = threadIdx.x;
    if (blockIdx.x < BB * HH) {
        extern __shared__ __align__(16) __half sT[];   // [128][T_STRIDE]
        const int b = blockIdx.x >> 7;
        const int y = blockIdx.x & 127;
        const float* src = x + (size_t)b * CIN * HW + y * WW;
        __half*      dst = g_xh + ((size_t)b * HH + y) * WW * CIN;
#pragma unroll
        for (int i = 0; i < 16; i++) {
            int idx = tid + (i << 8);
            int w   = idx & 127;
            int c0  = (idx >> 7) << 1;
            float2 v;
            v.x = __ldg(src + (size_t)c0 * HW + w);
            v.y = __ldg(src + ((size_t)c0 + 1) * HW + w);
            __half2 hh = __float22half2_rn(v);
            *(__half2*)(sT + w * T_STRIDE + c0) = hh;
        }
        __syncthreads();
        // 4x aligned LDS.32 (stride 132B -> uint4 would misalign for odd w)
#pragma unroll
        for (int i = 0; i < 4; i++) {
            int idx = tid + (i << 8);
            int w   = idx >> 3;
            int cg  = idx & 7;
            const uint32_t* pr = (const uint32_t*)(sT + w * T_STRIDE + (cg << 3));
            uint4 v;
            v.x = pr[0]; v.y = pr[1]; v.z = pr[2]; v.w = pr[3];
            *(uint4*)(dst + w * CIN + (cg << 3)) = v;
        }
    } else {
        int e = (blockIdx.x - BB * HH) * 256 + tid;
        if (e < NBF) {
            int lane = e & 31, kc = (e >> 5) & 3, t4 = (e >> 7) & 3, k = e >> 9;
            uint32_t r[4];
#pragma unroll
            for (int m = 0; m < 4; m++) {
                int o = (t4 << 4) + ((m >> 1) << 3) + (lane >> 2);
                int c = (kc << 4) + ((m & 1) << 3) + ((lane & 3) << 1);
                r[m] = pack2(wgt[o * (CIN * KK) + c * KK + k],
                             wgt[o * (CIN * KK) + (c + 1) * KK + k]);
            }
            g_bf[e] = make_uint4(r[0], r[1], r[2], r[3]);
        } else if (e < NBF + NPF) {
            int j = e - NBF;
            int lane = j & 31, kc = (j >> 5) & 3, nn = (j >> 7) & 1, t = j >> 8;
            uint32_t r[4];
#pragma unroll
            for (int m = 0; m < 4; m++) {
                int p = (nn << 4) + ((m >> 1) << 3) + (lane >> 2);
                int c = (kc << 4) + ((m & 1) << 3) + ((lane & 3) << 1);
                float v0 = (p < NP) ? pgw[p * (CIN * KK) + c * KK + t] : 0.f;
                float v1 = (p < NP) ? pgw[p * (CIN * KK) + (c + 1) * KK + t] : 0.f;
                r[m] = pack2(v0, v1);
            }
            g_pf[j] = make_uint4(r[0], r[1], r[2], r[3]);
        }
    }
}

// ---------------------------------------------------------------------------
// Kernel 1: param conv, fp16 mma + ldmatrix A; B fragments direct from
// global table -> NO per-tap smem staging, NO per-tap __syncthreads.
// ---------------------------------------------------------------------------
__global__ void __launch_bounds__(256) param_mma_kernel(
    const float* __restrict__ pgb)
{
    extern __shared__ __align__(16) __half psm[];
    __half* sX = psm;                          // [3][130][SH_STRIDE]
    float*  sD = (float*)(psm + 3 * PX_TILE);  // [128][PD_STRIDE]

    const int tid  = threadIdx.x;
    const int lane = tid & 31;
    const int wid  = tid >> 5;
    const int b    = blockIdx.x >> 7;
    const int h    = blockIdx.x & 127;

    const int w0 = wid << 4;
    const int gy = lane >> 2;
    const int tg = lane & 3;

    const int a_row = w0 + (lane & 15);
    const int a_c8  = (lane >> 4) << 3;

    // ---- stage X rows h-1..h+1 (coalesced), zero pad pos 0/129 ----
#pragma unroll
    for (int i = 0; i < 12; i++) {
        int idx = tid + (i << 8);
        int ti  = idx >> 10;
        int r   = idx & 1023;
        int w   = r >> 3;
        int cg  = r & 7;
        int row = h - 1 + ti;
        uint4 v = make_uint4(0, 0, 0, 0);
        if (row >= 0 && row < HH)
            v = __ldg((const uint4*)(g_xh + (((size_t)b * HH + row) * WW + w) * CIN) + cg);
        *(uint4*)(sX + (ti * 130 + w + 1) * SH_STRIDE + (cg << 3)) = v;
    }
    if (tid < 48) {
        int ti  = tid >> 4;
        int r   = tid & 15;
        int pos = (r >> 3) ? 129 : 0;
        int cg  = r & 7;
        *(uint4*)(sX + (ti * 130 + pos) * SH_STRIDE + (cg << 3)) = make_uint4(0, 0, 0, 0);
    }
    __syncthreads();   // the ONLY pre-loop barrier; taps run barrier-free

    float acc[16];
#pragma unroll
    for (int i = 0; i < 16; i++) acc[i] = 0.f;

    for (int t = 0; t < KK; t++) {
        const int ti = t / 3, tj = t % 3;
        const uint32_t sX_base = smem_u32(sX) + (ti * 130 + tj) * SH_STRIDE * 2;
#pragma unroll
        for (int kc = 0; kc < 4; kc++) {
            int c0 = kc << 4;
            uint32_t a0, a1, a2, a3;
            LDMATRIX_X4(a0, a1, a2, a3,
                        sX_base + (a_row * SH_STRIDE + c0 + a_c8) * 2);
#pragma unroll
            for (int nn = 0; nn < 2; nn++) {
                uint4 bv = __ldg(&g_pf[(t << 8) + (nn << 7) + (kc << 5) + lane]);
                MMA_F16(acc + (nn << 3),     a0, a1, a2, a3, bv.x, bv.y);
                MMA_F16(acc + (nn << 3) + 4, a0, a1, a2, a3, bv.z, bv.w);
            }
        }
    }
    __syncthreads();

#pragma unroll
    for (int n = 0; n < 4; n++) {
#pragma unroll
        for (int j = 0; j < 4; j++) {
            int p  = (n << 3) + (tg << 1) + (j & 1);
            int wr = w0 + gy + ((j >> 1) << 3);
            sD[wr * PD_STRIDE + p] = acc[(n << 2) + j];
        }
    }
    __syncthreads();

    if (tid < WW) {
        float prm[NP];
#pragma unroll
        for (int p = 0; p < NP; p++)
            prm[p] = sD[tid * PD_STRIDE + p] + __ldg(pgb + p);
        const int base = b * KK * HW + h * WW + tid;
#pragma unroll
        for (int k = 0; k < KK; k++) {
            int ki = k / 3, kj = k % 3;
            int4 co; float4 cq;
            make_corner((float)(h - 1 + ki) + prm[2 * k],
                        (float)(tid - 1 + kj) + prm[2 * k + 1],
                        1.f / (1.f + expf(-prm[18 + k])), co, cq);
            g_co[base + k * HW] = co;
            g_cq[base + k * HW] = cq;
        }
    }
}

// ---------------------------------------------------------------------------
// Kernel 2: DCN main. S double-buffered in smem (36.9KB total, 1 sync/tap);
// B fragments direct from global table (L1-resident: 73.7KB < L1D carveout).
// Warp tile 32w x 32o.
// ---------------------------------------------------------------------------
__global__ void __launch_bounds__(256, 4) dcn_kernel(
    const float* __restrict__ bias,
    float* __restrict__ out)
{
    extern __shared__ __align__(16) __half smh[];   // 2 * BUF_H halves

    const int tid  = threadIdx.x;
    const int lane = tid & 31;
    const int wid  = tid >> 5;
    const int b    = blockIdx.x >> 7;
    const int h    = blockIdx.x & 127;

    const int cg = lane & 7;
    const int px = lane >> 3;
    const int ws0 = wid << 4;
    const __half* xh = g_xh + ((size_t)b << 20);
    const int prow = b * KK * HW + h * WW;

    const int mg = wid & 3;
    const int ng = wid >> 2;
    const int gy = lane >> 2;
    const int tg = lane & 3;
    const int a_row0 = (mg << 5) + (lane & 15);
    const int a_c8   = (lane >> 4) << 3;

    float acc[32];
#pragma unroll
    for (int i = 0; i < 32; i++) acc[i] = 0.f;

    for (int k = 0; k < KK; k++) {
        __half* sS = smh + (k & 1) * BUF_H;

        // ---- stage S_k: fp16 NHWC gather (LDG.128 = 8ch), fp32 blend ----
        {
            const int pk = prow + k * HW;
#pragma unroll
            for (int r = 0; r < 4; r++) {
                int w = ws0 + (r << 2) + px;
                int4   co = __ldg(&g_co[pk + w]);
                float4 cq = __ldg(&g_cq[pk + w]);
                uint4 u0 = __ldg((const uint4*)(xh + ((size_t)co.x << 6)) + cg);
                uint4 u1 = __ldg((const uint4*)(xh + ((size_t)co.y << 6)) + cg);
                uint4 u2 = __ldg((const uint4*)(xh + ((size_t)co.z << 6)) + cg);
                uint4 u3 = __ldg((const uint4*)(xh + ((size_t)co.w << 6)) + cg);
                const __half2* p0 = (const __half2*)&u0;
                const __half2* p1 = (const __half2*)&u1;
                const __half2* p2 = (const __half2*)&u2;
                const __half2* p3 = (const __half2*)&u3;
                uint32_t res[4];
#pragma unroll
                for (int j = 0; j < 4; j++) {
                    float2 f0 = __half22float2(p0[j]);
                    float2 f1 = __half22float2(p1[j]);
                    float2 f2 = __half22float2(p2[j]);
                    float2 f3 = __half22float2(p3[j]);
                    float2 s;
                    s.x = cq.x * f0.x + cq.y * f1.x + cq.z * f2.x + cq.w * f3.x;
                    s.y = cq.x * f0.y + cq.y * f1.y + cq.z * f2.y + cq.w * f3.y;
                    __half2 hh = __float22half2_rn(s);
                    res[j] = *(uint32_t*)&hh;
                }
                *(uint4*)(sS + w * SH_STRIDE + (cg << 3)) =
                    make_uint4(res[0], res[1], res[2], res[3]);
            }
        }
        __syncthreads();

        // ---- MMA: 4 K-chunks of 16; A via ldmatrix, B via table LDG ----
        const uint32_t sS_base = smem_u32(sS);
#pragma unroll
        for (int kc = 0; kc < 4; kc++) {
            int c0 = kc << 4;
            uint32_t a0, a1, a2, a3, a4, a5, a6, a7;
            LDMATRIX_X4(a0, a1, a2, a3,
                        sS_base + (a_row0 * SH_STRIDE + c0 + a_c8) * 2);
            LDMATRIX_X4(a4, a5, a6, a7,
                        sS_base + ((a_row0 + 16) * SH_STRIDE + c0 + a_c8) * 2);
#pragma unroll
            for (int q = 0; q < 2; q++) {
                int t4 = (ng << 1) | q;
                uint4 bv = __ldg(&g_bf[(k << 9) + (t4 << 7) + (kc << 5) + lane]);
                int nj = q << 1;
                MMA_F16(acc + (nj << 2),            a0, a1, a2, a3, bv.x, bv.y);
                MMA_F16(acc + ((nj + 1) << 2),      a0, a1, a2, a3, bv.z, bv.w);
                MMA_F16(acc + ((4 + nj) << 2),      a4, a5, a6, a7, bv.x, bv.y);
                MMA_F16(acc + ((4 + nj + 1) << 2),  a4, a5, a6, a7, bv.z, bv.w);
            }
        }
    }

    // ---- epilogue: acc[(mi*4+nj)*4+j] -> out[b][o][h][wr] ----
#pragma unroll
    for (int mi = 0; mi < 2; mi++) {
#pragma unroll
        for (int nj = 0; nj < 4; nj++) {
#pragma unroll
            for (int j = 0; j < 4; j++) {
                int o  = (ng << 5) + (nj << 3) + (tg << 1) + (j & 1);
                int wr = (mg << 5) + (mi << 4) + gy + ((j >> 1) << 3);
                out[(((size_t)b * COUT + o) * HH + h) * WW + wr] =
                    acc[((mi << 2) + nj) * 4 + j] + __ldg(bias + o);
            }
        }
    }
}

// ---------------------------------------------------------------------------
extern "C" void kernel_launch(void* const* d_in, const int* in_sizes, int n_in,
                              void* d_out, int out_size)
{
    const float* x    = (const float*)d_in[0];
    const float* wgt  = (const float*)d_in[1];
    const float* bias = (const float*)d_in[2];
    const float* pgw  = (const float*)d_in[3];
    const float* pgb  = (const float*)d_in[4];
    float* out = (float*)d_out;

    const int smem0 = WW * T_STRIDE * (int)sizeof(__half);   // 16896 B
    cudaFuncSetAttribute(prep_kernel,
                         cudaFuncAttributeMaxDynamicSharedMemorySize, smem0);

    const int smem1 = 3 * PX_TILE * (int)sizeof(__half)
                    + WW * PD_STRIDE * (int)sizeof(float);   // 74592 B
    cudaFuncSetAttribute(param_mma_kernel,
                         cudaFuncAttributeMaxDynamicSharedMemorySize, smem1);

    const int smem2 = 2 * BUF_H * (int)sizeof(__half);       // 36864 B
    cudaFuncSetAttribute(dcn_kernel,
                         cudaFuncAttributeMaxDynamicSharedMemorySize, smem2);

    const int nfrag_blocks = (NBF + NPF + 255) / 256;        // 27
    prep_kernel<<<BB * HH + nfrag_blocks, 256, smem0>>>(x, wgt, pgw);
    param_mma_kernel<<<BB * HH, 256, smem1>>>(pgb);
    dcn_kernel<<<BB * HH, 256, smem2>>>(bias, out);
}

// round 14
// speedup vs baseline: 8.1043x; 1.2356x over previous
#include <cuda_runtime.h>
#include <cuda_fp16.h>
#include <math.h>
#include <stdint.h>

#define BB   8
#define CIN  64
#define COUT 64
#define HH   128
#define WW   128
#define KK   9
#define NP   27
#define HW   (HH * WW)

#define SH_STRIDE 72                  // fp16 tile row stride (144 B)
#define BUF_H     (WW * SH_STRIDE)    // S buffer slot (halves)
#define PX_TILE   (130 * SH_STRIDE)   // param X tile per image row (halves)
#define PD_STRIDE 36                  // D staging stride (floats)
#define T_STRIDE  66                  // transpose smem tile stride (halves)

// fused smem byte layout
#define SM_BYTES   74592
#define OFF_SD     56160              // phase A: sD floats
#define OFF_CO     36864              // phase B: corner tables [9][128] co+cq
#define OFF_CQ     (OFF_CO + KK * WW * 16)

#define NBF 4608                      // dcn B-frag entries
#define NPF 2304                      // param B-frag entries

// ---------------------------------------------------------------------------
// Scratch (device globals: no allocation allowed)
// ---------------------------------------------------------------------------
__device__ uint4    g_bf[NBF];            // dcn  B fragments (mma register layout)
__device__ uint4    g_pf[NPF];            // param B fragments
__device__ __half   g_xh[BB * HW * CIN];  // x as fp16 NHWC: [b][y][x][c]

// ---------------------------------------------------------------------------
__device__ __forceinline__ uint32_t smem_u32(const void* p) {
    uint32_t a;
    asm("{ .reg .u64 t; cvta.to.shared.u64 t, %1; cvt.u32.u64 %0, t; }" : "=r"(a) : "l"(p));
    return a;
}

__device__ __forceinline__ void make_corner(float sy, float sx, float mk,
                                            int4& co, float4& cq) {
    float y0f = floorf(sy), x0f = floorf(sx);
    int   iy0 = (int)y0f,   ix0 = (int)x0f;
    float fy = sy - y0f,    fx = sx - x0f;
    float w00 = (1.f - fy) * (1.f - fx);
    float w01 = (1.f - fy) * fx;
    float w10 = fy * (1.f - fx);
    float w11 = fy * fx;
    bool oky0 = (iy0 >= 0) && (iy0 < HH);
    bool oky1 = (iy0 + 1 >= 0) && (iy0 + 1 < HH);
    bool okx0 = (ix0 >= 0) && (ix0 < WW);
    bool okx1 = (ix0 + 1 >= 0) && (ix0 + 1 < WW);
    int cy0 = min(max(iy0, 0), HH - 1);
    int cy1 = min(max(iy0 + 1, 0), HH - 1);
    int cx0 = min(max(ix0, 0), WW - 1);
    int cx1 = min(max(ix0 + 1, 0), WW - 1);
    co = make_int4(cy0 * WW + cx0, cy0 * WW + cx1, cy1 * WW + cx0, cy1 * WW + cx1);
    cq = make_float4((oky0 && okx0) ? w00 * mk : 0.f,
                     (oky0 && okx1) ? w01 * mk : 0.f,
                     (oky1 && okx0) ? w10 * mk : 0.f,
                     (oky1 && okx1) ? w11 * mk : 0.f);
}

#define MMA_F16(d, a0, a1, a2, a3, b0, b1)                                    \
    asm volatile(                                                             \
        "mma.sync.aligned.m16n8k16.row.col.f32.f16.f16.f32 "                  \
        "{%0,%1,%2,%3}, {%4,%5,%6,%7}, {%8,%9}, {%0,%1,%2,%3};"               \
        : "+f"((d)[0]), "+f"((d)[1]), "+f"((d)[2]), "+f"((d)[3])              \
        : "r"(a0), "r"(a1), "r"(a2), "r"(a3), "r"(b0), "r"(b1))

#define LDMATRIX_X4(r0, r1, r2, r3, addr)                                     \
    asm volatile("ldmatrix.sync.aligned.m8n8.x4.shared.b16 {%0,%1,%2,%3}, [%4];" \
                 : "=r"(r0), "=r"(r1), "=r"(r2), "=r"(r3) : "r"(addr))

__device__ __forceinline__ uint32_t pack2(float lo, float hi) {
    __half2 h = __floats2half2_rn(lo, hi);
    return *(uint32_t*)&h;
}

// ---------------------------------------------------------------------------
// Kernel 0: fused prep (transpose + B-fragment tables)
// ---------------------------------------------------------------------------
__global__ void __launch_bounds__(256) prep_kernel(
    const float* __restrict__ x,
    const float* __restrict__ wgt,
    const float* __restrict__ pgw)
{
    const int tid = threadIdx.x;
    if (blockIdx.x < BB * HH) {
        extern __shared__ __align__(16) __half sT[];   // [128][T_STRIDE]
        const int b = blockIdx.x >> 7;
        const int y = blockIdx.x & 127;
        const float* src = x + (size_t)b * CIN * HW + y * WW;
        __half*      dst = g_xh + ((size_t)b * HH + y) * WW * CIN;
#pragma unroll
        for (int i = 0; i < 16; i++) {
            int idx = tid + (i << 8);
            int w   = idx & 127;
            int c0  = (idx >> 7) << 1;
            float2 v;
            v.x = __ldg(src + (size_t)c0 * HW + w);
            v.y = __ldg(src + ((size_t)c0 + 1) * HW + w);
            __half2 hh = __float22half2_rn(v);
            *(__half2*)(sT + w * T_STRIDE + c0) = hh;
        }
        __syncthreads();
#pragma unroll
        for (int i = 0; i < 4; i++) {
            int idx = tid + (i << 8);
            int w   = idx >> 3;
            int cg  = idx & 7;
            const uint32_t* pr = (const uint32_t*)(sT + w * T_STRIDE + (cg << 3));
            uint4 v;
            v.x = pr[0]; v.y = pr[1]; v.z = pr[2]; v.w = pr[3];
            *(uint4*)(dst + w * CIN + (cg << 3)) = v;
        }
    } else {
        int e = (blockIdx.x - BB * HH) * 256 + tid;
        if (e < NBF) {
            int lane = e & 31, kc = (e >> 5) & 3, t4 = (e >> 7) & 3, k = e >> 9;
            uint32_t r[4];
#pragma unroll
            for (int m = 0; m < 4; m++) {
                int o = (t4 << 4) + ((m >> 1) << 3) + (lane >> 2);
                int c = (kc << 4) + ((m & 1) << 3) + ((lane & 3) << 1);
                r[m] = pack2(wgt[o * (CIN * KK) + c * KK + k],
                             wgt[o * (CIN * KK) + (c + 1) * KK + k]);
            }
            g_bf[e] = make_uint4(r[0], r[1], r[2], r[3]);
        } else if (e < NBF + NPF) {
            int j = e - NBF;
            int lane = j & 31, kc = (j >> 5) & 3, nn = (j >> 7) & 1, t = j >> 8;
            uint32_t r[4];
#pragma unroll
            for (int m = 0; m < 4; m++) {
                int p = (nn << 4) + ((m >> 1) << 3) + (lane >> 2);
                int c = (kc << 4) + ((m & 1) << 3) + ((lane & 3) << 1);
                float v0 = (p < NP) ? pgw[p * (CIN * KK) + c * KK + t] : 0.f;
                float v1 = (p < NP) ? pgw[p * (CIN * KK) + (c + 1) * KK + t] : 0.f;
                r[m] = pack2(v0, v1);
            }
            g_pf[j] = make_uint4(r[0], r[1], r[2], r[3]);
        }
    }
}

// ---------------------------------------------------------------------------
// Kernel 1: FUSED param conv + DCN main per (b,h) block.
// Phase A: X tile -> fp16 MMA -> prm -> corner tables in SMEM (never global).
// Phase B: 9-tap sampled GEMM, S double-buffered, B frags from global table.
// ---------------------------------------------------------------------------
__global__ void __launch_bounds__(256, 3) fused_kernel(
    const float* __restrict__ pgb,
    const float* __restrict__ bias,
    float* __restrict__ out)
{
    extern __shared__ __align__(16) __half sm[];
    __half* sX  = sm;                                   // phase A: [3][130][SH_STRIDE]
    float*  sD  = (float*)((char*)sm + OFF_SD);         // phase A: [128][PD_STRIDE]
    int4*   sCO = (int4*)((char*)sm + OFF_CO);          // phase B: [9][128]
    float4* sCQ = (float4*)((char*)sm + OFF_CQ);        // phase B: [9][128]

    const int tid  = threadIdx.x;
    const int lane = tid & 31;
    const int wid  = tid >> 5;
    const int b    = blockIdx.x >> 7;
    const int h    = blockIdx.x & 127;

    const int gy = lane >> 2;
    const int tg = lane & 3;
    const int a_c8 = (lane >> 4) << 3;

    // ================= PHASE A: param conv =================
    {
        const int w0 = wid << 4;
        const int a_row = w0 + (lane & 15);

        // stage X rows h-1..h+1 (coalesced), zero pad pos 0/129
#pragma unroll
        for (int i = 0; i < 12; i++) {
            int idx = tid + (i << 8);
            int ti  = idx >> 10;
            int r   = idx & 1023;
            int w   = r >> 3;
            int cg  = r & 7;
            int row = h - 1 + ti;
            uint4 v = make_uint4(0, 0, 0, 0);
            if (row >= 0 && row < HH)
                v = __ldg((const uint4*)(g_xh + (((size_t)b * HH + row) * WW + w) * CIN) + cg);
            *(uint4*)(sX + (ti * 130 + w + 1) * SH_STRIDE + (cg << 3)) = v;
        }
        if (tid < 48) {
            int ti  = tid >> 4;
            int r   = tid & 15;
            int pos = (r >> 3) ? 129 : 0;
            int cg  = r & 7;
            *(uint4*)(sX + (ti * 130 + pos) * SH_STRIDE + (cg << 3)) = make_uint4(0, 0, 0, 0);
        }
        __syncthreads();

        float acc[16];
#pragma unroll
        for (int i = 0; i < 16; i++) acc[i] = 0.f;

        for (int t = 0; t < KK; t++) {
            const int ti = t / 3, tj = t % 3;
            const uint32_t sX_base = smem_u32(sX) + (ti * 130 + tj) * SH_STRIDE * 2;
#pragma unroll
            for (int kc = 0; kc < 4; kc++) {
                int c0 = kc << 4;
                uint32_t a0, a1, a2, a3;
                LDMATRIX_X4(a0, a1, a2, a3,
                            sX_base + (a_row * SH_STRIDE + c0 + a_c8) * 2);
#pragma unroll
                for (int nn = 0; nn < 2; nn++) {
                    uint4 bv = __ldg(&g_pf[(t << 8) + (nn << 7) + (kc << 5) + lane]);
                    MMA_F16(acc + (nn << 3),     a0, a1, a2, a3, bv.x, bv.y);
                    MMA_F16(acc + (nn << 3) + 4, a0, a1, a2, a3, bv.z, bv.w);
                }
            }
        }
        __syncthreads();   // sX reads done (sD region disjoint from sX; safe to fill now)

#pragma unroll
        for (int n = 0; n < 4; n++) {
#pragma unroll
            for (int j = 0; j < 4; j++) {
                int p  = (n << 3) + (tg << 1) + (j & 1);
                int wr = w0 + gy + ((j >> 1) << 3);
                sD[wr * PD_STRIDE + p] = acc[(n << 2) + j];
            }
        }
        __syncthreads();

        // prm into registers (tid<128), then corners into smem tables
        float prm[NP];
        if (tid < WW) {
#pragma unroll
            for (int p = 0; p < NP; p++)
                prm[p] = sD[tid * PD_STRIDE + p] + __ldg(pgb + p);
        }
        __syncthreads();   // all sD reads done before corner region (overlaps sD/sX) is written
        if (tid < WW) {
#pragma unroll
            for (int k = 0; k < KK; k++) {
                int ki = k / 3, kj = k % 3;
                int4 co; float4 cq;
                make_corner((float)(h - 1 + ki) + prm[2 * k],
                            (float)(tid - 1 + kj) + prm[2 * k + 1],
                            1.f / (1.f + expf(-prm[18 + k])), co, cq);
                sCO[(k << 7) + tid] = co;
                sCQ[(k << 7) + tid] = cq;
            }
        }
        __syncthreads();
    }

    // ================= PHASE B: DCN main =================
    const int cg = lane & 7;
    const int px = lane >> 3;
    const int ws0 = wid << 4;
    const __half* xh = g_xh + ((size_t)b << 20);

    const int mg = wid & 3;
    const int ng = wid >> 2;
    const int a_row0 = (mg << 5) + (lane & 15);

    float acc[32];
#pragma unroll
    for (int i = 0; i < 32; i++) acc[i] = 0.f;

    for (int k = 0; k < KK; k++) {
        __half* sS = sm + (k & 1) * BUF_H;

        // ---- stage S_k: corners from SMEM, fp16 NHWC gather, fp32 blend ----
#pragma unroll
        for (int r = 0; r < 4; r++) {
            int w = ws0 + (r << 2) + px;
            int4   co = sCO[(k << 7) + w];
            float4 cq = sCQ[(k << 7) + w];
            uint4 u0 = __ldg((const uint4*)(xh + ((size_t)co.x << 6)) + cg);
            uint4 u1 = __ldg((const uint4*)(xh + ((size_t)co.y << 6)) + cg);
            uint4 u2 = __ldg((const uint4*)(xh + ((size_t)co.z << 6)) + cg);
            uint4 u3 = __ldg((const uint4*)(xh + ((size_t)co.w << 6)) + cg);
            const __half2* p0 = (const __half2*)&u0;
            const __half2* p1 = (const __half2*)&u1;
            const __half2* p2 = (const __half2*)&u2;
            const __half2* p3 = (const __half2*)&u3;
            uint32_t res[4];
#pragma unroll
            for (int j = 0; j < 4; j++) {
                float2 f0 = __half22float2(p0[j]);
                float2 f1 = __half22float2(p1[j]);
                float2 f2 = __half22float2(p2[j]);
                float2 f3 = __half22float2(p3[j]);
                float2 s;
                s.x = cq.x * f0.x + cq.y * f1.x + cq.z * f2.x + cq.w * f3.x;
                s.y = cq.x * f0.y + cq.y * f1.y + cq.z * f2.y + cq.w * f3.y;
                __half2 hh = __float22half2_rn(s);
                res[j] = *(uint32_t*)&hh;
            }
            *(uint4*)(sS + w * SH_STRIDE + (cg << 3)) =
                make_uint4(res[0], res[1], res[2], res[3]);
        }
        __syncthreads();

        // ---- MMA: 4 K-chunks of 16; A via ldmatrix, B via table LDG ----
        const uint32_t sS_base = smem_u32(sS);
#pragma unroll
        for (int kc = 0; kc < 4; kc++) {
            int c0 = kc << 4;
            uint32_t a0, a1, a2, a3, a4, a5, a6, a7;
            LDMATRIX_X4(a0, a1, a2, a3,
                        sS_base + (a_row0 * SH_STRIDE + c0 + a_c8) * 2);
            LDMATRIX_X4(a4, a5, a6, a7,
                        sS_base + ((a_row0 + 16) * SH_STRIDE + c0 + a_c8) * 2);
#pragma unroll
            for (int q = 0; q < 2; q++) {
                int t4 = (ng << 1) | q;
                uint4 bv = __ldg(&g_bf[(k << 9) + (t4 << 7) + (kc << 5) + lane]);
                int nj = q << 1;
                MMA_F16(acc + (nj << 2),            a0, a1, a2, a3, bv.x, bv.y);
                MMA_F16(acc + ((nj + 1) << 2),      a0, a1, a2, a3, bv.z, bv.w);
                MMA_F16(acc + ((4 + nj) << 2),      a4, a5, a6, a7, bv.x, bv.y);
                MMA_F16(acc + ((4 + nj + 1) << 2),  a4, a5, a6, a7, bv.z, bv.w);
            }
        }
    }

    // ---- epilogue: acc[(mi*4+nj)*4+j] -> out[b][o][h][wr] ----
#pragma unroll
    for (int mi = 0; mi < 2; mi++) {
#pragma unroll
        for (int nj = 0; nj < 4; nj++) {
#pragma unroll
            for (int j = 0; j < 4; j++) {
                int o  = (ng << 5) + (nj << 3) + (tg << 1) + (j & 1);
                int wr = (mg << 5) + (mi << 4) + gy + ((j >> 1) << 3);
                out[(((size_t)b * COUT + o) * HH + h) * WW + wr] =
                    acc[((mi << 2) + nj) * 4 + j] + __ldg(bias + o);
            }
        }
    }
}

// ---------------------------------------------------------------------------
extern "C" void kernel_launch(void* const* d_in, const int* in_sizes, int n_in,
                              void* d_out, int out_size)
{
    const float* x    = (const float*)d_in[0];
    const float* wgt  = (const float*)d_in[1];
    const float* bias = (const float*)d_in[2];
    const float* pgw  = (const float*)d_in[3];
    const float* pgb  = (const float*)d_in[4];
    float* out = (float*)d_out;

    const int smem0 = WW * T_STRIDE * (int)sizeof(__half);   // 16896 B
    cudaFuncSetAttribute(prep_kernel,
                         cudaFuncAttributeMaxDynamicSharedMemorySize, smem0);

    cudaFuncSetAttribute(fused_kernel,
                         cudaFuncAttributeMaxDynamicSharedMemorySize, SM_BYTES);

    const int nfrag_blocks = (NBF + NPF + 255) / 256;        // 27
    prep_kernel<<<BB * HH + nfrag_blocks, 256, smem0>>>(x, wgt, pgw);
    fused_kernel<<<BB * HH, 256, SM_BYTES>>>(pgb, bias, out);
}

// round 15
// speedup vs baseline: 8.5278x; 1.0523x over previous
#include <cuda_runtime.h>
#include <cuda_fp16.h>
#include <math.h>
#include <stdint.h>

#define BB   8
#define CIN  64
#define COUT 64
#define HH   128
#define WW   128
#define KK   9
#define NP   27
#define HW   (HH * WW)

#define SH_STRIDE 72                  // fp16 tile row stride (144 B)
#define BUF_H     (WW * SH_STRIDE)    // S buffer slot (halves)
#define PX_TILE   (130 * SH_STRIDE)   // param X tile per image row (halves)
#define PD_STRIDE 36                  // D staging stride (floats)
#define T_STRIDE  66                  // transpose smem tile stride (halves)

// fused smem byte layout (56160 B total -> 4 blocks/SM)
//   phase A: sX [0, 56160);  sD overlay [36864, 55296)
//   phase B: S double buffer [0, 36864); packed corners [36864, 55296)
#define SM_BYTES   56160
#define OFF_SD     36864
#define OFF_CP     36864              // packed corner table [9][128] x uint4

#define NBF 4608                      // dcn B-frag entries
#define NPF 2304                      // param B-frag entries

// ---------------------------------------------------------------------------
// Scratch (device globals: no allocation allowed)
// ---------------------------------------------------------------------------
__device__ uint4    g_bf[NBF];            // dcn  B fragments (mma register layout)
__device__ uint4    g_pf[NPF];            // param B fragments
__device__ __half   g_xh[BB * HW * CIN];  // x as fp16 NHWC: [b][y][x][c]

// ---------------------------------------------------------------------------
__device__ __forceinline__ uint32_t smem_u32(const void* p) {
    uint32_t a;
    asm("{ .reg .u64 t; cvta.to.shared.u64 t, %1; cvt.u32.u64 %0, t; }" : "=r"(a) : "l"(p));
    return a;
}

__device__ __forceinline__ void make_corner(float sy, float sx, float mk,
                                            int4& co, float4& cq) {
    float y0f = floorf(sy), x0f = floorf(sx);
    int   iy0 = (int)y0f,   ix0 = (int)x0f;
    float fy = sy - y0f,    fx = sx - x0f;
    float w00 = (1.f - fy) * (1.f - fx);
    float w01 = (1.f - fy) * fx;
    float w10 = fy * (1.f - fx);
    float w11 = fy * fx;
    bool oky0 = (iy0 >= 0) && (iy0 < HH);
    bool oky1 = (iy0 + 1 >= 0) && (iy0 + 1 < HH);
    bool okx0 = (ix0 >= 0) && (ix0 < WW);
    bool okx1 = (ix0 + 1 >= 0) && (ix0 + 1 < WW);
    int cy0 = min(max(iy0, 0), HH - 1);
    int cy1 = min(max(iy0 + 1, 0), HH - 1);
    int cx0 = min(max(ix0, 0), WW - 1);
    int cx1 = min(max(ix0 + 1, 0), WW - 1);
    co = make_int4(cy0 * WW + cx0, cy0 * WW + cx1, cy1 * WW + cx0, cy1 * WW + cx1);
    cq = make_float4((oky0 && okx0) ? w00 * mk : 0.f,
                     (oky0 && okx1) ? w01 * mk : 0.f,
                     (oky1 && okx0) ? w10 * mk : 0.f,
                     (oky1 && okx1) ? w11 * mk : 0.f);
}

#define MMA_F16(d, a0, a1, a2, a3, b0, b1)                                    \
    asm volatile(                                                             \
        "mma.sync.aligned.m16n8k16.row.col.f32.f16.f16.f32 "                  \
        "{%0,%1,%2,%3}, {%4,%5,%6,%7}, {%8,%9}, {%0,%1,%2,%3};"               \
        : "+f"((d)[0]), "+f"((d)[1]), "+f"((d)[2]), "+f"((d)[3])              \
        : "r"(a0), "r"(a1), "r"(a2), "r"(a3), "r"(b0), "r"(b1))

#define LDMATRIX_X4(r0, r1, r2, r3, addr)                                     \
    asm volatile("ldmatrix.sync.aligned.m8n8.x4.shared.b16 {%0,%1,%2,%3}, [%4];" \
                 : "=r"(r0), "=r"(r1), "=r"(r2), "=r"(r3) : "r"(addr))

__device__ __forceinline__ uint32_t pack2(float lo, float hi) {
    __half2 h = __floats2half2_rn(lo, hi);
    return *(uint32_t*)&h;
}

// ---------------------------------------------------------------------------
// Kernel 0: fused prep (transpose + B-fragment tables), unchanged
// ---------------------------------------------------------------------------
__global__ void __launch_bounds__(256) prep_kernel(
    const float* __restrict__ x,
    const float* __restrict__ wgt,
    const float* __restrict__ pgw)
{
    const int tid = threadIdx.x;
    if (blockIdx.x < BB * HH) {
        extern __shared__ __align__(16) __half sT[];   // [128][T_STRIDE]
        const int b = blockIdx.x >> 7;
        const int y = blockIdx.x & 127;
        const float* src = x + (size_t)b * CIN * HW + y * WW;
        __half*      dst = g_xh + ((size_t)b * HH + y) * WW * CIN;
#pragma unroll
        for (int i = 0; i < 16; i++) {
            int idx = tid + (i << 8);
            int w   = idx & 127;
            int c0  = (idx >> 7) << 1;
            float2 v;
            v.x = __ldg(src + (size_t)c0 * HW + w);
            v.y = __ldg(src + ((size_t)c0 + 1) * HW + w);
            __half2 hh = __float22half2_rn(v);
            *(__half2*)(sT + w * T_STRIDE + c0) = hh;
        }
        __syncthreads();
#pragma unroll
        for (int i = 0; i < 4; i++) {
            int idx = tid + (i << 8);
            int w   = idx >> 3;
            int cg  = idx & 7;
            const uint32_t* pr = (const uint32_t*)(sT + w * T_STRIDE + (cg << 3));
            uint4 v;
            v.x = pr[0]; v.y = pr[1]; v.z = pr[2]; v.w = pr[3];
            *(uint4*)(dst + w * CIN + (cg << 3)) = v;
        }
    } else {
        int e = (blockIdx.x - BB * HH) * 256 + tid;
        if (e < NBF) {
            int lane = e & 31, kc = (e >> 5) & 3, t4 = (e >> 7) & 3, k = e >> 9;
            uint32_t r[4];
#pragma unroll
            for (int m = 0; m < 4; m++) {
                int o = (t4 << 4) + ((m >> 1) << 3) + (lane >> 2);
                int c = (kc << 4) + ((m & 1) << 3) + ((lane & 3) << 1);
                r[m] = pack2(wgt[o * (CIN * KK) + c * KK + k],
                             wgt[o * (CIN * KK) + (c + 1) * KK + k]);
            }
            g_bf[e] = make_uint4(r[0], r[1], r[2], r[3]);
        } else if (e < NBF + NPF) {
            int j = e - NBF;
            int lane = j & 31, kc = (j >> 5) & 3, nn = (j >> 7) & 1, t = j >> 8;
            uint32_t r[4];
#pragma unroll
            for (int m = 0; m < 4; m++) {
                int p = (nn << 4) + ((m >> 1) << 3) + (lane >> 2);
                int c = (kc << 4) + ((m & 1) << 3) + ((lane & 3) << 1);
                float v0 = (p < NP) ? pgw[p * (CIN * KK) + c * KK + t] : 0.f;
                float v1 = (p < NP) ? pgw[p * (CIN * KK) + (c + 1) * KK + t] : 0.f;
                r[m] = pack2(v0, v1);
            }
            g_pf[j] = make_uint4(r[0], r[1], r[2], r[3]);
        }
    }
}

// ---------------------------------------------------------------------------
// Kernel 1: FUSED param conv + DCN main per (b,h) block.
// Corner tables compressed to one uint4/pixel (co as 4xu16, cq as 2xhalf2)
// -> smem 56.2 KB -> 4 blocks/SM; corner reads 1 LDS.128/pixel.
// ---------------------------------------------------------------------------
__global__ void __launch_bounds__(256, 4) fused_kernel(
    const float* __restrict__ pgb,
    const float* __restrict__ bias,
    float* __restrict__ out)
{
    extern __shared__ __align__(16) __half sm[];
    __half* sX  = sm;                                   // phase A: [3][130][SH_STRIDE]
    float*  sD  = (float*)((char*)sm + OFF_SD);         // phase A: [128][PD_STRIDE]
    uint4*  sCP = (uint4*)((char*)sm + OFF_CP);         // phase B: [9][128] packed

    const int tid  = threadIdx.x;
    const int lane = tid & 31;
    const int wid  = tid >> 5;
    const int b    = blockIdx.x >> 7;
    const int h    = blockIdx.x & 127;

    const int gy = lane >> 2;
    const int tg = lane & 3;
    const int a_c8 = (lane >> 4) << 3;

    // ================= PHASE A: param conv =================
    {
        const int w0 = wid << 4;
        const int a_row = w0 + (lane & 15);

        // stage X rows h-1..h+1 (coalesced), zero pad pos 0/129
#pragma unroll
        for (int i = 0; i < 12; i++) {
            int idx = tid + (i << 8);
            int ti  = idx >> 10;
            int r   = idx & 1023;
            int w   = r >> 3;
            int cg  = r & 7;
            int row = h - 1 + ti;
            uint4 v = make_uint4(0, 0, 0, 0);
            if (row >= 0 && row < HH)
                v = __ldg((const uint4*)(g_xh + (((size_t)b * HH + row) * WW + w) * CIN) + cg);
            *(uint4*)(sX + (ti * 130 + w + 1) * SH_STRIDE + (cg << 3)) = v;
        }
        if (tid < 48) {
            int ti  = tid >> 4;
            int r   = tid & 15;
            int pos = (r >> 3) ? 129 : 0;
            int cg  = r & 7;
            *(uint4*)(sX + (ti * 130 + pos) * SH_STRIDE + (cg << 3)) = make_uint4(0, 0, 0, 0);
        }
        __syncthreads();

        float acc[16];
#pragma unroll
        for (int i = 0; i < 16; i++) acc[i] = 0.f;

        for (int t = 0; t < KK; t++) {
            const int ti = t / 3, tj = t % 3;
            const uint32_t sX_base = smem_u32(sX) + (ti * 130 + tj) * SH_STRIDE * 2;
#pragma unroll
            for (int kc = 0; kc < 4; kc++) {
                int c0 = kc << 4;
                uint32_t a0, a1, a2, a3;
                LDMATRIX_X4(a0, a1, a2, a3,
                            sX_base + (a_row * SH_STRIDE + c0 + a_c8) * 2);
#pragma unroll
                for (int nn = 0; nn < 2; nn++) {
                    uint4 bv = __ldg(&g_pf[(t << 8) + (nn << 7) + (kc << 5) + lane]);
                    MMA_F16(acc + (nn << 3),     a0, a1, a2, a3, bv.x, bv.y);
                    MMA_F16(acc + (nn << 3) + 4, a0, a1, a2, a3, bv.z, bv.w);
                }
            }
        }
        __syncthreads();   // sX reads done; sD region (inside dead sX) safe to fill

#pragma unroll
        for (int n = 0; n < 4; n++) {
#pragma unroll
            for (int j = 0; j < 4; j++) {
                int p  = (n << 3) + (tg << 1) + (j & 1);
                int wr = w0 + gy + ((j >> 1) << 3);
                sD[wr * PD_STRIDE + p] = acc[(n << 2) + j];
            }
        }
        __syncthreads();

        // prm into registers (tid<128), then packed corners into smem table
        float prm[NP];
        if (tid < WW) {
#pragma unroll
            for (int p = 0; p < NP; p++)
                prm[p] = sD[tid * PD_STRIDE + p] + __ldg(pgb + p);
        }
        __syncthreads();   // all sD reads done before corner region overwrites it
        if (tid < WW) {
#pragma unroll
            for (int k = 0; k < KK; k++) {
                int ki = k / 3, kj = k % 3;
                int4 co; float4 cq;
                make_corner((float)(h - 1 + ki) + prm[2 * k],
                            (float)(tid - 1 + kj) + prm[2 * k + 1],
                            1.f / (1.f + expf(-prm[18 + k])), co, cq);
                uint4 pk;
                pk.x = (uint32_t)co.x | ((uint32_t)co.y << 16);
                pk.y = (uint32_t)co.z | ((uint32_t)co.w << 16);
                pk.z = pack2(cq.x, cq.y);
                pk.w = pack2(cq.z, cq.w);
                sCP[(k << 7) + tid] = pk;
            }
        }
        __syncthreads();
    }

    // ================= PHASE B: DCN main =================
    const int cg = lane & 7;
    const int px = lane >> 3;
    const int ws0 = wid << 4;
    const __half* xh = g_xh + ((size_t)b << 20);

    const int mg = wid & 3;
    const int ng = wid >> 2;
    const int a_row0 = (mg << 5) + (lane & 15);

    float acc[32];
#pragma unroll
    for (int i = 0; i < 32; i++) acc[i] = 0.f;

    for (int k = 0; k < KK; k++) {
        __half* sS = sm + (k & 1) * BUF_H;

        // ---- stage S_k: packed corners from SMEM, fp16 NHWC gather ----
#pragma unroll
        for (int r = 0; r < 4; r++) {
            int w = ws0 + (r << 2) + px;
            uint4 cp = sCP[(k << 7) + w];
            int o0 = cp.x & 0xFFFF, o1 = cp.x >> 16;
            int o2 = cp.y & 0xFFFF, o3 = cp.y >> 16;
            float2 q01 = __half22float2(*(__half2*)&cp.z);
            float2 q23 = __half22float2(*(__half2*)&cp.w);
            uint4 u0 = __ldg((const uint4*)(xh + ((size_t)o0 << 6)) + cg);
            uint4 u1 = __ldg((const uint4*)(xh + ((size_t)o1 << 6)) + cg);
            uint4 u2 = __ldg((const uint4*)(xh + ((size_t)o2 << 6)) + cg);
            uint4 u3 = __ldg((const uint4*)(xh + ((size_t)o3 << 6)) + cg);
            const __half2* p0 = (const __half2*)&u0;
            const __half2* p1 = (const __half2*)&u1;
            const __half2* p2 = (const __half2*)&u2;
            const __half2* p3 = (const __half2*)&u3;
            uint32_t res[4];
#pragma unroll
            for (int j = 0; j < 4; j++) {
                float2 f0 = __half22float2(p0[j]);
                float2 f1 = __half22float2(p1[j]);
                float2 f2 = __half22float2(p2[j]);
                float2 f3 = __half22float2(p3[j]);
                float2 s;
                s.x = q01.x * f0.x + q01.y * f1.x + q23.x * f2.x + q23.y * f3.x;
                s.y = q01.x * f0.y + q01.y * f1.y + q23.x * f2.y + q23.y * f3.y;
                __half2 hh = __float22half2_rn(s);
                res[j] = *(uint32_t*)&hh;
            }
            *(uint4*)(sS + w * SH_STRIDE + (cg << 3)) =
                make_uint4(res[0], res[1], res[2], res[3]);
        }
        __syncthreads();

        // ---- MMA: 4 K-chunks of 16; A via ldmatrix, B via table LDG ----
        const uint32_t sS_base = smem_u32(sS);
#pragma unroll
        for (int kc = 0; kc < 4; kc++) {
            int c0 = kc << 4;
            uint32_t a0, a1, a2, a3, a4, a5, a6, a7;
            LDMATRIX_X4(a0, a1, a2, a3,
                        sS_base + (a_row0 * SH_STRIDE + c0 + a_c8) * 2);
            LDMATRIX_X4(a4, a5, a6, a7,
                        sS_base + ((a_row0 + 16) * SH_STRIDE + c0 + a_c8) * 2);
#pragma unroll
            for (int q = 0; q < 2; q++) {
                int t4 = (ng << 1) | q;
                uint4 bv = __ldg(&g_bf[(k << 9) + (t4 << 7) + (kc << 5) + lane]);
                int nj = q << 1;
                MMA_F16(acc + (nj << 2),            a0, a1, a2, a3, bv.x, bv.y);
                MMA_F16(acc + ((nj + 1) << 2),      a0, a1, a2, a3, bv.z, bv.w);
                MMA_F16(acc + ((4 + nj) << 2),      a4, a5, a6, a7, bv.x, bv.y);
                MMA_F16(acc + ((4 + nj + 1) << 2),  a4, a5, a6, a7, bv.z, bv.w);
            }
        }
    }

    // ---- epilogue: acc[(mi*4+nj)*4+j] -> out[b][o][h][wr] ----
#pragma unroll
    for (int mi = 0; mi < 2; mi++) {
#pragma unroll
        for (int nj = 0; nj < 4; nj++) {
#pragma unroll
            for (int j = 0; j < 4; j++) {
                int o  = (ng << 5) + (nj << 3) + (tg << 1) + (j & 1);
                int wr = (mg << 5) + (mi << 4) + gy + ((j >> 1) << 3);
                out[(((size_t)b * COUT + o) * HH + h) * WW + wr] =
                    acc[((mi << 2) + nj) * 4 + j] + __ldg(bias + o);
            }
        }
    }
}

// ---------------------------------------------------------------------------
extern "C" void kernel_launch(void* const* d_in, const int* in_sizes, int n_in,
                              void* d_out, int out_size)
{
    const float* x    = (const float*)d_in[0];
    const float* wgt  = (const float*)d_in[1];
    const float* bias = (const float*)d_in[2];
    const float* pgw  = (const float*)d_in[3];
    const float* pgb  = (const float*)d_in[4];
    float* out = (float*)d_out;

    const int smem0 = WW * T_STRIDE * (int)sizeof(__half);   // 16896 B
    cudaFuncSetAttribute(prep_kernel,
                         cudaFuncAttributeMaxDynamicSharedMemorySize, smem0);

    cudaFuncSetAttribute(fused_kernel,
                         cudaFuncAttributeMaxDynamicSharedMemorySize, SM_BYTES);

    const int nfrag_blocks = (NBF + NPF + 255) / 256;        // 27
    prep_kernel<<<BB * HH + nfrag_blocks, 256, smem0>>>(x, wgt, pgw);
    fused_kernel<<<BB * HH, 256, SM_BYTES>>>(pgb, bias, out);
}

// round 17
// speedup vs baseline: 8.8726x; 1.0404x over previous
#include <cuda_runtime.h>
#include <cuda_fp16.h>
#include <math.h>
#include <stdint.h>

#define BB   8
#define CIN  64
#define COUT 64
#define HH   128
#define WW   128
#define KK   9
#define NP   27
#define HW   (HH * WW)

#define SH_STRIDE 72                  // fp16 tile row stride (144 B)
#define BUF_H     (WW * SH_STRIDE)    // S buffer slot (halves)
#define PX_TILE   (130 * SH_STRIDE)   // param X tile per image row (halves)
#define PD_STRIDE 36                  // D staging stride (floats)
#define T_STRIDE  66                  // transpose smem tile stride (halves)

// fused smem byte layout (56160 B total -> 4 blocks/SM)
//   phase A: sX [0, 56160);  sD overlay [36864, 55296)
//   phase B: S double buffer [0, 36864); packed corners [36864, 55296)
#define SM_BYTES   56160
#define OFF_SD     36864
#define OFF_CP     36864              // packed corner table [9][128] x uint4

#define NBF 4608                      // dcn B-frag entries
#define NPF 2304                      // param B-frag entries

// ---------------------------------------------------------------------------
// Scratch (device globals: no allocation allowed)
// ---------------------------------------------------------------------------
__device__ uint4    g_bf[NBF];            // dcn  B fragments (mma register layout)
__device__ uint4    g_pf[NPF];            // param B fragments
__device__ __half   g_xh[BB * HW * CIN];  // x as fp16 NHWC: [b][y][x][c]

// ---------------------------------------------------------------------------
__device__ __forceinline__ uint32_t smem_u32(const void* p) {
    uint32_t a;
    asm("{ .reg .u64 t; cvta.to.shared.u64 t, %1; cvt.u32.u64 %0, t; }" : "=r"(a) : "l"(p));
    return a;
}

__device__ __forceinline__ void make_corner(float sy, float sx, float mk,
                                            int4& co, float4& cq) {
    float y0f = floorf(sy), x0f = floorf(sx);
    int   iy0 = (int)y0f,   ix0 = (int)x0f;
    float fy = sy - y0f,    fx = sx - x0f;
    float w00 = (1.f - fy) * (1.f - fx);
    float w01 = (1.f - fy) * fx;
    float w10 = fy * (1.f - fx);
    float w11 = fy * fx;
    bool oky0 = (iy0 >= 0) && (iy0 < HH);
    bool oky1 = (iy0 + 1 >= 0) && (iy0 + 1 < HH);
    bool okx0 = (ix0 >= 0) && (ix0 < WW);
    bool okx1 = (ix0 + 1 >= 0) && (ix0 + 1 < WW);
    int cy0 = min(max(iy0, 0), HH - 1);
    int cy1 = min(max(iy0 + 1, 0), HH - 1);
    int cx0 = min(max(ix0, 0), WW - 1);
    int cx1 = min(max(ix0 + 1, 0), WW - 1);
    co = make_int4(cy0 * WW + cx0, cy0 * WW + cx1, cy1 * WW + cx0, cy1 * WW + cx1);
    cq = make_float4((oky0 && okx0) ? w00 * mk : 0.f,
                     (oky0 && okx1) ? w01 * mk : 0.f,
                     (oky1 && okx0) ? w10 * mk : 0.f,
                     (oky1 && okx1) ? w11 * mk : 0.f);
}

#define MMA_F16(d, a0, a1, a2, a3, b0, b1)                                    \
    asm volatile(                                                             \
        "mma.sync.aligned.m16n8k16.row.col.f32.f16.f16.f32 "                  \
        "{%0,%1,%2,%3}, {%4,%5,%6,%7}, {%8,%9}, {%0,%1,%2,%3};"               \
        : "+f"((d)[0]), "+f"((d)[1]), "+f"((d)[2]), "+f"((d)[3])              \
        : "r"(a0), "r"(a1), "r"(a2), "r"(a3), "r"(b0), "r"(b1))

#define LDMATRIX_X4(r0, r1, r2, r3, addr)                                     \
    asm volatile("ldmatrix.sync.aligned.m8n8.x4.shared.b16 {%0,%1,%2,%3}, [%4];" \
                 : "=r"(r0), "=r"(r1), "=r"(r2), "=r"(r3) : "r"(addr))

__device__ __forceinline__ uint32_t pack2(float lo, float hi) {
    __half2 h = __floats2half2_rn(lo, hi);
    return *(uint32_t*)&h;
}

// ---------------------------------------------------------------------------
// Kernel 0: fused prep (transpose + B-fragment tables), unchanged
// ---------------------------------------------------------------------------
__global__ void __launch_bounds__(256) prep_kernel(
    const float* __restrict__ x,
    const float* __restrict__ wgt,
    const float* __restrict__ pgw)
{
    const int tid = threadIdx.x;
    if (blockIdx.x < BB * HH) {
        extern __shared__ __align__(16) __half sT[];   // [128][T_STRIDE]
        const int b = blockIdx.x >> 7;
        const int y = blockIdx.x & 127;
        const float* src = x + (size_t)b * CIN * HW + y * WW;
        __half*      dst = g_xh + ((size_t)b * HH + y) * WW * CIN;
#pragma unroll
        for (int i = 0; i < 16; i++) {
            int idx = tid + (i << 8);
            int w   = idx & 127;
            int c0  = (idx >> 7) << 1;
            float2 v;
            v.x = __ldg(src + (size_t)c0 * HW + w);
            v.y = __ldg(src + ((size_t)c0 + 1) * HW + w);
            __half2 hh = __float22half2_rn(v);
            *(__half2*)(sT + w * T_STRIDE + c0) = hh;
        }
        __syncthreads();
#pragma unroll
        for (int i = 0; i < 4; i++) {
            int idx = tid + (i << 8);
            int w   = idx >> 3;
            int cg  = idx & 7;
            const uint32_t* pr = (const uint32_t*)(sT + w * T_STRIDE + (cg << 3));
            uint4 v;
            v.x = pr[0]; v.y = pr[1]; v.z = pr[2]; v.w = pr[3];
            *(uint4*)(dst + w * CIN + (cg << 3)) = v;
        }
    } else {
        int e = (blockIdx.x - BB * HH) * 256 + tid;
        if (e < NBF) {
            int lane = e & 31, kc = (e >> 5) & 3, t4 = (e >> 7) & 3, k = e >> 9;
            uint32_t r[4];
#pragma unroll
            for (int m = 0; m < 4; m++) {
                int o = (t4 << 4) + ((m >> 1) << 3) + (lane >> 2);
                int c = (kc << 4) + ((m & 1) << 3) + ((lane & 3) << 1);
                r[m] = pack2(wgt[o * (CIN * KK) + c * KK + k],
                             wgt[o * (CIN * KK) + (c + 1) * KK + k]);
            }
            g_bf[e] = make_uint4(r[0], r[1], r[2], r[3]);
        } else if (e < NBF + NPF) {
            int j = e - NBF;
            int lane = j & 31, kc = (j >> 5) & 3, nn = (j >> 7) & 1, t = j >> 8;
            uint32_t r[4];
#pragma unroll
            for (int m = 0; m < 4; m++) {
                int p = (nn << 4) + ((m >> 1) << 3) + (lane >> 2);
                int c = (kc << 4) + ((m & 1) << 3) + ((lane & 3) << 1);
                float v0 = (p < NP) ? pgw[p * (CIN * KK) + c * KK + t] : 0.f;
                float v1 = (p < NP) ? pgw[p * (CIN * KK) + (c + 1) * KK + t] : 0.f;
                r[m] = pack2(v0, v1);
            }
            g_pf[j] = make_uint4(r[0], r[1], r[2], r[3]);
        }
    }
}

// ---------------------------------------------------------------------------
// Kernel 1: FUSED param conv + DCN main per (b,h) block.
// Phase B sampler blend in native half2 (HMUL2/HFMA2, no unpack/repack).
// ---------------------------------------------------------------------------
__global__ void __launch_bounds__(256, 4) fused_kernel(
    const float* __restrict__ pgb,
    const float* __restrict__ bias,
    float* __restrict__ out)
{
    extern __shared__ __align__(16) __half sm[];
    __half* sX  = sm;                                   // phase A: [3][130][SH_STRIDE]
    float*  sD  = (float*)((char*)sm + OFF_SD);         // phase A: [128][PD_STRIDE]
    uint4*  sCP = (uint4*)((char*)sm + OFF_CP);         // phase B: [9][128] packed

    const int tid  = threadIdx.x;
    const int lane = tid & 31;
    const int wid  = tid >> 5;
    const int b    = blockIdx.x >> 7;
    const int h    = blockIdx.x & 127;

    const int gy = lane >> 2;
    const int tg = lane & 3;
    const int a_c8 = (lane >> 4) << 3;

    // ================= PHASE A: param conv =================
    {
        const int w0 = wid << 4;
        const int a_row = w0 + (lane & 15);

        // stage X rows h-1..h+1 (coalesced), zero pad pos 0/129
#pragma unroll
        for (int i = 0; i < 12; i++) {
            int idx = tid + (i << 8);
            int ti  = idx >> 10;
            int r   = idx & 1023;
            int w   = r >> 3;
            int cg  = r & 7;
            int row = h - 1 + ti;
            uint4 v = make_uint4(0, 0, 0, 0);
            if (row >= 0 && row < HH)
                v = __ldg((const uint4*)(g_xh + (((size_t)b * HH + row) * WW + w) * CIN) + cg);
            *(uint4*)(sX + (ti * 130 + w + 1) * SH_STRIDE + (cg << 3)) = v;
        }
        if (tid < 48) {
            int ti  = tid >> 4;
            int r   = tid & 15;
            int pos = (r >> 3) ? 129 : 0;
            int cg  = r & 7;
            *(uint4*)(sX + (ti * 130 + pos) * SH_STRIDE + (cg << 3)) = make_uint4(0, 0, 0, 0);
        }
        __syncthreads();

        float acc[16];
#pragma unroll
        for (int i = 0; i < 16; i++) acc[i] = 0.f;

        for (int t = 0; t < KK; t++) {
            const int ti = t / 3, tj = t % 3;
            const uint32_t sX_base = smem_u32(sX) + (ti * 130 + tj) * SH_STRIDE * 2;
#pragma unroll
            for (int kc = 0; kc < 4; kc++) {
                int c0 = kc << 4;
                uint32_t a0, a1, a2, a3;
                LDMATRIX_X4(a0, a1, a2, a3,
                            sX_base + (a_row * SH_STRIDE + c0 + a_c8) * 2);
#pragma unroll
                for (int nn = 0; nn < 2; nn++) {
                    uint4 bv = __ldg(&g_pf[(t << 8) + (nn << 7) + (kc << 5) + lane]);
                    MMA_F16(acc + (nn << 3),     a0, a1, a2, a3, bv.x, bv.y);
                    MMA_F16(acc + (nn << 3) + 4, a0, a1, a2, a3, bv.z, bv.w);
                }
            }
        }
        __syncthreads();   // sX reads done; sD region (inside dead sX) safe to fill

#pragma unroll
        for (int n = 0; n < 4; n++) {
#pragma unroll
            for (int j = 0; j < 4; j++) {
                int p  = (n << 3) + (tg << 1) + (j & 1);
                int wr = w0 + gy + ((j >> 1) << 3);
                sD[wr * PD_STRIDE + p] = acc[(n << 2) + j];
            }
        }
        __syncthreads();

        // prm into registers (tid<128), then packed corners into smem table
        float prm[NP];
        if (tid < WW) {
#pragma unroll
            for (int p = 0; p < NP; p++)
                prm[p] = sD[tid * PD_STRIDE + p] + __ldg(pgb + p);
        }
        __syncthreads();   // all sD reads done before corner region overwrites it
        if (tid < WW) {
#pragma unroll
            for (int k = 0; k < KK; k++) {
                int ki = k / 3, kj = k % 3;
                int4 co; float4 cq;
                make_corner((float)(h - 1 + ki) + prm[2 * k],
                            (float)(tid - 1 + kj) + prm[2 * k + 1],
                            1.f / (1.f + expf(-prm[18 + k])), co, cq);
                uint4 pk;
                pk.x = (uint32_t)co.x | ((uint32_t)co.y << 16);
                pk.y = (uint32_t)co.z | ((uint32_t)co.w << 16);
                pk.z = pack2(cq.x, cq.y);
                pk.w = pack2(cq.z, cq.w);
                sCP[(k << 7) + tid] = pk;
            }
        }
        __syncthreads();
    }

    // ================= PHASE B: DCN main =================
    const int cg = lane & 7;
    const int px = lane >> 3;
    const int ws0 = wid << 4;
    const __half* xh = g_xh + ((size_t)b << 20);

    const int mg = wid & 3;
    const int ng = wid >> 2;
    const int a_row0 = (mg << 5) + (lane & 15);

    float acc[32];
#pragma unroll
    for (int i = 0; i < 32; i++) acc[i] = 0.f;

    for (int k = 0; k < KK; k++) {
        __half* sS = sm + (k & 1) * BUF_H;

        // ---- stage S_k: packed corners, fp16 gather, HALF2 blend ----
#pragma unroll
        for (int r = 0; r < 4; r++) {
            int w = ws0 + (r << 2) + px;
            uint4 cp = sCP[(k << 7) + w];
            int o0 = cp.x & 0xFFFF, o1 = cp.x >> 16;
            int o2 = cp.y & 0xFFFF, o3 = cp.y >> 16;
            __half2 qv01 = *(__half2*)&cp.z;
            __half2 qv23 = *(__half2*)&cp.w;
            __half2 q0 = __low2half2(qv01),  q1 = __high2half2(qv01);
            __half2 q2 = __low2half2(qv23),  q3 = __high2half2(qv23);
            uint4 u0 = __ldg((const uint4*)(xh + ((size_t)o0 << 6)) + cg);
            uint4 u1 = __ldg((const uint4*)(xh + ((size_t)o1 << 6)) + cg);
            uint4 u2 = __ldg((const uint4*)(xh + ((size_t)o2 << 6)) + cg);
            uint4 u3 = __ldg((const uint4*)(xh + ((size_t)o3 << 6)) + cg);
            const __half2* p0 = (const __half2*)&u0;
            const __half2* p1 = (const __half2*)&u1;
            const __half2* p2 = (const __half2*)&u2;
            const __half2* p3 = (const __half2*)&u3;
            uint32_t res[4];
#pragma unroll
            for (int j = 0; j < 4; j++) {
                __half2 s = __hmul2(p0[j], q0);
                s = __hfma2(p1[j], q1, s);
                s = __hfma2(p2[j], q2, s);
                s = __hfma2(p3[j], q3, s);
                res[j] = *(uint32_t*)&s;
            }
            *(uint4*)(sS + w * SH_STRIDE + (cg << 3)) =
                make_uint4(res[0], res[1], res[2], res[3]);
        }
        __syncthreads();

        // ---- MMA: 4 K-chunks of 16; A via ldmatrix, B via table LDG ----
        const uint32_t sS_base = smem_u32(sS);
#pragma unroll
        for (int kc = 0; kc < 4; kc++) {
            int c0 = kc << 4;
            uint32_t a0, a1, a2, a3, a4, a5, a6, a7;
            LDMATRIX_X4(a0, a1, a2, a3,
                        sS_base + (a_row0 * SH_STRIDE + c0 + a_c8) * 2);
            LDMATRIX_X4(a4, a5, a6, a7,
                        sS_base + ((a_row0 + 16) * SH_STRIDE + c0 + a_c8) * 2);
#pragma unroll
            for (int q = 0; q < 2; q++) {
                int t4 = (ng << 1) | q;
                uint4 bv = __ldg(&g_bf[(k << 9) + (t4 << 7) + (kc << 5) + lane]);
                int nj = q << 1;
                MMA_F16(acc + (nj << 2),            a0, a1, a2, a3, bv.x, bv.y);
                MMA_F16(acc + ((nj + 1) << 2),      a0, a1, a2, a3, bv.z, bv.w);
                MMA_F16(acc + ((4 + nj) << 2),      a4, a5, a6, a7, bv.x, bv.y);
                MMA_F16(acc + ((4 + nj + 1) << 2),  a4, a5, a6, a7, bv.z, bv.w);
            }
        }
    }

    // ---- epilogue: acc[(mi*4+nj)*4+j] -> out[b][o][h][wr] ----
#pragma unroll
    for (int mi = 0; mi < 2; mi++) {
#pragma unroll
        for (int nj = 0; nj < 4; nj++) {
#pragma unroll
            for (int j = 0; j < 4; j++) {
                int o  = (ng << 5) + (nj << 3) + (tg << 1) + (j & 1);
                int wr = (mg << 5) + (mi << 4) + gy + ((j >> 1) << 3);
                out[(((size_t)b * COUT + o) * HH + h) * WW + wr] =
                    acc[((mi << 2) + nj) * 4 + j] + __ldg(bias + o);
            }
        }
    }
}

// ---------------------------------------------------------------------------
extern "C" void kernel_launch(void* const* d_in, const int* in_sizes, int n_in,
                              void* d_out, int out_size)
{
    const float* x    = (const float*)d_in[0];
    const float* wgt  = (const float*)d_in[1];
    const float* bias = (const float*)d_in[2];
    const float* pgw  = (const float*)d_in[3];
    const float* pgb  = (const float*)d_in[4];
    float* out = (float*)d_out;

    const int smem0 = WW * T_STRIDE * (int)sizeof(__half);   // 16896 B
    cudaFuncSetAttribute(prep_kernel,
                         cudaFuncAttributeMaxDynamicSharedMemorySize, smem0);

    cudaFuncSetAttribute(fused_kernel,
                         cudaFuncAttributeMaxDynamicSharedMemorySize, SM_BYTES);

    const int nfrag_blocks = (NBF + NPF + 255) / 256;        // 27
    prep_kernel<<<BB * HH + nfrag_blocks, 256, smem0>>>(x, wgt, pgw);
    fused_kernel<<<BB * HH, 256, SM_BYTES>>>(pgb, bias, out);
}